// round 2
// baseline (speedup 1.0000x reference)
#include <cuda_runtime.h>
#include <math.h>
#include <stdint.h>

#define Tn   4096
#define Cn   2048
#define NH   16
#define NKV  4
#define HD   128
#define FFN  8192

// ---------------- scratch (static device globals; no allocation) ----------------
static __device__ float  g_h [Tn * Cn];          // rmsnorm1 output
static __device__ float  g_q [Tn * Cn];          // Q  [T, 16*128]
static __device__ float  g_k [Tn * NKV * HD];    // K  [T, 4*128]
static __device__ float  g_v [Tn * NKV * HD];    // V  [T, 4*128]
static __device__ float  g_y [Tn * Cn];          // attention output
static __device__ float  g_h2[Tn * Cn];          // rmsnorm2 output
static __device__ float  g_g [Tn * FFN];         // gate (then silu(g)*u)
static __device__ float  g_u [Tn * FFN];         // up
static __device__ float2 g_rope[Tn * 64];        // (cos, sin) table

// ---------------- RoPE cos/sin table (double sincos — fast-math immune) ----------------
__global__ void rope_table_kernel(float2* __restrict__ tab) {
    int idx = blockIdx.x * blockDim.x + threadIdx.x;
    if (idx >= Tn * 64) return;
    int i = idx & 63;
    int t = idx >> 6;
    // match reference rounding: inv_freq rounded to fp32, angle = fp32(t) * fp32(invf)
    double invf_d = pow(500000.0, -((double)(2 * i) / 128.0));
    float  invf_f = (float)invf_d;
    float  ang_f  = (float)t * invf_f;   // single fp32 multiply like pos * inv_freq
    double c, s;
    sincos((double)ang_f, &s, &c);       // accurate regardless of --use_fast_math
    tab[idx] = make_float2((float)c, (float)s);
}

// ---------------- rmsnorm: one block per row ----------------
__global__ void __launch_bounds__(256) rmsnorm_kernel(const float* __restrict__ x,
                                                      const float* __restrict__ w,
                                                      float* __restrict__ out) {
    const int row = blockIdx.x;
    const float* xr = x + (size_t)row * Cn;
    float s = 0.f;
    for (int i = threadIdx.x; i < Cn; i += 256) {
        float v = xr[i];
        s = fmaf(v, v, s);
    }
    __shared__ float red[8];
    #pragma unroll
    for (int o = 16; o; o >>= 1) s += __shfl_xor_sync(0xffffffffu, s, o);
    if ((threadIdx.x & 31) == 0) red[threadIdx.x >> 5] = s;
    __syncthreads();
    if (threadIdx.x < 32) {
        float v = (threadIdx.x < 8) ? red[threadIdx.x] : 0.f;
        #pragma unroll
        for (int o = 4; o; o >>= 1) v += __shfl_xor_sync(0xffffffffu, v, o);
        if (threadIdx.x == 0) red[0] = v;
    }
    __syncthreads();
    const float scale = rsqrtf(red[0] * (1.0f / Cn) + 1e-5f);
    float* orow = out + (size_t)row * Cn;
    for (int i = threadIdx.x; i < Cn; i += 256)
        orow[i] = xr[i] * scale * w[i];
}

// ---------------- generic GEMM: C[m,n] = sum_k A[m,k]*B[n,k] (+ R[m,n]) ----------------
__global__ void __launch_bounds__(256) gemm_nt(const float* __restrict__ A,
                                               const float* __restrict__ B,
                                               float* __restrict__ C,
                                               const float* __restrict__ R,
                                               int M, int N, int K) {
    __shared__ float As[16][128];
    __shared__ float Bs[16][128];
    const int bm = blockIdx.y * 128;
    const int bn = blockIdx.x * 128;
    const int tid = threadIdx.x;
    const int ty = tid >> 4;
    const int tx = tid & 15;

    float acc[8][8];
    #pragma unroll
    for (int i = 0; i < 8; i++)
        #pragma unroll
        for (int j = 0; j < 8; j++) acc[i][j] = 0.f;

    const float* Abase = A + (size_t)bm * K;
    const float* Bbase = B + (size_t)bn * K;

    for (int kt = 0; kt < K; kt += 16) {
        #pragma unroll
        for (int it = 0; it < 2; it++) {
            int idx = tid + it * 256;          // 0..511
            int row = idx >> 2;                // 0..127
            int kc  = (idx & 3) << 2;          // 0,4,8,12
            float4 va = *(const float4*)(Abase + (size_t)row * K + kt + kc);
            As[kc + 0][row] = va.x; As[kc + 1][row] = va.y;
            As[kc + 2][row] = va.z; As[kc + 3][row] = va.w;
            float4 vb = *(const float4*)(Bbase + (size_t)row * K + kt + kc);
            Bs[kc + 0][row] = vb.x; Bs[kc + 1][row] = vb.y;
            Bs[kc + 2][row] = vb.z; Bs[kc + 3][row] = vb.w;
        }
        __syncthreads();
        #pragma unroll
        for (int kk = 0; kk < 16; kk++) {
            float ar[8], br[8];
            *(float4*)(ar)     = *(const float4*)&As[kk][ty * 8];
            *(float4*)(ar + 4) = *(const float4*)&As[kk][ty * 8 + 4];
            *(float4*)(br)     = *(const float4*)&Bs[kk][tx * 8];
            *(float4*)(br + 4) = *(const float4*)&Bs[kk][tx * 8 + 4];
            #pragma unroll
            for (int i = 0; i < 8; i++)
                #pragma unroll
                for (int j = 0; j < 8; j++)
                    acc[i][j] = fmaf(ar[i], br[j], acc[i][j]);
        }
        __syncthreads();
    }

    #pragma unroll
    for (int i = 0; i < 8; i++) {
        size_t off = (size_t)(bm + ty * 8 + i) * N + bn + tx * 8;
        float4 o0 = make_float4(acc[i][0], acc[i][1], acc[i][2], acc[i][3]);
        float4 o1 = make_float4(acc[i][4], acc[i][5], acc[i][6], acc[i][7]);
        if (R) {
            float4 r0 = *(const float4*)(R + off);
            float4 r1 = *(const float4*)(R + off + 4);
            o0.x += r0.x; o0.y += r0.y; o0.z += r0.z; o0.w += r0.w;
            o1.x += r1.x; o1.y += r1.y; o1.z += r1.z; o1.w += r1.w;
        }
        *(float4*)(C + off)     = o0;
        *(float4*)(C + off + 4) = o1;
    }
}

// ---------------- RoPE (interleaved pairs, full 128 dims, table-driven) ----------------
__global__ void rope_kernel(float* __restrict__ q, float* __restrict__ k,
                            const float2* __restrict__ tab) {
    const int total = Tn * (NH + NKV) * 64;
    int idx = blockIdx.x * blockDim.x + threadIdx.x;
    if (idx >= total) return;
    int i    = idx & 63;
    int rest = idx >> 6;
    int head = rest % (NH + NKV);
    int t    = rest / (NH + NKV);
    float2 cs = tab[t * 64 + i];
    float c = cs.x, s = cs.y;
    float* p = (head < NH) ? (q + (size_t)t * Cn + head * HD + 2 * i)
                           : (k + (size_t)t * (NKV * HD) + (head - NH) * HD + 2 * i);
    float2 ab = *(float2*)p;
    float a = ab.x, b = ab.y;
    *(float2*)p = make_float2(fmaf(a, c, -b * s), fmaf(a, s, b * c));
}

// ---------------- causal flash attention, fp32, 64x64 tiles ----------------
#define QS 132   // padded row stride for Q/K/V tiles (128 + 4)
#define PS 68    // padded row stride for P tile (64 + 4)
#define ATTN_SMEM ((3 * 64 * QS + 64 * PS) * 4)

__global__ void __launch_bounds__(256) attn_kernel(const float* __restrict__ q,
                                                   const float* __restrict__ k,
                                                   const float* __restrict__ v,
                                                   float* __restrict__ y) {
    extern __shared__ float sm[];
    float* Qs = sm;                    // 64 x QS
    float* Ks = Qs + 64 * QS;          // 64 x QS
    float* Vs = Ks + 64 * QS;          // 64 x QS
    float* Pp = Vs + 64 * QS;          // 64 x PS
    const int qt   = blockIdx.x;
    const int head = blockIdx.y;
    const int kvh  = head >> 2;
    const int tid  = threadIdx.x;
    const int ty   = tid >> 4;
    const int tx   = tid & 15;
    const float scale = 0.088388347648318447f;  // 1/sqrt(128)

    // load Q tile (pre-scaled)
    for (int idx = tid; idx < 64 * 32; idx += 256) {
        int r  = idx >> 5;
        int c4 = (idx & 31) << 2;
        float4 vq = *(const float4*)(q + (size_t)(qt * 64 + r) * Cn + head * HD + c4);
        vq.x *= scale; vq.y *= scale; vq.z *= scale; vq.w *= scale;
        *(float4*)(Qs + r * QS + c4) = vq;
    }

    float m[4] = {-1e30f, -1e30f, -1e30f, -1e30f};
    float l[4] = {0.f, 0.f, 0.f, 0.f};
    float acc[4][8];
    #pragma unroll
    for (int i = 0; i < 4; i++)
        #pragma unroll
        for (int j = 0; j < 8; j++) acc[i][j] = 0.f;

    for (int jt = 0; jt <= qt; jt++) {
        __syncthreads();   // previous PV / Q-load done before overwriting tiles
        for (int idx = tid; idx < 64 * 32; idx += 256) {
            int r  = idx >> 5;
            int c4 = (idx & 31) << 2;
            size_t goff = (size_t)(jt * 64 + r) * (NKV * HD) + kvh * HD + c4;
            *(float4*)(Ks + r * QS + c4) = *(const float4*)(k + goff);
            *(float4*)(Vs + r * QS + c4) = *(const float4*)(v + goff);
        }
        __syncthreads();

        // S = Q K^T (4x4 per thread)
        float s4[4][4];
        #pragma unroll
        for (int i = 0; i < 4; i++)
            #pragma unroll
            for (int j = 0; j < 4; j++) s4[i][j] = 0.f;

        #pragma unroll 8
        for (int kk4 = 0; kk4 < 32; kk4++) {
            float4 qv[4], kv[4];
            #pragma unroll
            for (int i = 0; i < 4; i++) qv[i] = *(const float4*)(Qs + (ty * 4 + i) * QS + kk4 * 4);
            #pragma unroll
            for (int j = 0; j < 4; j++) kv[j] = *(const float4*)(Ks + (tx * 4 + j) * QS + kk4 * 4);
            #pragma unroll
            for (int i = 0; i < 4; i++)
                #pragma unroll
                for (int j = 0; j < 4; j++) {
                    s4[i][j] = fmaf(qv[i].x, kv[j].x, s4[i][j]);
                    s4[i][j] = fmaf(qv[i].y, kv[j].y, s4[i][j]);
                    s4[i][j] = fmaf(qv[i].z, kv[j].z, s4[i][j]);
                    s4[i][j] = fmaf(qv[i].w, kv[j].w, s4[i][j]);
                }
        }

        if (jt == qt) {
            #pragma unroll
            for (int i = 0; i < 4; i++)
                #pragma unroll
                for (int j = 0; j < 4; j++)
                    if (tx * 4 + j > ty * 4 + i) s4[i][j] = -1e30f;
        }

        // online softmax per q-row (row spread over the 16 tx lanes of the half-warp)
        #pragma unroll
        for (int i = 0; i < 4; i++) {
            float mr = fmaxf(fmaxf(s4[i][0], s4[i][1]), fmaxf(s4[i][2], s4[i][3]));
            #pragma unroll
            for (int o = 1; o < 16; o <<= 1) mr = fmaxf(mr, __shfl_xor_sync(0xffffffffu, mr, o));
            float mnew = fmaxf(m[i], mr);
            float p0 = expf(s4[i][0] - mnew);
            float p1 = expf(s4[i][1] - mnew);
            float p2 = expf(s4[i][2] - mnew);
            float p3 = expf(s4[i][3] - mnew);
            float rs = (p0 + p1) + (p2 + p3);
            #pragma unroll
            for (int o = 1; o < 16; o <<= 1) rs += __shfl_xor_sync(0xffffffffu, rs, o);
            float alpha = expf(m[i] - mnew);
            m[i] = mnew;
            l[i] = l[i] * alpha + rs;
            #pragma unroll
            for (int j = 0; j < 8; j++) acc[i][j] *= alpha;
            *(float4*)(Pp + (ty * 4 + i) * PS + tx * 4) = make_float4(p0, p1, p2, p3);
        }
        __syncthreads();

        // O += P V  (thread owns cols [tx*4, tx*4+4) and [64+tx*4, 64+tx*4+4))
        #pragma unroll 4
        for (int kk = 0; kk < 64; kk++) {
            float4 v0 = *(const float4*)(Vs + kk * QS + tx * 4);
            float4 v1 = *(const float4*)(Vs + kk * QS + 64 + tx * 4);
            #pragma unroll
            for (int i = 0; i < 4; i++) {
                float p = Pp[(ty * 4 + i) * PS + kk];
                acc[i][0] = fmaf(p, v0.x, acc[i][0]);
                acc[i][1] = fmaf(p, v0.y, acc[i][1]);
                acc[i][2] = fmaf(p, v0.z, acc[i][2]);
                acc[i][3] = fmaf(p, v0.w, acc[i][3]);
                acc[i][4] = fmaf(p, v1.x, acc[i][4]);
                acc[i][5] = fmaf(p, v1.y, acc[i][5]);
                acc[i][6] = fmaf(p, v1.z, acc[i][6]);
                acc[i][7] = fmaf(p, v1.w, acc[i][7]);
            }
        }
    }

    #pragma unroll
    for (int i = 0; i < 4; i++) {
        float inv = 1.0f / l[i];
        size_t off = (size_t)(qt * 64 + ty * 4 + i) * Cn + head * HD;
        *(float4*)(y + off + tx * 4) =
            make_float4(acc[i][0] * inv, acc[i][1] * inv, acc[i][2] * inv, acc[i][3] * inv);
        *(float4*)(y + off + 64 + tx * 4) =
            make_float4(acc[i][4] * inv, acc[i][5] * inv, acc[i][6] * inv, acc[i][7] * inv);
    }
}

// ---------------- silu(g) * u -> g ----------------
__global__ void silu_mul_kernel(float* __restrict__ g, const float* __restrict__ u) {
    const int n4 = Tn * FFN / 4;
    int i = blockIdx.x * blockDim.x + threadIdx.x;
    if (i >= n4) return;
    float4 gv = ((const float4*)g)[i];
    float4 uv = ((const float4*)u)[i];
    gv.x = gv.x / (1.f + expf(-gv.x)) * uv.x;
    gv.y = gv.y / (1.f + expf(-gv.y)) * uv.y;
    gv.z = gv.z / (1.f + expf(-gv.z)) * uv.z;
    gv.w = gv.w / (1.f + expf(-gv.w)) * uv.w;
    ((float4*)g)[i] = gv;
}

// ---------------- launch ----------------
extern "C" void kernel_launch(void* const* d_in, const int* in_sizes, int n_in,
                              void* d_out, int out_size) {
    (void)in_sizes; (void)n_in; (void)out_size;
    const float* x           = (const float*)d_in[0];
    // d_in[1] = attn_bias (causal -1e9 mask) — implemented directly as causal masking
    const float* attn_norm_w = (const float*)d_in[2];
    const float* wq          = (const float*)d_in[3];
    const float* wk          = (const float*)d_in[4];
    const float* wv          = (const float*)d_in[5];
    const float* wo          = (const float*)d_in[6];
    const float* ffn_norm_w  = (const float*)d_in[7];
    const float* w_gate      = (const float*)d_in[8];
    const float* w_up        = (const float*)d_in[9];
    const float* w_down      = (const float*)d_in[10];
    float* out = (float*)d_out;

    float *h, *q, *k, *v, *y, *h2, *g, *u;
    float2* rtab;
    cudaGetSymbolAddress((void**)&h,  g_h);
    cudaGetSymbolAddress((void**)&q,  g_q);
    cudaGetSymbolAddress((void**)&k,  g_k);
    cudaGetSymbolAddress((void**)&v,  g_v);
    cudaGetSymbolAddress((void**)&y,  g_y);
    cudaGetSymbolAddress((void**)&h2, g_h2);
    cudaGetSymbolAddress((void**)&g,  g_g);
    cudaGetSymbolAddress((void**)&u,  g_u);
    cudaGetSymbolAddress((void**)&rtab, g_rope);

    cudaFuncSetAttribute(attn_kernel, cudaFuncAttributeMaxDynamicSharedMemorySize, ATTN_SMEM);

    // 0) RoPE cos/sin table (fp64 sincos, fast-math immune)
    rope_table_kernel<<<(Tn * 64 + 255) / 256, 256>>>(rtab);
    // 1) rmsnorm1
    rmsnorm_kernel<<<Tn, 256>>>(x, attn_norm_w, h);
    // 2) Q/K/V projections
    gemm_nt<<<dim3(Cn / 128, Tn / 128), 256>>>(h, wq, q, nullptr, Tn, Cn, Cn);
    gemm_nt<<<dim3((NKV * HD) / 128, Tn / 128), 256>>>(h, wk, k, nullptr, Tn, NKV * HD, Cn);
    gemm_nt<<<dim3((NKV * HD) / 128, Tn / 128), 256>>>(h, wv, v, nullptr, Tn, NKV * HD, Cn);
    // 3) RoPE on q (16 heads) and k (4 heads)
    {
        int total = Tn * (NH + NKV) * 64;
        rope_kernel<<<(total + 255) / 256, 256>>>(q, k, rtab);
    }
    // 4) causal flash attention
    attn_kernel<<<dim3(Tn / 64, NH), 256, ATTN_SMEM>>>(q, k, v, y);
    // 5) output projection + residual  -> out = x + y @ wo^T
    gemm_nt<<<dim3(Cn / 128, Tn / 128), 256>>>(y, wo, out, x, Tn, Cn, Cn);
    // 6) rmsnorm2
    rmsnorm_kernel<<<Tn, 256>>>(out, ffn_norm_w, h2);
    // 7) gate / up
    gemm_nt<<<dim3(FFN / 128, Tn / 128), 256>>>(h2, w_gate, g, nullptr, Tn, FFN, Cn);
    gemm_nt<<<dim3(FFN / 128, Tn / 128), 256>>>(h2, w_up,   u, nullptr, Tn, FFN, Cn);
    // 8) silu(g)*u -> g
    silu_mul_kernel<<<(Tn * FFN / 4 + 255) / 256, 256>>>(g, u);
    // 9) down projection + residual -> out += g @ w_down^T
    gemm_nt<<<dim3(Cn / 128, Tn / 128), 256>>>(g, w_down, out, out, Tn, Cn, FFN);
}

// round 3
// speedup vs baseline: 1.9443x; 1.9443x over previous
#include <cuda_runtime.h>
#include <cuda_bf16.h>
#include <math.h>
#include <stdint.h>

#define Tn   4096
#define Cn   2048
#define NH   16
#define NKV  4
#define HD   128
#define FFN  8192

typedef __nv_bfloat16 bf16;

// ---------------- scratch (static device globals; no allocation) ----------------
static __device__ float  g_q [Tn * Cn];
static __device__ float  g_k [Tn * NKV * HD];
static __device__ float  g_v [Tn * NKV * HD];
static __device__ float  g_g [Tn * FFN];
static __device__ float  g_u [Tn * FFN];
static __device__ float2 g_rope[Tn * 64];

static __device__ bf16 g_h_hi [Tn * Cn],  g_h_lo [Tn * Cn];
static __device__ bf16 g_h2_hi[Tn * Cn],  g_h2_lo[Tn * Cn];
static __device__ bf16 g_y_hi [Tn * Cn],  g_y_lo [Tn * Cn];
static __device__ bf16 g_gs_hi[Tn * FFN], g_gs_lo[Tn * FFN];

static __device__ bf16 g_wq_hi[Cn * Cn],        g_wq_lo[Cn * Cn];
static __device__ bf16 g_wk_hi[NKV * HD * Cn],  g_wk_lo[NKV * HD * Cn];
static __device__ bf16 g_wv_hi[NKV * HD * Cn],  g_wv_lo[NKV * HD * Cn];
static __device__ bf16 g_wo_hi[Cn * Cn],        g_wo_lo[Cn * Cn];
static __device__ bf16 g_wg_hi[FFN * Cn],       g_wg_lo[FFN * Cn];
static __device__ bf16 g_wu_hi[FFN * Cn],       g_wu_lo[FFN * Cn];
static __device__ bf16 g_wd_hi[Cn * FFN],       g_wd_lo[Cn * FFN];

__device__ __forceinline__ void split2(float x, bf16& hi, bf16& lo) {
    hi = __float2bfloat16(x);
    lo = __float2bfloat16(x - __bfloat162float(hi));
}

// ---------------- weight fp32 -> (hi, lo) bf16 ----------------
__global__ void convert_kernel(const float* __restrict__ w,
                               bf16* __restrict__ hi, bf16* __restrict__ lo, int n) {
    int i = blockIdx.x * blockDim.x + threadIdx.x;
    if (i < n) split2(w[i], hi[i], lo[i]);
}

// ---------------- RoPE cos/sin table (double sincos — fast-math immune) ----------------
__global__ void rope_table_kernel(float2* __restrict__ tab) {
    int idx = blockIdx.x * blockDim.x + threadIdx.x;
    if (idx >= Tn * 64) return;
    int i = idx & 63;
    int t = idx >> 6;
    double invf_d = pow(500000.0, -((double)(2 * i) / 128.0));
    float  invf_f = (float)invf_d;
    float  ang_f  = (float)t * invf_f;
    double c, s;
    sincos((double)ang_f, &s, &c);
    tab[idx] = make_float2((float)c, (float)s);
}

// ---------------- rmsnorm: one block per row, writes split bf16 ----------------
__global__ void __launch_bounds__(256) rmsnorm_kernel(const float* __restrict__ x,
                                                      const float* __restrict__ w,
                                                      bf16* __restrict__ ohi,
                                                      bf16* __restrict__ olo) {
    const int row = blockIdx.x;
    const float* xr = x + (size_t)row * Cn;
    float s = 0.f;
    for (int i = threadIdx.x; i < Cn; i += 256) {
        float v = xr[i];
        s = fmaf(v, v, s);
    }
    __shared__ float red[8];
    #pragma unroll
    for (int o = 16; o; o >>= 1) s += __shfl_xor_sync(0xffffffffu, s, o);
    if ((threadIdx.x & 31) == 0) red[threadIdx.x >> 5] = s;
    __syncthreads();
    if (threadIdx.x < 32) {
        float v = (threadIdx.x < 8) ? red[threadIdx.x] : 0.f;
        #pragma unroll
        for (int o = 4; o; o >>= 1) v += __shfl_xor_sync(0xffffffffu, v, o);
        if (threadIdx.x == 0) red[0] = v;
    }
    __syncthreads();
    const float scale = rsqrtf(red[0] * (1.0f / Cn) + 1e-5f);
    size_t base = (size_t)row * Cn;
    for (int i = threadIdx.x; i < Cn; i += 256) {
        float v = xr[i] * scale * w[i];
        split2(v, ohi[base + i], olo[base + i]);
    }
}

// =====================================================================
// bf16x3 tensor-core GEMM:  C[m,n] = sum_k A[m,k] * B[n,k]  (+ R[m,n])
// A = Ahi + Alo, B = Bhi + Blo; accumulate hi*hi + hi*lo + lo*hi in fp32.
// 128x128x32 tiles, 8 warps (warp tile 32x64), cp.async 3-stage pipeline.
// =====================================================================
#define STAGES 3
#define TILE_BYTES  (128 * 64)          // one 128x32 bf16 tile = 8KB
#define STAGE_BYTES (4 * TILE_BYTES)    // Ahi, Alo, Bhi, Blo = 32KB
#define GEMM_SMEM   (STAGES * STAGE_BYTES)

// swizzled byte offset for (row, 16B-chunk) in a [128][32] bf16 tile (64B rows)
__device__ __forceinline__ uint32_t sw(uint32_t row, uint32_t chunk) {
    return (row << 6) + (((chunk ^ (row >> 1)) & 3u) << 4);
}

__device__ __forceinline__ void cp16(uint32_t dst, const void* src) {
    asm volatile("cp.async.cg.shared.global [%0], [%1], 16;\n" :: "r"(dst), "l"(src));
}

__device__ __forceinline__ void ldm4(uint32_t* r, uint32_t addr) {
    asm volatile("ldmatrix.sync.aligned.m8n8.x4.shared.b16 {%0,%1,%2,%3}, [%4];\n"
                 : "=r"(r[0]), "=r"(r[1]), "=r"(r[2]), "=r"(r[3]) : "r"(addr));
}

__device__ __forceinline__ void mma16816(float* c, const uint32_t* a, const uint32_t* b) {
    asm volatile("mma.sync.aligned.m16n8k16.row.col.f32.bf16.bf16.f32 "
                 "{%0,%1,%2,%3},{%4,%5,%6,%7},{%8,%9},{%0,%1,%2,%3};\n"
                 : "+f"(c[0]), "+f"(c[1]), "+f"(c[2]), "+f"(c[3])
                 : "r"(a[0]), "r"(a[1]), "r"(a[2]), "r"(a[3]), "r"(b[0]), "r"(b[1]));
}

__global__ void __launch_bounds__(256, 1) gemm_bf16x3(
        const bf16* __restrict__ Ahi, const bf16* __restrict__ Alo,
        const bf16* __restrict__ Bhi, const bf16* __restrict__ Blo,
        float* __restrict__ C, const float* __restrict__ R,
        int M, int N, int K) {
    extern __shared__ __align__(128) char smem_raw[];
    const uint32_t smem_u = (uint32_t)__cvta_generic_to_shared(smem_raw);
    const int tid  = threadIdx.x;
    const int warp = tid >> 5;
    const int lane = tid & 31;
    const int wm   = warp & 3;     // 4 warps along M (32 rows each)
    const int wn   = warp >> 2;    // 2 warps along N (64 cols each)
    const int bm   = blockIdx.y * 128;
    const int bn   = blockIdx.x * 128;

    float acc[2][8][4];
    #pragma unroll
    for (int i = 0; i < 2; i++)
        #pragma unroll
        for (int j = 0; j < 8; j++)
            #pragma unroll
            for (int v = 0; v < 4; v++) acc[i][j][v] = 0.f;

    const int kiters = K >> 5;

    // stage loader: rows of A from bm, rows of B from bn, K offset kt (elements)
    auto load_stage = [&](int stage, int kt) {
        const uint32_t sbase = smem_u + stage * STAGE_BYTES;
        const bf16* gptr[4] = {Ahi, Alo, Bhi, Blo};
        #pragma unroll
        for (int tile = 0; tile < 4; tile++) {
            const int rbase = (tile < 2) ? bm : bn;
            const bf16* gp = gptr[tile];
            #pragma unroll
            for (int rep = 0; rep < 2; rep++) {
                int idx  = tid + rep * 256;        // 0..511
                int row  = idx >> 2;               // 0..127
                int ch   = idx & 3;                // 16B chunk
                const void* src = gp + (size_t)(rbase + row) * K + kt + ch * 8;
                cp16(sbase + tile * TILE_BYTES + sw(row, ch), src);
            }
        }
    };

    #pragma unroll
    for (int s = 0; s < STAGES - 1; s++) {
        load_stage(s, s * 32);
        asm volatile("cp.async.commit_group;\n");
    }

    for (int it = 0; it < kiters; ++it) {
        asm volatile("cp.async.wait_group %0;\n" :: "n"(STAGES - 2));
        __syncthreads();
        int pf = it + STAGES - 1;
        if (pf < kiters) load_stage(pf % STAGES, pf * 32);
        asm volatile("cp.async.commit_group;\n");

        const uint32_t sb   = smem_u + (it % STAGES) * STAGE_BYTES;
        const uint32_t sAhi = sb;
        const uint32_t sAlo = sb + TILE_BYTES;
        const uint32_t sBhi = sb + 2 * TILE_BYTES;
        const uint32_t sBlo = sb + 3 * TILE_BYTES;

        #pragma unroll
        for (int kf = 0; kf < 2; kf++) {
            uint32_t ah[2][4], al[2][4];
            #pragma unroll
            for (int mt = 0; mt < 2; mt++) {
                uint32_t row = wm * 32 + mt * 16 + (lane & 15);
                uint32_t ch  = kf * 2 + (lane >> 4);
                uint32_t off = sw(row, ch);
                ldm4(ah[mt], sAhi + off);
                ldm4(al[mt], sAlo + off);
            }
            uint32_t bh[8][2], bl[8][2];
            #pragma unroll
            for (int p = 0; p < 4; p++) {        // each x4 covers n-tiles 2p, 2p+1
                uint32_t rowb = wn * 64 + p * 16 + (lane & 7) + ((lane >> 4) & 1) * 8;
                uint32_t chb  = kf * 2 + ((lane >> 3) & 1);
                uint32_t offb = sw(rowb, chb);
                uint32_t r[4];
                ldm4(r, sBhi + offb);
                bh[2 * p][0] = r[0]; bh[2 * p][1] = r[1];
                bh[2 * p + 1][0] = r[2]; bh[2 * p + 1][1] = r[3];
                ldm4(r, sBlo + offb);
                bl[2 * p][0] = r[0]; bl[2 * p][1] = r[1];
                bl[2 * p + 1][0] = r[2]; bl[2 * p + 1][1] = r[3];
            }
            #pragma unroll
            for (int mt = 0; mt < 2; mt++)
                #pragma unroll
                for (int nt = 0; nt < 8; nt++) {
                    mma16816(acc[mt][nt], ah[mt], bh[nt]);
                    mma16816(acc[mt][nt], ah[mt], bl[nt]);
                    mma16816(acc[mt][nt], al[mt], bh[nt]);
                }
        }
    }

    // epilogue
    const int rb = bm + wm * 32;
    const int cb = bn + wn * 64;
    #pragma unroll
    for (int mt = 0; mt < 2; mt++)
        #pragma unroll
        for (int nt = 0; nt < 8; nt++) {
            int r0 = rb + mt * 16 + (lane >> 2);
            int c  = cb + nt * 8 + (lane & 3) * 2;
            size_t i0 = (size_t)r0 * N + c;
            size_t i1 = (size_t)(r0 + 8) * N + c;
            float2 v0 = make_float2(acc[mt][nt][0], acc[mt][nt][1]);
            float2 v1 = make_float2(acc[mt][nt][2], acc[mt][nt][3]);
            if (R) {
                float2 q0 = *(const float2*)(R + i0);
                float2 q1 = *(const float2*)(R + i1);
                v0.x += q0.x; v0.y += q0.y;
                v1.x += q1.x; v1.y += q1.y;
            }
            *(float2*)(C + i0) = v0;
            *(float2*)(C + i1) = v1;
        }
}

// ---------------- RoPE (interleaved pairs, full 128 dims, table-driven) ----------------
__global__ void rope_kernel(float* __restrict__ q, float* __restrict__ k,
                            const float2* __restrict__ tab) {
    const int total = Tn * (NH + NKV) * 64;
    int idx = blockIdx.x * blockDim.x + threadIdx.x;
    if (idx >= total) return;
    int i    = idx & 63;
    int rest = idx >> 6;
    int head = rest % (NH + NKV);
    int t    = rest / (NH + NKV);
    float2 cs = tab[t * 64 + i];
    float c = cs.x, s = cs.y;
    float* p = (head < NH) ? (q + (size_t)t * Cn + head * HD + 2 * i)
                           : (k + (size_t)t * (NKV * HD) + (head - NH) * HD + 2 * i);
    float2 ab = *(float2*)p;
    float a = ab.x, b = ab.y;
    *(float2*)p = make_float2(fmaf(a, c, -b * s), fmaf(a, s, b * c));
}

// ---------------- causal flash attention, fp32, 64x64 tiles ----------------
#define QS 132
#define PS 68
#define ATTN_SMEM ((3 * 64 * QS + 64 * PS) * 4)

__global__ void __launch_bounds__(256) attn_kernel(const float* __restrict__ q,
                                                   const float* __restrict__ k,
                                                   const float* __restrict__ v,
                                                   bf16* __restrict__ yhi,
                                                   bf16* __restrict__ ylo) {
    extern __shared__ float sm[];
    float* Qs = sm;
    float* Ks = Qs + 64 * QS;
    float* Vs = Ks + 64 * QS;
    float* Pp = Vs + 64 * QS;
    const int qt   = blockIdx.x;
    const int head = blockIdx.y;
    const int kvh  = head >> 2;
    const int tid  = threadIdx.x;
    const int ty   = tid >> 4;
    const int tx   = tid & 15;
    const float scale = 0.088388347648318447f;

    for (int idx = tid; idx < 64 * 32; idx += 256) {
        int r  = idx >> 5;
        int c4 = (idx & 31) << 2;
        float4 vq = *(const float4*)(q + (size_t)(qt * 64 + r) * Cn + head * HD + c4);
        vq.x *= scale; vq.y *= scale; vq.z *= scale; vq.w *= scale;
        *(float4*)(Qs + r * QS + c4) = vq;
    }

    float m[4] = {-1e30f, -1e30f, -1e30f, -1e30f};
    float l[4] = {0.f, 0.f, 0.f, 0.f};
    float acc[4][8];
    #pragma unroll
    for (int i = 0; i < 4; i++)
        #pragma unroll
        for (int j = 0; j < 8; j++) acc[i][j] = 0.f;

    for (int jt = 0; jt <= qt; jt++) {
        __syncthreads();
        for (int idx = tid; idx < 64 * 32; idx += 256) {
            int r  = idx >> 5;
            int c4 = (idx & 31) << 2;
            size_t goff = (size_t)(jt * 64 + r) * (NKV * HD) + kvh * HD + c4;
            *(float4*)(Ks + r * QS + c4) = *(const float4*)(k + goff);
            *(float4*)(Vs + r * QS + c4) = *(const float4*)(v + goff);
        }
        __syncthreads();

        float s4[4][4];
        #pragma unroll
        for (int i = 0; i < 4; i++)
            #pragma unroll
            for (int j = 0; j < 4; j++) s4[i][j] = 0.f;

        #pragma unroll 8
        for (int kk4 = 0; kk4 < 32; kk4++) {
            float4 qv[4], kv[4];
            #pragma unroll
            for (int i = 0; i < 4; i++) qv[i] = *(const float4*)(Qs + (ty * 4 + i) * QS + kk4 * 4);
            #pragma unroll
            for (int j = 0; j < 4; j++) kv[j] = *(const float4*)(Ks + (tx * 4 + j) * QS + kk4 * 4);
            #pragma unroll
            for (int i = 0; i < 4; i++)
                #pragma unroll
                for (int j = 0; j < 4; j++) {
                    s4[i][j] = fmaf(qv[i].x, kv[j].x, s4[i][j]);
                    s4[i][j] = fmaf(qv[i].y, kv[j].y, s4[i][j]);
                    s4[i][j] = fmaf(qv[i].z, kv[j].z, s4[i][j]);
                    s4[i][j] = fmaf(qv[i].w, kv[j].w, s4[i][j]);
                }
        }

        if (jt == qt) {
            #pragma unroll
            for (int i = 0; i < 4; i++)
                #pragma unroll
                for (int j = 0; j < 4; j++)
                    if (tx * 4 + j > ty * 4 + i) s4[i][j] = -1e30f;
        }

        #pragma unroll
        for (int i = 0; i < 4; i++) {
            float mr = fmaxf(fmaxf(s4[i][0], s4[i][1]), fmaxf(s4[i][2], s4[i][3]));
            #pragma unroll
            for (int o = 1; o < 16; o <<= 1) mr = fmaxf(mr, __shfl_xor_sync(0xffffffffu, mr, o));
            float mnew = fmaxf(m[i], mr);
            float p0 = expf(s4[i][0] - mnew);
            float p1 = expf(s4[i][1] - mnew);
            float p2 = expf(s4[i][2] - mnew);
            float p3 = expf(s4[i][3] - mnew);
            float rs = (p0 + p1) + (p2 + p3);
            #pragma unroll
            for (int o = 1; o < 16; o <<= 1) rs += __shfl_xor_sync(0xffffffffu, rs, o);
            float alpha = expf(m[i] - mnew);
            m[i] = mnew;
            l[i] = l[i] * alpha + rs;
            #pragma unroll
            for (int j = 0; j < 8; j++) acc[i][j] *= alpha;
            *(float4*)(Pp + (ty * 4 + i) * PS + tx * 4) = make_float4(p0, p1, p2, p3);
        }
        __syncthreads();

        #pragma unroll 4
        for (int kk = 0; kk < 64; kk++) {
            float4 v0 = *(const float4*)(Vs + kk * QS + tx * 4);
            float4 v1 = *(const float4*)(Vs + kk * QS + 64 + tx * 4);
            #pragma unroll
            for (int i = 0; i < 4; i++) {
                float p = Pp[(ty * 4 + i) * PS + kk];
                acc[i][0] = fmaf(p, v0.x, acc[i][0]);
                acc[i][1] = fmaf(p, v0.y, acc[i][1]);
                acc[i][2] = fmaf(p, v0.z, acc[i][2]);
                acc[i][3] = fmaf(p, v0.w, acc[i][3]);
                acc[i][4] = fmaf(p, v1.x, acc[i][4]);
                acc[i][5] = fmaf(p, v1.y, acc[i][5]);
                acc[i][6] = fmaf(p, v1.z, acc[i][6]);
                acc[i][7] = fmaf(p, v1.w, acc[i][7]);
            }
        }
    }

    #pragma unroll
    for (int i = 0; i < 4; i++) {
        float inv = 1.0f / l[i];
        size_t off = (size_t)(qt * 64 + ty * 4 + i) * Cn + head * HD;
        #pragma unroll
        for (int j = 0; j < 4; j++) {
            float val = acc[i][j] * inv;
            split2(val, yhi[off + tx * 4 + j], ylo[off + tx * 4 + j]);
        }
        #pragma unroll
        for (int j = 0; j < 4; j++) {
            float val = acc[i][4 + j] * inv;
            split2(val, yhi[off + 64 + tx * 4 + j], ylo[off + 64 + tx * 4 + j]);
        }
    }
}

// ---------------- silu(g) * u -> split bf16 ----------------
__global__ void silu_mul_kernel(const float* __restrict__ g, const float* __restrict__ u,
                                bf16* __restrict__ ohi, bf16* __restrict__ olo) {
    const int n4 = Tn * FFN / 4;
    int i = blockIdx.x * blockDim.x + threadIdx.x;
    if (i >= n4) return;
    float4 gv = ((const float4*)g)[i];
    float4 uv = ((const float4*)u)[i];
    float r0 = gv.x / (1.f + expf(-gv.x)) * uv.x;
    float r1 = gv.y / (1.f + expf(-gv.y)) * uv.y;
    float r2 = gv.z / (1.f + expf(-gv.z)) * uv.z;
    float r3 = gv.w / (1.f + expf(-gv.w)) * uv.w;
    int b = i * 4;
    split2(r0, ohi[b + 0], olo[b + 0]);
    split2(r1, ohi[b + 1], olo[b + 1]);
    split2(r2, ohi[b + 2], olo[b + 2]);
    split2(r3, ohi[b + 3], olo[b + 3]);
}

// ---------------- launch ----------------
extern "C" void kernel_launch(void* const* d_in, const int* in_sizes, int n_in,
                              void* d_out, int out_size) {
    (void)in_sizes; (void)n_in; (void)out_size;
    const float* x           = (const float*)d_in[0];
    const float* attn_norm_w = (const float*)d_in[2];
    const float* wq          = (const float*)d_in[3];
    const float* wk          = (const float*)d_in[4];
    const float* wv          = (const float*)d_in[5];
    const float* wo          = (const float*)d_in[6];
    const float* ffn_norm_w  = (const float*)d_in[7];
    const float* w_gate      = (const float*)d_in[8];
    const float* w_up        = (const float*)d_in[9];
    const float* w_down      = (const float*)d_in[10];
    float* out = (float*)d_out;

    float *q, *k, *v, *g, *u;
    float2* rtab;
    bf16 *h_hi, *h_lo, *h2_hi, *h2_lo, *y_hi, *y_lo, *gs_hi, *gs_lo;
    bf16 *wq_hi, *wq_lo, *wk_hi, *wk_lo, *wv_hi, *wv_lo, *wo_hi, *wo_lo;
    bf16 *wg_hi, *wg_lo, *wu_hi, *wu_lo, *wd_hi, *wd_lo;

    cudaGetSymbolAddress((void**)&q,  g_q);
    cudaGetSymbolAddress((void**)&k,  g_k);
    cudaGetSymbolAddress((void**)&v,  g_v);
    cudaGetSymbolAddress((void**)&g,  g_g);
    cudaGetSymbolAddress((void**)&u,  g_u);
    cudaGetSymbolAddress((void**)&rtab, g_rope);
    cudaGetSymbolAddress((void**)&h_hi,  g_h_hi);  cudaGetSymbolAddress((void**)&h_lo,  g_h_lo);
    cudaGetSymbolAddress((void**)&h2_hi, g_h2_hi); cudaGetSymbolAddress((void**)&h2_lo, g_h2_lo);
    cudaGetSymbolAddress((void**)&y_hi,  g_y_hi);  cudaGetSymbolAddress((void**)&y_lo,  g_y_lo);
    cudaGetSymbolAddress((void**)&gs_hi, g_gs_hi); cudaGetSymbolAddress((void**)&gs_lo, g_gs_lo);
    cudaGetSymbolAddress((void**)&wq_hi, g_wq_hi); cudaGetSymbolAddress((void**)&wq_lo, g_wq_lo);
    cudaGetSymbolAddress((void**)&wk_hi, g_wk_hi); cudaGetSymbolAddress((void**)&wk_lo, g_wk_lo);
    cudaGetSymbolAddress((void**)&wv_hi, g_wv_hi); cudaGetSymbolAddress((void**)&wv_lo, g_wv_lo);
    cudaGetSymbolAddress((void**)&wo_hi, g_wo_hi); cudaGetSymbolAddress((void**)&wo_lo, g_wo_lo);
    cudaGetSymbolAddress((void**)&wg_hi, g_wg_hi); cudaGetSymbolAddress((void**)&wg_lo, g_wg_lo);
    cudaGetSymbolAddress((void**)&wu_hi, g_wu_hi); cudaGetSymbolAddress((void**)&wu_lo, g_wu_lo);
    cudaGetSymbolAddress((void**)&wd_hi, g_wd_hi); cudaGetSymbolAddress((void**)&wd_lo, g_wd_lo);

    cudaFuncSetAttribute(attn_kernel, cudaFuncAttributeMaxDynamicSharedMemorySize, ATTN_SMEM);
    cudaFuncSetAttribute(gemm_bf16x3, cudaFuncAttributeMaxDynamicSharedMemorySize, GEMM_SMEM);

    // 0) RoPE table + weight splits
    rope_table_kernel<<<(Tn * 64 + 255) / 256, 256>>>(rtab);
    convert_kernel<<<(Cn * Cn + 255) / 256, 256>>>(wq, wq_hi, wq_lo, Cn * Cn);
    convert_kernel<<<(NKV * HD * Cn + 255) / 256, 256>>>(wk, wk_hi, wk_lo, NKV * HD * Cn);
    convert_kernel<<<(NKV * HD * Cn + 255) / 256, 256>>>(wv, wv_hi, wv_lo, NKV * HD * Cn);
    convert_kernel<<<(Cn * Cn + 255) / 256, 256>>>(wo, wo_hi, wo_lo, Cn * Cn);
    convert_kernel<<<(FFN * Cn + 255) / 256, 256>>>(w_gate, wg_hi, wg_lo, FFN * Cn);
    convert_kernel<<<(FFN * Cn + 255) / 256, 256>>>(w_up,   wu_hi, wu_lo, FFN * Cn);
    convert_kernel<<<(Cn * FFN + 255) / 256, 256>>>(w_down, wd_hi, wd_lo, Cn * FFN);

    // 1) rmsnorm1 -> split
    rmsnorm_kernel<<<Tn, 256>>>(x, attn_norm_w, h_hi, h_lo);
    // 2) Q/K/V projections (tensor cores)
    gemm_bf16x3<<<dim3(Cn / 128, Tn / 128), 256, GEMM_SMEM>>>(h_hi, h_lo, wq_hi, wq_lo, q, nullptr, Tn, Cn, Cn);
    gemm_bf16x3<<<dim3((NKV * HD) / 128, Tn / 128), 256, GEMM_SMEM>>>(h_hi, h_lo, wk_hi, wk_lo, k, nullptr, Tn, NKV * HD, Cn);
    gemm_bf16x3<<<dim3((NKV * HD) / 128, Tn / 128), 256, GEMM_SMEM>>>(h_hi, h_lo, wv_hi, wv_lo, v, nullptr, Tn, NKV * HD, Cn);
    // 3) RoPE
    {
        int total = Tn * (NH + NKV) * 64;
        rope_kernel<<<(total + 255) / 256, 256>>>(q, k, rtab);
    }
    // 4) causal flash attention (fp32), split epilogue
    attn_kernel<<<dim3(Tn / 64, NH), 256, ATTN_SMEM>>>(q, k, v, y_hi, y_lo);
    // 5) out = x + y @ wo^T
    gemm_bf16x3<<<dim3(Cn / 128, Tn / 128), 256, GEMM_SMEM>>>(y_hi, y_lo, wo_hi, wo_lo, out, x, Tn, Cn, Cn);
    // 6) rmsnorm2 -> split
    rmsnorm_kernel<<<Tn, 256>>>(out, ffn_norm_w, h2_hi, h2_lo);
    // 7) gate / up
    gemm_bf16x3<<<dim3(FFN / 128, Tn / 128), 256, GEMM_SMEM>>>(h2_hi, h2_lo, wg_hi, wg_lo, g, nullptr, Tn, FFN, Cn);
    gemm_bf16x3<<<dim3(FFN / 128, Tn / 128), 256, GEMM_SMEM>>>(h2_hi, h2_lo, wu_hi, wu_lo, u, nullptr, Tn, FFN, Cn);
    // 8) silu(g)*u -> split
    silu_mul_kernel<<<(Tn * FFN / 4 + 255) / 256, 256>>>(g, u, gs_hi, gs_lo);
    // 9) out += gs @ w_down^T
    gemm_bf16x3<<<dim3(Cn / 128, Tn / 128), 256, GEMM_SMEM>>>(gs_hi, gs_lo, wd_hi, wd_lo, out, out, Tn, Cn, FFN);
}

// round 5
// speedup vs baseline: 3.1011x; 1.5950x over previous
#include <cuda_runtime.h>
#include <cuda_bf16.h>
#include <math.h>
#include <stdint.h>

#define Tn   4096
#define Cn   2048
#define NH   16
#define NKV  4
#define HD   128
#define FFN  8192

typedef __nv_bfloat16 bf16;

// ---------------- scratch (static device globals; no allocation) ----------------
static __device__ float  g_q [Tn * Cn];
static __device__ float  g_k [Tn * NKV * HD];
static __device__ float  g_v [Tn * NKV * HD];
static __device__ float  g_g [Tn * FFN];
static __device__ float  g_u [Tn * FFN];
static __device__ float2 g_rope[Tn * 64];

static __device__ bf16 g_h_hi [Tn * Cn],  g_h_lo [Tn * Cn];
static __device__ bf16 g_h2_hi[Tn * Cn],  g_h2_lo[Tn * Cn];
static __device__ bf16 g_y_hi [Tn * Cn],  g_y_lo [Tn * Cn];
static __device__ bf16 g_gs_hi[Tn * FFN], g_gs_lo[Tn * FFN];

static __device__ bf16 g_qhi[Tn * Cn],       g_qlo[Tn * Cn];
static __device__ bf16 g_khi[Tn * NKV * HD], g_klo[Tn * NKV * HD];
static __device__ bf16 g_vhi[Tn * NKV * HD], g_vlo[Tn * NKV * HD];

static __device__ bf16 g_wq_hi[Cn * Cn],        g_wq_lo[Cn * Cn];
static __device__ bf16 g_wk_hi[NKV * HD * Cn],  g_wk_lo[NKV * HD * Cn];
static __device__ bf16 g_wv_hi[NKV * HD * Cn],  g_wv_lo[NKV * HD * Cn];
static __device__ bf16 g_wo_hi[Cn * Cn],        g_wo_lo[Cn * Cn];
static __device__ bf16 g_wg_hi[FFN * Cn],       g_wg_lo[FFN * Cn];
static __device__ bf16 g_wu_hi[FFN * Cn],       g_wu_lo[FFN * Cn];
static __device__ bf16 g_wd_hi[Cn * FFN],       g_wd_lo[Cn * FFN];

__device__ __forceinline__ void split2(float x, bf16& hi, bf16& lo) {
    hi = __float2bfloat16(x);
    lo = __float2bfloat16(x - __bfloat162float(hi));
}

__device__ __forceinline__ uint32_t pack_bf2(bf16 a, bf16 b) {
    __nv_bfloat162 t; t.x = a; t.y = b;
    return *reinterpret_cast<uint32_t*>(&t);
}

// ---------------- weight / activation fp32 -> (hi, lo) bf16 ----------------
__global__ void convert_kernel(const float* __restrict__ w,
                               bf16* __restrict__ hi, bf16* __restrict__ lo, int n) {
    int i = blockIdx.x * blockDim.x + threadIdx.x;
    if (i < n) split2(w[i], hi[i], lo[i]);
}

// ---------------- RoPE cos/sin table (double sincos — fast-math immune) ----------------
__global__ void rope_table_kernel(float2* __restrict__ tab) {
    int idx = blockIdx.x * blockDim.x + threadIdx.x;
    if (idx >= Tn * 64) return;
    int i = idx & 63;
    int t = idx >> 6;
    double invf_d = pow(500000.0, -((double)(2 * i) / 128.0));
    float  invf_f = (float)invf_d;
    float  ang_f  = (float)t * invf_f;
    double c, s;
    sincos((double)ang_f, &s, &c);
    tab[idx] = make_float2((float)c, (float)s);
}

// ---------------- rmsnorm: one block per row, writes split bf16 ----------------
__global__ void __launch_bounds__(256) rmsnorm_kernel(const float* __restrict__ x,
                                                      const float* __restrict__ w,
                                                      bf16* __restrict__ ohi,
                                                      bf16* __restrict__ olo) {
    const int row = blockIdx.x;
    const float* xr = x + (size_t)row * Cn;
    float s = 0.f;
    for (int i = threadIdx.x; i < Cn; i += 256) {
        float v = xr[i];
        s = fmaf(v, v, s);
    }
    __shared__ float red[8];
    #pragma unroll
    for (int o = 16; o; o >>= 1) s += __shfl_xor_sync(0xffffffffu, s, o);
    if ((threadIdx.x & 31) == 0) red[threadIdx.x >> 5] = s;
    __syncthreads();
    if (threadIdx.x < 32) {
        float v = (threadIdx.x < 8) ? red[threadIdx.x] : 0.f;
        #pragma unroll
        for (int o = 4; o; o >>= 1) v += __shfl_xor_sync(0xffffffffu, v, o);
        if (threadIdx.x == 0) red[0] = v;
    }
    __syncthreads();
    const float scale = rsqrtf(red[0] * (1.0f / Cn) + 1e-5f);
    size_t base = (size_t)row * Cn;
    for (int i = threadIdx.x; i < Cn; i += 256) {
        float v = xr[i] * scale * w[i];
        split2(v, ohi[base + i], olo[base + i]);
    }
}

// =====================================================================
// bf16x3 tensor-core GEMM:  C[m,n] = sum_k A[m,k]*B[n,k] (+ R[m,n])
// =====================================================================
#define STAGES 3
#define TILE_BYTES  (128 * 64)
#define STAGE_BYTES (4 * TILE_BYTES)
#define GEMM_SMEM   (STAGES * STAGE_BYTES)

__device__ __forceinline__ uint32_t sw(uint32_t row, uint32_t chunk) {
    return (row << 6) + (((chunk ^ (row >> 1)) & 3u) << 4);
}

__device__ __forceinline__ void cp16(uint32_t dst, const void* src) {
    asm volatile("cp.async.cg.shared.global [%0], [%1], 16;\n" :: "r"(dst), "l"(src));
}

__device__ __forceinline__ void ldm4(uint32_t* r, uint32_t addr) {
    asm volatile("ldmatrix.sync.aligned.m8n8.x4.shared.b16 {%0,%1,%2,%3}, [%4];\n"
                 : "=r"(r[0]), "=r"(r[1]), "=r"(r[2]), "=r"(r[3]) : "r"(addr));
}

__device__ __forceinline__ void ldm4t(uint32_t* r, uint32_t addr) {
    asm volatile("ldmatrix.sync.aligned.m8n8.x4.trans.shared.b16 {%0,%1,%2,%3}, [%4];\n"
                 : "=r"(r[0]), "=r"(r[1]), "=r"(r[2]), "=r"(r[3]) : "r"(addr));
}

__device__ __forceinline__ void mma16816(float* c, const uint32_t* a, const uint32_t* b) {
    asm volatile("mma.sync.aligned.m16n8k16.row.col.f32.bf16.bf16.f32 "
                 "{%0,%1,%2,%3},{%4,%5,%6,%7},{%8,%9},{%0,%1,%2,%3};\n"
                 : "+f"(c[0]), "+f"(c[1]), "+f"(c[2]), "+f"(c[3])
                 : "r"(a[0]), "r"(a[1]), "r"(a[2]), "r"(a[3]), "r"(b[0]), "r"(b[1]));
}

__global__ void __launch_bounds__(256, 1) gemm_bf16x3(
        const bf16* __restrict__ Ahi, const bf16* __restrict__ Alo,
        const bf16* __restrict__ Bhi, const bf16* __restrict__ Blo,
        float* __restrict__ C, const float* __restrict__ R,
        int M, int N, int K) {
    extern __shared__ __align__(128) char smem_raw[];
    const uint32_t smem_u = (uint32_t)__cvta_generic_to_shared(smem_raw);
    const int tid  = threadIdx.x;
    const int warp = tid >> 5;
    const int lane = tid & 31;
    const int wm   = warp & 3;
    const int wn   = warp >> 2;
    const int bm   = blockIdx.y * 128;
    const int bn   = blockIdx.x * 128;

    float acc[2][8][4];
    #pragma unroll
    for (int i = 0; i < 2; i++)
        #pragma unroll
        for (int j = 0; j < 8; j++)
            #pragma unroll
            for (int v = 0; v < 4; v++) acc[i][j][v] = 0.f;

    const int kiters = K >> 5;

    auto load_stage = [&](int stage, int kt) {
        const uint32_t sbase = smem_u + stage * STAGE_BYTES;
        const bf16* gptr[4] = {Ahi, Alo, Bhi, Blo};
        #pragma unroll
        for (int tile = 0; tile < 4; tile++) {
            const int rbase = (tile < 2) ? bm : bn;
            const bf16* gp = gptr[tile];
            #pragma unroll
            for (int rep = 0; rep < 2; rep++) {
                int idx  = tid + rep * 256;
                int row  = idx >> 2;
                int ch   = idx & 3;
                const void* src = gp + (size_t)(rbase + row) * K + kt + ch * 8;
                cp16(sbase + tile * TILE_BYTES + sw(row, ch), src);
            }
        }
    };

    #pragma unroll
    for (int s = 0; s < STAGES - 1; s++) {
        load_stage(s, s * 32);
        asm volatile("cp.async.commit_group;\n");
    }

    for (int it = 0; it < kiters; ++it) {
        asm volatile("cp.async.wait_group %0;\n" :: "n"(STAGES - 2));
        __syncthreads();
        int pf = it + STAGES - 1;
        if (pf < kiters) load_stage(pf % STAGES, pf * 32);
        asm volatile("cp.async.commit_group;\n");

        const uint32_t sb   = smem_u + (it % STAGES) * STAGE_BYTES;
        const uint32_t sAhi = sb;
        const uint32_t sAlo = sb + TILE_BYTES;
        const uint32_t sBhi = sb + 2 * TILE_BYTES;
        const uint32_t sBlo = sb + 3 * TILE_BYTES;

        #pragma unroll
        for (int kf = 0; kf < 2; kf++) {
            uint32_t ah[2][4], al[2][4];
            #pragma unroll
            for (int mt = 0; mt < 2; mt++) {
                uint32_t row = wm * 32 + mt * 16 + (lane & 15);
                uint32_t ch  = kf * 2 + (lane >> 4);
                uint32_t off = sw(row, ch);
                ldm4(ah[mt], sAhi + off);
                ldm4(al[mt], sAlo + off);
            }
            uint32_t bh[8][2], bl[8][2];
            #pragma unroll
            for (int p = 0; p < 4; p++) {
                uint32_t rowb = wn * 64 + p * 16 + (lane & 7) + ((lane >> 4) & 1) * 8;
                uint32_t chb  = kf * 2 + ((lane >> 3) & 1);
                uint32_t offb = sw(rowb, chb);
                uint32_t r[4];
                ldm4(r, sBhi + offb);
                bh[2 * p][0] = r[0]; bh[2 * p][1] = r[1];
                bh[2 * p + 1][0] = r[2]; bh[2 * p + 1][1] = r[3];
                ldm4(r, sBlo + offb);
                bl[2 * p][0] = r[0]; bl[2 * p][1] = r[1];
                bl[2 * p + 1][0] = r[2]; bl[2 * p + 1][1] = r[3];
            }
            #pragma unroll
            for (int mt = 0; mt < 2; mt++)
                #pragma unroll
                for (int nt = 0; nt < 8; nt++) {
                    mma16816(acc[mt][nt], ah[mt], bh[nt]);
                    mma16816(acc[mt][nt], ah[mt], bl[nt]);
                    mma16816(acc[mt][nt], al[mt], bh[nt]);
                }
        }
    }

    const int rb = bm + wm * 32;
    const int cb = bn + wn * 64;
    #pragma unroll
    for (int mt = 0; mt < 2; mt++)
        #pragma unroll
        for (int nt = 0; nt < 8; nt++) {
            int r0 = rb + mt * 16 + (lane >> 2);
            int c  = cb + nt * 8 + (lane & 3) * 2;
            size_t i0 = (size_t)r0 * N + c;
            size_t i1 = (size_t)(r0 + 8) * N + c;
            float2 v0 = make_float2(acc[mt][nt][0], acc[mt][nt][1]);
            float2 v1 = make_float2(acc[mt][nt][2], acc[mt][nt][3]);
            if (R) {
                float2 q0 = *(const float2*)(R + i0);
                float2 q1 = *(const float2*)(R + i1);
                v0.x += q0.x; v0.y += q0.y;
                v1.x += q1.x; v1.y += q1.y;
            }
            *(float2*)(C + i0) = v0;
            *(float2*)(C + i1) = v1;
        }
}

// ---------------- RoPE + split: fp32 q/k -> rotated split bf16 ----------------
__global__ void rope_split_kernel(const float* __restrict__ q, const float* __restrict__ k,
                                  const float2* __restrict__ tab,
                                  bf16* __restrict__ qhi, bf16* __restrict__ qlo,
                                  bf16* __restrict__ khi, bf16* __restrict__ klo) {
    const int total = Tn * (NH + NKV) * 64;
    int idx = blockIdx.x * blockDim.x + threadIdx.x;
    if (idx >= total) return;
    int i    = idx & 63;
    int rest = idx >> 6;
    int head = rest % (NH + NKV);
    int t    = rest / (NH + NKV);
    float2 cs = tab[t * 64 + i];
    float c = cs.x, s = cs.y;
    if (head < NH) {
        size_t off = (size_t)t * Cn + head * HD + 2 * i;
        float2 ab = *(const float2*)(q + off);
        float a = ab.x, b = ab.y;
        float r0 = fmaf(a, c, -b * s);
        float r1 = fmaf(a, s,  b * c);
        split2(r0, qhi[off], qlo[off]);
        split2(r1, qhi[off + 1], qlo[off + 1]);
    } else {
        size_t off = (size_t)t * (NKV * HD) + (head - NH) * HD + 2 * i;
        float2 ab = *(const float2*)(k + off);
        float a = ab.x, b = ab.y;
        float r0 = fmaf(a, c, -b * s);
        float r1 = fmaf(a, s,  b * c);
        split2(r0, khi[off], klo[off]);
        split2(r1, khi[off + 1], klo[off + 1]);
    }
}

// =====================================================================
// Tensor-core causal flash attention (split precision)
// =====================================================================
#define AQ_HI 0
#define AQ_LO 32768
#define AKV   65536
#define AKV_STAGE 65536
#define AK_LO 16384
#define AV_HI 32768
#define AV_LO 49152
#define ATTN_SMEM (AKV + 2 * AKV_STAGE)

__device__ __forceinline__ uint32_t sw256(uint32_t row, uint32_t ch) {
    return (row << 8) + ((((ch ^ row) & 7u) | (ch & 8u)) << 4);
}

__global__ void __launch_bounds__(256, 1) attn_tc(
        const bf16* __restrict__ qhi, const bf16* __restrict__ qlo,
        const bf16* __restrict__ khi, const bf16* __restrict__ klo,
        const bf16* __restrict__ vhi, const bf16* __restrict__ vlo,
        bf16* __restrict__ yhi, bf16* __restrict__ ylo) {
    extern __shared__ __align__(128) char smem_raw[];
    const uint32_t sb = (uint32_t)__cvta_generic_to_shared(smem_raw);
    const int qt   = 31 - blockIdx.x;          // big tiles first
    const int head = blockIdx.y;
    const int kvh  = head >> 2;
    const int qb   = qt * 128;
    const int tid  = threadIdx.x;
    const int warp = tid >> 5;
    const int lane = tid & 31;
    const int njt  = 2 * qt + 2;

    #pragma unroll
    for (int i = 0; i < 8; i++) {
        int idx = tid + i * 256;
        int row = idx >> 4;
        int ch  = idx & 15;
        size_t g = (size_t)(qb + row) * Cn + head * HD + ch * 8;
        uint32_t off = sw256(row, ch);
        cp16(sb + AQ_HI + off, qhi + g);
        cp16(sb + AQ_LO + off, qlo + g);
    }

    auto load_kv = [&](int jt, int buf) {
        const uint32_t base = sb + AKV + buf * AKV_STAGE;
        #pragma unroll
        for (int i = 0; i < 4; i++) {
            int idx = tid + i * 256;
            int row = idx >> 4;
            int ch  = idx & 15;
            size_t g = (size_t)(jt * 64 + row) * (NKV * HD) + kvh * HD + ch * 8;
            uint32_t off = sw256(row, ch);
            cp16(base + off,          khi + g);
            cp16(base + AK_LO + off,  klo + g);
            cp16(base + AV_HI + off,  vhi + g);
            cp16(base + AV_LO + off,  vlo + g);
        }
    };

    load_kv(0, 0);
    asm volatile("cp.async.commit_group;\n");   // group: Q + kv0

    float m0 = -1e30f, m1 = -1e30f, l0 = 0.f, l1 = 0.f;
    float o[16][4];
    #pragma unroll
    for (int nt = 0; nt < 16; nt++)
        #pragma unroll
        for (int e = 0; e < 4; e++) o[nt][e] = 0.f;

    const float cs = 0.12751743621340608f;      // log2(e)/sqrt(128)
    const int r0g = qb + (warp << 4) + (lane >> 2);
    const int r1g = r0g + 8;

    for (int jt = 0; jt < njt; jt++) {
        if (jt + 1 < njt) load_kv(jt + 1, (jt + 1) & 1);
        asm volatile("cp.async.commit_group;\n");
        asm volatile("cp.async.wait_group 1;\n");
        __syncthreads();

        const uint32_t kb   = sb + AKV + (jt & 1) * AKV_STAGE;
        const uint32_t kbl  = kb + AK_LO;
        const uint32_t vb   = kb + AV_HI;
        const uint32_t vbl  = kb + AV_LO;

        // ---- S = Q K^T ----
        float sacc[8][4];
        #pragma unroll
        for (int nt = 0; nt < 8; nt++)
            #pragma unroll
            for (int e = 0; e < 4; e++) sacc[nt][e] = 0.f;

        #pragma unroll
        for (int ks = 0; ks < 8; ks++) {
            uint32_t ah[4], al[4];
            {
                uint32_t row = (warp << 4) + (lane & 15);
                uint32_t ch  = ks * 2 + (lane >> 4);
                uint32_t off = sw256(row, ch);
                ldm4(ah, sb + AQ_HI + off);
                ldm4(al, sb + AQ_LO + off);
            }
            #pragma unroll
            for (int p = 0; p < 4; p++) {
                uint32_t rowb = p * 16 + (lane & 7) + ((lane >> 4) & 1) * 8;
                uint32_t chb  = ks * 2 + ((lane >> 3) & 1);
                uint32_t offb = sw256(rowb, chb);
                uint32_t bh[4], bl[4];
                ldm4(bh, kb + offb);
                ldm4(bl, kbl + offb);
                mma16816(sacc[2 * p],     ah, bh);
                mma16816(sacc[2 * p],     ah, bl);
                mma16816(sacc[2 * p],     al, bh);
                mma16816(sacc[2 * p + 1], ah, bh + 2);
                mma16816(sacc[2 * p + 1], ah, bl + 2);
                mma16816(sacc[2 * p + 1], al, bh + 2);
            }
        }

        // ---- scale + mask ----
        const bool domask = (jt >= 2 * qt);
        #pragma unroll
        for (int nt = 0; nt < 8; nt++) {
            int cbase = jt * 64 + nt * 8 + (lane & 3) * 2;
            #pragma unroll
            for (int e = 0; e < 4; e++) {
                float v = sacc[nt][e] * cs;
                if (domask) {
                    int col = cbase + (e & 1);
                    int row = (e < 2) ? r0g : r1g;
                    if (col > row) v = -1e30f;
                }
                sacc[nt][e] = v;
            }
        }

        // ---- online softmax (base-2) ----
        float mx0 = -1e30f, mx1 = -1e30f;
        #pragma unroll
        for (int nt = 0; nt < 8; nt++) {
            mx0 = fmaxf(mx0, fmaxf(sacc[nt][0], sacc[nt][1]));
            mx1 = fmaxf(mx1, fmaxf(sacc[nt][2], sacc[nt][3]));
        }
        mx0 = fmaxf(mx0, __shfl_xor_sync(0xffffffffu, mx0, 1));
        mx0 = fmaxf(mx0, __shfl_xor_sync(0xffffffffu, mx0, 2));
        mx1 = fmaxf(mx1, __shfl_xor_sync(0xffffffffu, mx1, 1));
        mx1 = fmaxf(mx1, __shfl_xor_sync(0xffffffffu, mx1, 2));
        float mn0 = fmaxf(m0, mx0);
        float mn1 = fmaxf(m1, mx1);

        float ls0 = 0.f, ls1 = 0.f;
        #pragma unroll
        for (int nt = 0; nt < 8; nt++) {
            float p0 = exp2f(sacc[nt][0] - mn0);
            float p1 = exp2f(sacc[nt][1] - mn0);
            float p2 = exp2f(sacc[nt][2] - mn1);
            float p3 = exp2f(sacc[nt][3] - mn1);
            ls0 += p0 + p1;
            ls1 += p2 + p3;
            sacc[nt][0] = p0; sacc[nt][1] = p1; sacc[nt][2] = p2; sacc[nt][3] = p3;
        }
        ls0 += __shfl_xor_sync(0xffffffffu, ls0, 1);
        ls0 += __shfl_xor_sync(0xffffffffu, ls0, 2);
        ls1 += __shfl_xor_sync(0xffffffffu, ls1, 1);
        ls1 += __shfl_xor_sync(0xffffffffu, ls1, 2);

        float a0 = exp2f(m0 - mn0);
        float a1 = exp2f(m1 - mn1);
        m0 = mn0; m1 = mn1;
        l0 = l0 * a0 + ls0;
        l1 = l1 * a1 + ls1;
        #pragma unroll
        for (int nt = 0; nt < 16; nt++) {
            o[nt][0] *= a0; o[nt][1] *= a0;
            o[nt][2] *= a1; o[nt][3] *= a1;
        }

        // ---- O += P V ----
        #pragma unroll
        for (int ks = 0; ks < 4; ks++) {
            bf16 h0, q0, h1, q1, h2, q2, h3, q3;
            uint32_t ah[4], al[4];
            split2(sacc[2 * ks][0], h0, q0); split2(sacc[2 * ks][1], h1, q1);
            ah[0] = pack_bf2(h0, h1); al[0] = pack_bf2(q0, q1);
            split2(sacc[2 * ks][2], h0, q0); split2(sacc[2 * ks][3], h1, q1);
            ah[1] = pack_bf2(h0, h1); al[1] = pack_bf2(q0, q1);
            split2(sacc[2 * ks + 1][0], h2, q2); split2(sacc[2 * ks + 1][1], h3, q3);
            ah[2] = pack_bf2(h2, h3); al[2] = pack_bf2(q2, q3);
            split2(sacc[2 * ks + 1][2], h2, q2); split2(sacc[2 * ks + 1][3], h3, q3);
            ah[3] = pack_bf2(h2, h3); al[3] = pack_bf2(q2, q3);

            #pragma unroll
            for (int dc = 0; dc < 8; dc++) {
                uint32_t row = ks * 16 + (lane & 15);
                uint32_t ch  = dc * 2 + (lane >> 4);
                uint32_t off = sw256(row, ch);
                uint32_t bh[4], bl[4];
                ldm4t(bh, vb + off);
                ldm4t(bl, vbl + off);
                mma16816(o[2 * dc],     ah, bh);
                mma16816(o[2 * dc],     al, bh);
                mma16816(o[2 * dc],     ah, bl);
                mma16816(o[2 * dc + 1], ah, bh + 2);
                mma16816(o[2 * dc + 1], al, bh + 2);
                mma16816(o[2 * dc + 1], ah, bl + 2);
            }
        }
        __syncthreads();
    }

    // ---- epilogue ----
    float inv0 = 1.0f / l0;
    float inv1 = 1.0f / l1;
    #pragma unroll
    for (int nt = 0; nt < 16; nt++) {
        int c = head * HD + nt * 8 + (lane & 3) * 2;
        size_t i0 = (size_t)r0g * Cn + c;
        size_t i1 = (size_t)r1g * Cn + c;
        bf16 a, b, e, f;
        split2(o[nt][0] * inv0, a, e);
        split2(o[nt][1] * inv0, b, f);
        *(uint32_t*)(yhi + i0) = pack_bf2(a, b);
        *(uint32_t*)(ylo + i0) = pack_bf2(e, f);
        split2(o[nt][2] * inv1, a, e);
        split2(o[nt][3] * inv1, b, f);
        *(uint32_t*)(yhi + i1) = pack_bf2(a, b);
        *(uint32_t*)(ylo + i1) = pack_bf2(e, f);
    }
}

// ---------------- silu(g) * u -> split bf16 ----------------
__global__ void silu_mul_kernel(const float* __restrict__ g, const float* __restrict__ u,
                                bf16* __restrict__ ohi, bf16* __restrict__ olo) {
    const int n4 = Tn * FFN / 4;
    int i = blockIdx.x * blockDim.x + threadIdx.x;
    if (i >= n4) return;
    float4 gv = ((const float4*)g)[i];
    float4 uv = ((const float4*)u)[i];
    float r0 = gv.x / (1.f + expf(-gv.x)) * uv.x;
    float r1 = gv.y / (1.f + expf(-gv.y)) * uv.y;
    float r2 = gv.z / (1.f + expf(-gv.z)) * uv.z;
    float r3 = gv.w / (1.f + expf(-gv.w)) * uv.w;
    int b = i * 4;
    split2(r0, ohi[b + 0], olo[b + 0]);
    split2(r1, ohi[b + 1], olo[b + 1]);
    split2(r2, ohi[b + 2], olo[b + 2]);
    split2(r3, ohi[b + 3], olo[b + 3]);
}

// ---------------- launch ----------------
extern "C" void kernel_launch(void* const* d_in, const int* in_sizes, int n_in,
                              void* d_out, int out_size) {
    (void)in_sizes; (void)n_in; (void)out_size;
    const float* x           = (const float*)d_in[0];
    const float* attn_norm_w = (const float*)d_in[2];
    const float* wq          = (const float*)d_in[3];
    const float* wk          = (const float*)d_in[4];
    const float* wv          = (const float*)d_in[5];
    const float* wo          = (const float*)d_in[6];
    const float* ffn_norm_w  = (const float*)d_in[7];
    const float* w_gate      = (const float*)d_in[8];
    const float* w_up        = (const float*)d_in[9];
    const float* w_down      = (const float*)d_in[10];
    float* out = (float*)d_out;

    float *q, *k, *v, *g, *u;
    float2* rtab;
    bf16 *h_hi, *h_lo, *h2_hi, *h2_lo, *y_hi, *y_lo, *gs_hi, *gs_lo;
    bf16 *qhi, *qlo, *khi, *klo, *vhi, *vlo;
    bf16 *wq_hi, *wq_lo, *wk_hi, *wk_lo, *wv_hi, *wv_lo, *wo_hi, *wo_lo;
    bf16 *wg_hi, *wg_lo, *wu_hi, *wu_lo, *wd_hi, *wd_lo;

    cudaGetSymbolAddress((void**)&q,  g_q);
    cudaGetSymbolAddress((void**)&k,  g_k);
    cudaGetSymbolAddress((void**)&v,  g_v);
    cudaGetSymbolAddress((void**)&g,  g_g);
    cudaGetSymbolAddress((void**)&u,  g_u);
    cudaGetSymbolAddress((void**)&rtab, g_rope);
    cudaGetSymbolAddress((void**)&h_hi,  g_h_hi);  cudaGetSymbolAddress((void**)&h_lo,  g_h_lo);
    cudaGetSymbolAddress((void**)&h2_hi, g_h2_hi); cudaGetSymbolAddress((void**)&h2_lo, g_h2_lo);
    cudaGetSymbolAddress((void**)&y_hi,  g_y_hi);  cudaGetSymbolAddress((void**)&y_lo,  g_y_lo);
    cudaGetSymbolAddress((void**)&gs_hi, g_gs_hi); cudaGetSymbolAddress((void**)&gs_lo, g_gs_lo);
    cudaGetSymbolAddress((void**)&qhi, g_qhi); cudaGetSymbolAddress((void**)&qlo, g_qlo);
    cudaGetSymbolAddress((void**)&khi, g_khi); cudaGetSymbolAddress((void**)&klo, g_klo);
    cudaGetSymbolAddress((void**)&vhi, g_vhi); cudaGetSymbolAddress((void**)&vlo, g_vlo);
    cudaGetSymbolAddress((void**)&wq_hi, g_wq_hi); cudaGetSymbolAddress((void**)&wq_lo, g_wq_lo);
    cudaGetSymbolAddress((void**)&wk_hi, g_wk_hi); cudaGetSymbolAddress((void**)&wk_lo, g_wk_lo);
    cudaGetSymbolAddress((void**)&wv_hi, g_wv_hi); cudaGetSymbolAddress((void**)&wv_lo, g_wv_lo);
    cudaGetSymbolAddress((void**)&wo_hi, g_wo_hi); cudaGetSymbolAddress((void**)&wo_lo, g_wo_lo);
    cudaGetSymbolAddress((void**)&wg_hi, g_wg_hi); cudaGetSymbolAddress((void**)&wg_lo, g_wg_lo);
    cudaGetSymbolAddress((void**)&wu_hi, g_wu_hi); cudaGetSymbolAddress((void**)&wu_lo, g_wu_lo);
    cudaGetSymbolAddress((void**)&wd_hi, g_wd_hi); cudaGetSymbolAddress((void**)&wd_lo, g_wd_lo);

    cudaFuncSetAttribute(gemm_bf16x3, cudaFuncAttributeMaxDynamicSharedMemorySize, GEMM_SMEM);
    cudaFuncSetAttribute(attn_tc, cudaFuncAttributeMaxDynamicSharedMemorySize, ATTN_SMEM);

    // 0) RoPE table + weight splits
    rope_table_kernel<<<(Tn * 64 + 255) / 256, 256>>>(rtab);
    convert_kernel<<<(Cn * Cn + 255) / 256, 256>>>(wq, wq_hi, wq_lo, Cn * Cn);
    convert_kernel<<<(NKV * HD * Cn + 255) / 256, 256>>>(wk, wk_hi, wk_lo, NKV * HD * Cn);
    convert_kernel<<<(NKV * HD * Cn + 255) / 256, 256>>>(wv, wv_hi, wv_lo, NKV * HD * Cn);
    convert_kernel<<<(Cn * Cn + 255) / 256, 256>>>(wo, wo_hi, wo_lo, Cn * Cn);
    convert_kernel<<<(FFN * Cn + 255) / 256, 256>>>(w_gate, wg_hi, wg_lo, FFN * Cn);
    convert_kernel<<<(FFN * Cn + 255) / 256, 256>>>(w_up,   wu_hi, wu_lo, FFN * Cn);
    convert_kernel<<<(Cn * FFN + 255) / 256, 256>>>(w_down, wd_hi, wd_lo, Cn * FFN);

    // 1) rmsnorm1 -> split
    rmsnorm_kernel<<<Tn, 256>>>(x, attn_norm_w, h_hi, h_lo);
    // 2) Q/K/V projections (fp32 outputs)
    gemm_bf16x3<<<dim3(Cn / 128, Tn / 128), 256, GEMM_SMEM>>>(h_hi, h_lo, wq_hi, wq_lo, q, nullptr, Tn, Cn, Cn);
    gemm_bf16x3<<<dim3((NKV * HD) / 128, Tn / 128), 256, GEMM_SMEM>>>(h_hi, h_lo, wk_hi, wk_lo, k, nullptr, Tn, NKV * HD, Cn);
    gemm_bf16x3<<<dim3((NKV * HD) / 128, Tn / 128), 256, GEMM_SMEM>>>(h_hi, h_lo, wv_hi, wv_lo, v, nullptr, Tn, NKV * HD, Cn);
    // 3) RoPE + split q/k, split v
    {
        int total = Tn * (NH + NKV) * 64;
        rope_split_kernel<<<(total + 255) / 256, 256>>>(q, k, rtab, qhi, qlo, khi, klo);
        convert_kernel<<<(Tn * NKV * HD + 255) / 256, 256>>>(v, vhi, vlo, Tn * NKV * HD);
    }
    // 4) tensor-core causal flash attention -> split y
    attn_tc<<<dim3(32, NH), 256, ATTN_SMEM>>>(qhi, qlo, khi, klo, vhi, vlo, y_hi, y_lo);
    // 5) out = x + y @ wo^T
    gemm_bf16x3<<<dim3(Cn / 128, Tn / 128), 256, GEMM_SMEM>>>(y_hi, y_lo, wo_hi, wo_lo, out, x, Tn, Cn, Cn);
    // 6) rmsnorm2 -> split
    rmsnorm_kernel<<<Tn, 256>>>(out, ffn_norm_w, h2_hi, h2_lo);
    // 7) gate / up
    gemm_bf16x3<<<dim3(FFN / 128, Tn / 128), 256, GEMM_SMEM>>>(h2_hi, h2_lo, wg_hi, wg_lo, g, nullptr, Tn, FFN, Cn);
    gemm_bf16x3<<<dim3(FFN / 128, Tn / 128), 256, GEMM_SMEM>>>(h2_hi, h2_lo, wu_hi, wu_lo, u, nullptr, Tn, FFN, Cn);
    // 8) silu(g)*u -> split
    silu_mul_kernel<<<(Tn * FFN / 4 + 255) / 256, 256>>>(g, u, gs_hi, gs_lo);
    // 9) out += gs @ w_down^T
    gemm_bf16x3<<<dim3(Cn / 128, Tn / 128), 256, GEMM_SMEM>>>(gs_hi, gs_lo, wd_hi, wd_lo, out, out, Tn, Cn, FFN);
}

// round 7
// speedup vs baseline: 3.1040x; 1.0009x over previous
#include <cuda_runtime.h>
#include <cuda_bf16.h>
#include <math.h>
#include <stdint.h>

#define Tn   4096
#define Cn   2048
#define NH   16
#define NKV  4
#define HD   128
#define FFN  8192

typedef __nv_bfloat16 bf16;

// ---------------- scratch (static device globals; no allocation) ----------------
static __device__ float  g_q [Tn * Cn];
static __device__ float  g_k [Tn * NKV * HD];
static __device__ float  g_v [Tn * NKV * HD];
static __device__ float  g_g [Tn * FFN];
static __device__ float  g_u [Tn * FFN];
static __device__ float2 g_rope[Tn * 64];

static __device__ bf16 g_h_hi [Tn * Cn],  g_h_lo [Tn * Cn];
static __device__ bf16 g_h2_hi[Tn * Cn],  g_h2_lo[Tn * Cn];
static __device__ bf16 g_y_hi [Tn * Cn],  g_y_lo [Tn * Cn];
static __device__ bf16 g_gs_hi[Tn * FFN], g_gs_lo[Tn * FFN];

static __device__ bf16 g_qhi[Tn * Cn],       g_qlo[Tn * Cn];
static __device__ bf16 g_khi[Tn * NKV * HD], g_klo[Tn * NKV * HD];
static __device__ bf16 g_vhi[Tn * NKV * HD], g_vlo[Tn * NKV * HD];

static __device__ bf16 g_wq_hi[Cn * Cn],        g_wq_lo[Cn * Cn];
static __device__ bf16 g_wk_hi[NKV * HD * Cn],  g_wk_lo[NKV * HD * Cn];
static __device__ bf16 g_wv_hi[NKV * HD * Cn],  g_wv_lo[NKV * HD * Cn];
static __device__ bf16 g_wo_hi[Cn * Cn],        g_wo_lo[Cn * Cn];
static __device__ bf16 g_wg_hi[FFN * Cn],       g_wg_lo[FFN * Cn];
static __device__ bf16 g_wu_hi[FFN * Cn],       g_wu_lo[FFN * Cn];
static __device__ bf16 g_wd_hi[Cn * FFN],       g_wd_lo[Cn * FFN];

__device__ __forceinline__ void split2(float x, bf16& hi, bf16& lo) {
    hi = __float2bfloat16(x);
    lo = __float2bfloat16(x - __bfloat162float(hi));
}

__device__ __forceinline__ uint32_t pack_bf2(bf16 a, bf16 b) {
    __nv_bfloat162 t; t.x = a; t.y = b;
    return *reinterpret_cast<uint32_t*>(&t);
}

// ---------------- weight / activation fp32 -> (hi, lo) bf16 ----------------
__global__ void convert_kernel(const float* __restrict__ w,
                               bf16* __restrict__ hi, bf16* __restrict__ lo, int n) {
    int i = blockIdx.x * blockDim.x + threadIdx.x;
    if (i < n) split2(w[i], hi[i], lo[i]);
}

// ---------------- RoPE cos/sin table (double sincos — fast-math immune) ----------------
__global__ void rope_table_kernel(float2* __restrict__ tab) {
    int idx = blockIdx.x * blockDim.x + threadIdx.x;
    if (idx >= Tn * 64) return;
    int i = idx & 63;
    int t = idx >> 6;
    double invf_d = pow(500000.0, -((double)(2 * i) / 128.0));
    float  invf_f = (float)invf_d;
    float  ang_f  = (float)t * invf_f;
    double c, s;
    sincos((double)ang_f, &s, &c);
    tab[idx] = make_float2((float)c, (float)s);
}

// ---------------- rmsnorm: one block per row, writes split bf16 ----------------
__global__ void __launch_bounds__(256) rmsnorm_kernel(const float* __restrict__ x,
                                                      const float* __restrict__ w,
                                                      bf16* __restrict__ ohi,
                                                      bf16* __restrict__ olo) {
    const int row = blockIdx.x;
    const float* xr = x + (size_t)row * Cn;
    float s = 0.f;
    for (int i = threadIdx.x; i < Cn; i += 256) {
        float v = xr[i];
        s = fmaf(v, v, s);
    }
    __shared__ float red[8];
    #pragma unroll
    for (int o = 16; o; o >>= 1) s += __shfl_xor_sync(0xffffffffu, s, o);
    if ((threadIdx.x & 31) == 0) red[threadIdx.x >> 5] = s;
    __syncthreads();
    if (threadIdx.x < 32) {
        float v = (threadIdx.x < 8) ? red[threadIdx.x] : 0.f;
        #pragma unroll
        for (int o = 4; o; o >>= 1) v += __shfl_xor_sync(0xffffffffu, v, o);
        if (threadIdx.x == 0) red[0] = v;
    }
    __syncthreads();
    const float scale = rsqrtf(red[0] * (1.0f / Cn) + 1e-5f);
    size_t base = (size_t)row * Cn;
    for (int i = threadIdx.x; i < Cn; i += 256) {
        float v = xr[i] * scale * w[i];
        split2(v, ohi[base + i], olo[base + i]);
    }
}

// =====================================================================
// bf16x3 tensor-core GEMM with product-major mma issue (chain-free)
// =====================================================================
#define STAGES 3
#define TILE_BYTES  (128 * 64)
#define STAGE_BYTES (4 * TILE_BYTES)
#define GEMM_SMEM   (STAGES * STAGE_BYTES)

__device__ __forceinline__ uint32_t sw(uint32_t row, uint32_t chunk) {
    return (row << 6) + (((chunk ^ (row >> 1)) & 3u) << 4);
}

__device__ __forceinline__ void cp16(uint32_t dst, const void* src) {
    asm volatile("cp.async.cg.shared.global [%0], [%1], 16;\n" :: "r"(dst), "l"(src));
}

__device__ __forceinline__ void ldm4(uint32_t* r, uint32_t addr) {
    asm volatile("ldmatrix.sync.aligned.m8n8.x4.shared.b16 {%0,%1,%2,%3}, [%4];\n"
                 : "=r"(r[0]), "=r"(r[1]), "=r"(r[2]), "=r"(r[3]) : "r"(addr));
}

__device__ __forceinline__ void ldm4t(uint32_t* r, uint32_t addr) {
    asm volatile("ldmatrix.sync.aligned.m8n8.x4.trans.shared.b16 {%0,%1,%2,%3}, [%4];\n"
                 : "=r"(r[0]), "=r"(r[1]), "=r"(r[2]), "=r"(r[3]) : "r"(addr));
}

__device__ __forceinline__ void mma16816(float* c, const uint32_t* a, const uint32_t* b) {
    asm volatile("mma.sync.aligned.m16n8k16.row.col.f32.bf16.bf16.f32 "
                 "{%0,%1,%2,%3},{%4,%5,%6,%7},{%8,%9},{%0,%1,%2,%3};\n"
                 : "+f"(c[0]), "+f"(c[1]), "+f"(c[2]), "+f"(c[3])
                 : "r"(a[0]), "r"(a[1]), "r"(a[2]), "r"(a[3]), "r"(b[0]), "r"(b[1]));
}

__global__ void __launch_bounds__(256, 1) gemm_bf16x3(
        const bf16* __restrict__ Ahi, const bf16* __restrict__ Alo,
        const bf16* __restrict__ Bhi, const bf16* __restrict__ Blo,
        float* __restrict__ C, const float* __restrict__ R,
        int M, int N, int K) {
    extern __shared__ __align__(128) char smem_raw[];
    const uint32_t smem_u = (uint32_t)__cvta_generic_to_shared(smem_raw);
    const int tid  = threadIdx.x;
    const int warp = tid >> 5;
    const int lane = tid & 31;
    const int wm   = warp & 3;
    const int wn   = warp >> 2;
    const int bm   = blockIdx.y * 128;
    const int bn   = blockIdx.x * 128;

    float acc[2][8][4];
    #pragma unroll
    for (int i = 0; i < 2; i++)
        #pragma unroll
        for (int j = 0; j < 8; j++)
            #pragma unroll
            for (int v = 0; v < 4; v++) acc[i][j][v] = 0.f;

    const int kiters = K >> 5;

    auto load_stage = [&](int stage, int kt) {
        const uint32_t sbase = smem_u + stage * STAGE_BYTES;
        const bf16* gptr[4] = {Ahi, Alo, Bhi, Blo};
        #pragma unroll
        for (int tile = 0; tile < 4; tile++) {
            const int rbase = (tile < 2) ? bm : bn;
            const bf16* gp = gptr[tile];
            #pragma unroll
            for (int rep = 0; rep < 2; rep++) {
                int idx  = tid + rep * 256;
                int row  = idx >> 2;
                int ch   = idx & 3;
                const void* src = gp + (size_t)(rbase + row) * K + kt + ch * 8;
                cp16(sbase + tile * TILE_BYTES + sw(row, ch), src);
            }
        }
    };

    #pragma unroll
    for (int s = 0; s < STAGES - 1; s++) {
        load_stage(s, s * 32);
        asm volatile("cp.async.commit_group;\n");
    }

    for (int it = 0; it < kiters; ++it) {
        asm volatile("cp.async.wait_group %0;\n" :: "n"(STAGES - 2));
        __syncthreads();
        int pf = it + STAGES - 1;
        if (pf < kiters) load_stage(pf % STAGES, pf * 32);
        asm volatile("cp.async.commit_group;\n");

        const uint32_t sb   = smem_u + (it % STAGES) * STAGE_BYTES;
        const uint32_t sAhi = sb;
        const uint32_t sAlo = sb + TILE_BYTES;
        const uint32_t sBhi = sb + 2 * TILE_BYTES;
        const uint32_t sBlo = sb + 3 * TILE_BYTES;

        #pragma unroll
        for (int kf = 0; kf < 2; kf++) {
            uint32_t ah[2][4], al[2][4];
            #pragma unroll
            for (int mt = 0; mt < 2; mt++) {
                uint32_t row = wm * 32 + mt * 16 + (lane & 15);
                uint32_t ch  = kf * 2 + (lane >> 4);
                uint32_t off = sw(row, ch);
                ldm4(ah[mt], sAhi + off);
                ldm4(al[mt], sAlo + off);
            }
            uint32_t bh[8][2], bl[8][2];
            #pragma unroll
            for (int p = 0; p < 4; p++) {
                uint32_t rowb = wn * 64 + p * 16 + (lane & 7) + ((lane >> 4) & 1) * 8;
                uint32_t chb  = kf * 2 + ((lane >> 3) & 1);
                uint32_t offb = sw(rowb, chb);
                uint32_t r[4];
                ldm4(r, sBhi + offb);
                bh[2 * p][0] = r[0]; bh[2 * p][1] = r[1];
                bh[2 * p + 1][0] = r[2]; bh[2 * p + 1][1] = r[3];
                ldm4(r, sBlo + offb);
                bl[2 * p][0] = r[0]; bl[2 * p][1] = r[1];
                bl[2 * p + 1][0] = r[2]; bl[2 * p + 1][1] = r[3];
            }
            // product-major issue: 16 independent mmas per pass, no RAW chains.
            // per-accumulator order preserved (hh, hl, lh) -> bit-identical results.
            #pragma unroll
            for (int mt = 0; mt < 2; mt++)
                #pragma unroll
                for (int nt = 0; nt < 8; nt++)
                    mma16816(acc[mt][nt], ah[mt], bh[nt]);
            #pragma unroll
            for (int mt = 0; mt < 2; mt++)
                #pragma unroll
                for (int nt = 0; nt < 8; nt++)
                    mma16816(acc[mt][nt], ah[mt], bl[nt]);
            #pragma unroll
            for (int mt = 0; mt < 2; mt++)
                #pragma unroll
                for (int nt = 0; nt < 8; nt++)
                    mma16816(acc[mt][nt], al[mt], bh[nt]);
        }
    }

    const int rb = bm + wm * 32;
    const int cb = bn + wn * 64;
    #pragma unroll
    for (int mt = 0; mt < 2; mt++)
        #pragma unroll
        for (int nt = 0; nt < 8; nt++) {
            int r0 = rb + mt * 16 + (lane >> 2);
            int c  = cb + nt * 8 + (lane & 3) * 2;
            size_t i0 = (size_t)r0 * N + c;
            size_t i1 = (size_t)(r0 + 8) * N + c;
            float2 v0 = make_float2(acc[mt][nt][0], acc[mt][nt][1]);
            float2 v1 = make_float2(acc[mt][nt][2], acc[mt][nt][3]);
            if (R) {
                float2 q0 = *(const float2*)(R + i0);
                float2 q1 = *(const float2*)(R + i1);
                v0.x += q0.x; v0.y += q0.y;
                v1.x += q1.x; v1.y += q1.y;
            }
            *(float2*)(C + i0) = v0;
            *(float2*)(C + i1) = v1;
        }
}

// ---------------- RoPE + split: fp32 q/k -> rotated split bf16 ----------------
__global__ void rope_split_kernel(const float* __restrict__ q, const float* __restrict__ k,
                                  const float2* __restrict__ tab,
                                  bf16* __restrict__ qhi, bf16* __restrict__ qlo,
                                  bf16* __restrict__ khi, bf16* __restrict__ klo) {
    const int total = Tn * (NH + NKV) * 64;
    int idx = blockIdx.x * blockDim.x + threadIdx.x;
    if (idx >= total) return;
    int i    = idx & 63;
    int rest = idx >> 6;
    int head = rest % (NH + NKV);
    int t    = rest / (NH + NKV);
    float2 cs = tab[t * 64 + i];
    float c = cs.x, s = cs.y;
    if (head < NH) {
        size_t off = (size_t)t * Cn + head * HD + 2 * i;
        float2 ab = *(const float2*)(q + off);
        float a = ab.x, b = ab.y;
        float r0 = fmaf(a, c, -b * s);
        float r1 = fmaf(a, s,  b * c);
        split2(r0, qhi[off], qlo[off]);
        split2(r1, qhi[off + 1], qlo[off + 1]);
    } else {
        size_t off = (size_t)t * (NKV * HD) + (head - NH) * HD + 2 * i;
        float2 ab = *(const float2*)(k + off);
        float a = ab.x, b = ab.y;
        float r0 = fmaf(a, c, -b * s);
        float r1 = fmaf(a, s,  b * c);
        split2(r0, khi[off], klo[off]);
        split2(r1, khi[off + 1], klo[off + 1]);
    }
}

// =====================================================================
// Tensor-core causal flash attention (split precision, chain-free issue)
// =====================================================================
#define AQ_HI 0
#define AQ_LO 32768
#define AKV   65536
#define AKV_STAGE 65536
#define AK_LO 16384
#define AV_HI 32768
#define AV_LO 49152
#define ATTN_SMEM (AKV + 2 * AKV_STAGE)

__device__ __forceinline__ uint32_t sw256(uint32_t row, uint32_t ch) {
    return (row << 8) + ((((ch ^ row) & 7u) | (ch & 8u)) << 4);
}

__global__ void __launch_bounds__(256, 1) attn_tc(
        const bf16* __restrict__ qhi, const bf16* __restrict__ qlo,
        const bf16* __restrict__ khi, const bf16* __restrict__ klo,
        const bf16* __restrict__ vhi, const bf16* __restrict__ vlo,
        bf16* __restrict__ yhi, bf16* __restrict__ ylo) {
    extern __shared__ __align__(128) char smem_raw[];
    const uint32_t sb = (uint32_t)__cvta_generic_to_shared(smem_raw);
    const int qt   = 31 - blockIdx.x;
    const int head = blockIdx.y;
    const int kvh  = head >> 2;
    const int qb   = qt * 128;
    const int tid  = threadIdx.x;
    const int warp = tid >> 5;
    const int lane = tid & 31;
    const int njt  = 2 * qt + 2;

    #pragma unroll
    for (int i = 0; i < 8; i++) {
        int idx = tid + i * 256;
        int row = idx >> 4;
        int ch  = idx & 15;
        size_t g = (size_t)(qb + row) * Cn + head * HD + ch * 8;
        uint32_t off = sw256(row, ch);
        cp16(sb + AQ_HI + off, qhi + g);
        cp16(sb + AQ_LO + off, qlo + g);
    }

    auto load_kv = [&](int jt, int buf) {
        const uint32_t base = sb + AKV + buf * AKV_STAGE;
        #pragma unroll
        for (int i = 0; i < 4; i++) {
            int idx = tid + i * 256;
            int row = idx >> 4;
            int ch  = idx & 15;
            size_t g = (size_t)(jt * 64 + row) * (NKV * HD) + kvh * HD + ch * 8;
            uint32_t off = sw256(row, ch);
            cp16(base + off,          khi + g);
            cp16(base + AK_LO + off,  klo + g);
            cp16(base + AV_HI + off,  vhi + g);
            cp16(base + AV_LO + off,  vlo + g);
        }
    };

    load_kv(0, 0);
    asm volatile("cp.async.commit_group;\n");

    float m0 = -1e30f, m1 = -1e30f, l0 = 0.f, l1 = 0.f;
    float o[16][4];
    #pragma unroll
    for (int nt = 0; nt < 16; nt++)
        #pragma unroll
        for (int e = 0; e < 4; e++) o[nt][e] = 0.f;

    const float cs = 0.12751743621340608f;      // log2(e)/sqrt(128)
    const int r0g = qb + (warp << 4) + (lane >> 2);
    const int r1g = r0g + 8;

    for (int jt = 0; jt < njt; jt++) {
        if (jt + 1 < njt) load_kv(jt + 1, (jt + 1) & 1);
        asm volatile("cp.async.commit_group;\n");
        asm volatile("cp.async.wait_group 1;\n");
        __syncthreads();

        const uint32_t kb   = sb + AKV + (jt & 1) * AKV_STAGE;
        const uint32_t kbl  = kb + AK_LO;
        const uint32_t vb   = kb + AV_HI;
        const uint32_t vbl  = kb + AV_LO;

        // ---- S = Q K^T (product-major, chain-free) ----
        float sacc[8][4];
        #pragma unroll
        for (int nt = 0; nt < 8; nt++)
            #pragma unroll
            for (int e = 0; e < 4; e++) sacc[nt][e] = 0.f;

        #pragma unroll
        for (int ks = 0; ks < 8; ks++) {
            uint32_t ah[4], al[4];
            {
                uint32_t row = (warp << 4) + (lane & 15);
                uint32_t ch  = ks * 2 + (lane >> 4);
                uint32_t off = sw256(row, ch);
                ldm4(ah, sb + AQ_HI + off);
                ldm4(al, sb + AQ_LO + off);
            }
            uint32_t bh[8][2], bl[8][2];
            #pragma unroll
            for (int p = 0; p < 4; p++) {
                uint32_t rowb = p * 16 + (lane & 7) + ((lane >> 4) & 1) * 8;
                uint32_t chb  = ks * 2 + ((lane >> 3) & 1);
                uint32_t offb = sw256(rowb, chb);
                uint32_t r[4];
                ldm4(r, kb + offb);
                bh[2 * p][0] = r[0]; bh[2 * p][1] = r[1];
                bh[2 * p + 1][0] = r[2]; bh[2 * p + 1][1] = r[3];
                ldm4(r, kbl + offb);
                bl[2 * p][0] = r[0]; bl[2 * p][1] = r[1];
                bl[2 * p + 1][0] = r[2]; bl[2 * p + 1][1] = r[3];
            }
            // per-acc order preserved: hh, hl, lh
            #pragma unroll
            for (int nt = 0; nt < 8; nt++) mma16816(sacc[nt], ah, bh[nt]);
            #pragma unroll
            for (int nt = 0; nt < 8; nt++) mma16816(sacc[nt], ah, bl[nt]);
            #pragma unroll
            for (int nt = 0; nt < 8; nt++) mma16816(sacc[nt], al, bh[nt]);
        }

        // ---- scale + mask ----
        const bool domask = (jt >= 2 * qt);
        #pragma unroll
        for (int nt = 0; nt < 8; nt++) {
            int cbase = jt * 64 + nt * 8 + (lane & 3) * 2;
            #pragma unroll
            for (int e = 0; e < 4; e++) {
                float v = sacc[nt][e] * cs;
                if (domask) {
                    int col = cbase + (e & 1);
                    int row = (e < 2) ? r0g : r1g;
                    if (col > row) v = -1e30f;
                }
                sacc[nt][e] = v;
            }
        }

        // ---- online softmax (base-2) ----
        float mx0 = -1e30f, mx1 = -1e30f;
        #pragma unroll
        for (int nt = 0; nt < 8; nt++) {
            mx0 = fmaxf(mx0, fmaxf(sacc[nt][0], sacc[nt][1]));
            mx1 = fmaxf(mx1, fmaxf(sacc[nt][2], sacc[nt][3]));
        }
        mx0 = fmaxf(mx0, __shfl_xor_sync(0xffffffffu, mx0, 1));
        mx0 = fmaxf(mx0, __shfl_xor_sync(0xffffffffu, mx0, 2));
        mx1 = fmaxf(mx1, __shfl_xor_sync(0xffffffffu, mx1, 1));
        mx1 = fmaxf(mx1, __shfl_xor_sync(0xffffffffu, mx1, 2));
        float mn0 = fmaxf(m0, mx0);
        float mn1 = fmaxf(m1, mx1);

        float ls0 = 0.f, ls1 = 0.f;
        #pragma unroll
        for (int nt = 0; nt < 8; nt++) {
            float p0 = exp2f(sacc[nt][0] - mn0);
            float p1 = exp2f(sacc[nt][1] - mn0);
            float p2 = exp2f(sacc[nt][2] - mn1);
            float p3 = exp2f(sacc[nt][3] - mn1);
            ls0 += p0 + p1;
            ls1 += p2 + p3;
            sacc[nt][0] = p0; sacc[nt][1] = p1; sacc[nt][2] = p2; sacc[nt][3] = p3;
        }
        ls0 += __shfl_xor_sync(0xffffffffu, ls0, 1);
        ls0 += __shfl_xor_sync(0xffffffffu, ls0, 2);
        ls1 += __shfl_xor_sync(0xffffffffu, ls1, 1);
        ls1 += __shfl_xor_sync(0xffffffffu, ls1, 2);

        float a0 = exp2f(m0 - mn0);
        float a1 = exp2f(m1 - mn1);
        m0 = mn0; m1 = mn1;
        l0 = l0 * a0 + ls0;
        l1 = l1 * a1 + ls1;
        #pragma unroll
        for (int nt = 0; nt < 16; nt++) {
            o[nt][0] *= a0; o[nt][1] *= a0;
            o[nt][2] *= a1; o[nt][3] *= a1;
        }

        // ---- O += P V (dc-pair interleave: 4 independent accumulators) ----
        #pragma unroll
        for (int ks = 0; ks < 4; ks++) {
            bf16 h0, q0, h1, q1, h2, q2, h3, q3;
            uint32_t ah[4], al[4];
            split2(sacc[2 * ks][0], h0, q0); split2(sacc[2 * ks][1], h1, q1);
            ah[0] = pack_bf2(h0, h1); al[0] = pack_bf2(q0, q1);
            split2(sacc[2 * ks][2], h0, q0); split2(sacc[2 * ks][3], h1, q1);
            ah[1] = pack_bf2(h0, h1); al[1] = pack_bf2(q0, q1);
            split2(sacc[2 * ks + 1][0], h2, q2); split2(sacc[2 * ks + 1][1], h3, q3);
            ah[2] = pack_bf2(h2, h3); al[2] = pack_bf2(q2, q3);
            split2(sacc[2 * ks + 1][2], h2, q2); split2(sacc[2 * ks + 1][3], h3, q3);
            ah[3] = pack_bf2(h2, h3); al[3] = pack_bf2(q2, q3);

            #pragma unroll
            for (int dq = 0; dq < 4; dq++) {       // dc pair (2dq, 2dq+1)
                uint32_t row = ks * 16 + (lane & 15);
                uint32_t ch0 = (2 * dq) * 2 + (lane >> 4);
                uint32_t ch1 = (2 * dq + 1) * 2 + (lane >> 4);
                uint32_t bh0[4], bl0[4], bh1[4], bl1[4];
                ldm4t(bh0, vb + sw256(row, ch0));
                ldm4t(bl0, vbl + sw256(row, ch0));
                ldm4t(bh1, vb + sw256(row, ch1));
                ldm4t(bl1, vbl + sw256(row, ch1));
                float* o0 = o[4 * dq + 0];
                float* o1 = o[4 * dq + 1];
                float* o2 = o[4 * dq + 2];
                float* o3 = o[4 * dq + 3];
                // per-acc order preserved: p_hi*v_hi, p_lo*v_hi, p_hi*v_lo
                mma16816(o0, ah, bh0);     mma16816(o1, ah, bh0 + 2);
                mma16816(o2, ah, bh1);     mma16816(o3, ah, bh1 + 2);
                mma16816(o0, al, bh0);     mma16816(o1, al, bh0 + 2);
                mma16816(o2, al, bh1);     mma16816(o3, al, bh1 + 2);
                mma16816(o0, ah, bl0);     mma16816(o1, ah, bl0 + 2);
                mma16816(o2, ah, bl1);     mma16816(o3, ah, bl1 + 2);
            }
        }
        __syncthreads();
    }

    // ---- epilogue ----
    float inv0 = 1.0f / l0;
    float inv1 = 1.0f / l1;
    #pragma unroll
    for (int nt = 0; nt < 16; nt++) {
        int c = head * HD + nt * 8 + (lane & 3) * 2;
        size_t i0 = (size_t)r0g * Cn + c;
        size_t i1 = (size_t)r1g * Cn + c;
        bf16 a, b, e, f;
        split2(o[nt][0] * inv0, a, e);
        split2(o[nt][1] * inv0, b, f);
        *(uint32_t*)(yhi + i0) = pack_bf2(a, b);
        *(uint32_t*)(ylo + i0) = pack_bf2(e, f);
        split2(o[nt][2] * inv1, a, e);
        split2(o[nt][3] * inv1, b, f);
        *(uint32_t*)(yhi + i1) = pack_bf2(a, b);
        *(uint32_t*)(ylo + i1) = pack_bf2(e, f);
    }
}

// ---------------- silu(g) * u -> split bf16 ----------------
__global__ void silu_mul_kernel(const float* __restrict__ g, const float* __restrict__ u,
                                bf16* __restrict__ ohi, bf16* __restrict__ olo) {
    const int n4 = Tn * FFN / 4;
    int i = blockIdx.x * blockDim.x + threadIdx.x;
    if (i >= n4) return;
    float4 gv = ((const float4*)g)[i];
    float4 uv = ((const float4*)u)[i];
    float r0 = gv.x / (1.f + expf(-gv.x)) * uv.x;
    float r1 = gv.y / (1.f + expf(-gv.y)) * uv.y;
    float r2 = gv.z / (1.f + expf(-gv.z)) * uv.z;
    float r3 = gv.w / (1.f + expf(-gv.w)) * uv.w;
    int b = i * 4;
    split2(r0, ohi[b + 0], olo[b + 0]);
    split2(r1, ohi[b + 1], olo[b + 1]);
    split2(r2, ohi[b + 2], olo[b + 2]);
    split2(r3, ohi[b + 3], olo[b + 3]);
}

// ---------------- launch ----------------
extern "C" void kernel_launch(void* const* d_in, const int* in_sizes, int n_in,
                              void* d_out, int out_size) {
    (void)in_sizes; (void)n_in; (void)out_size;
    const float* x           = (const float*)d_in[0];
    const float* attn_norm_w = (const float*)d_in[2];
    const float* wq          = (const float*)d_in[3];
    const float* wk          = (const float*)d_in[4];
    const float* wv          = (const float*)d_in[5];
    const float* wo          = (const float*)d_in[6];
    const float* ffn_norm_w  = (const float*)d_in[7];
    const float* w_gate      = (const float*)d_in[8];
    const float* w_up        = (const float*)d_in[9];
    const float* w_down      = (const float*)d_in[10];
    float* out = (float*)d_out;

    float *q, *k, *v, *g, *u;
    float2* rtab;
    bf16 *h_hi, *h_lo, *h2_hi, *h2_lo, *y_hi, *y_lo, *gs_hi, *gs_lo;
    bf16 *qhi, *qlo, *khi, *klo, *vhi, *vlo;
    bf16 *wq_hi, *wq_lo, *wk_hi, *wk_lo, *wv_hi, *wv_lo, *wo_hi, *wo_lo;
    bf16 *wg_hi, *wg_lo, *wu_hi, *wu_lo, *wd_hi, *wd_lo;

    cudaGetSymbolAddress((void**)&q,  g_q);
    cudaGetSymbolAddress((void**)&k,  g_k);
    cudaGetSymbolAddress((void**)&v,  g_v);
    cudaGetSymbolAddress((void**)&g,  g_g);
    cudaGetSymbolAddress((void**)&u,  g_u);
    cudaGetSymbolAddress((void**)&rtab, g_rope);
    cudaGetSymbolAddress((void**)&h_hi,  g_h_hi);  cudaGetSymbolAddress((void**)&h_lo,  g_h_lo);
    cudaGetSymbolAddress((void**)&h2_hi, g_h2_hi); cudaGetSymbolAddress((void**)&h2_lo, g_h2_lo);
    cudaGetSymbolAddress((void**)&y_hi,  g_y_hi);  cudaGetSymbolAddress((void**)&y_lo,  g_y_lo);
    cudaGetSymbolAddress((void**)&gs_hi, g_gs_hi); cudaGetSymbolAddress((void**)&gs_lo, g_gs_lo);
    cudaGetSymbolAddress((void**)&qhi, g_qhi); cudaGetSymbolAddress((void**)&qlo, g_qlo);
    cudaGetSymbolAddress((void**)&khi, g_khi); cudaGetSymbolAddress((void**)&klo, g_klo);
    cudaGetSymbolAddress((void**)&vhi, g_vhi); cudaGetSymbolAddress((void**)&vlo, g_vlo);
    cudaGetSymbolAddress((void**)&wq_hi, g_wq_hi); cudaGetSymbolAddress((void**)&wq_lo, g_wq_lo);
    cudaGetSymbolAddress((void**)&wk_hi, g_wk_hi); cudaGetSymbolAddress((void**)&wk_lo, g_wk_lo);
    cudaGetSymbolAddress((void**)&wv_hi, g_wv_hi); cudaGetSymbolAddress((void**)&wv_lo, g_wv_lo);
    cudaGetSymbolAddress((void**)&wo_hi, g_wo_hi); cudaGetSymbolAddress((void**)&wo_lo, g_wo_lo);
    cudaGetSymbolAddress((void**)&wg_hi, g_wg_hi); cudaGetSymbolAddress((void**)&wg_lo, g_wg_lo);
    cudaGetSymbolAddress((void**)&wu_hi, g_wu_hi); cudaGetSymbolAddress((void**)&wu_lo, g_wu_lo);
    cudaGetSymbolAddress((void**)&wd_hi, g_wd_hi); cudaGetSymbolAddress((void**)&wd_lo, g_wd_lo);

    cudaFuncSetAttribute(gemm_bf16x3, cudaFuncAttributeMaxDynamicSharedMemorySize, GEMM_SMEM);
    cudaFuncSetAttribute(attn_tc, cudaFuncAttributeMaxDynamicSharedMemorySize, ATTN_SMEM);

    // 0) RoPE table + weight splits
    rope_table_kernel<<<(Tn * 64 + 255) / 256, 256>>>(rtab);
    convert_kernel<<<(Cn * Cn + 255) / 256, 256>>>(wq, wq_hi, wq_lo, Cn * Cn);
    convert_kernel<<<(NKV * HD * Cn + 255) / 256, 256>>>(wk, wk_hi, wk_lo, NKV * HD * Cn);
    convert_kernel<<<(NKV * HD * Cn + 255) / 256, 256>>>(wv, wv_hi, wv_lo, NKV * HD * Cn);
    convert_kernel<<<(Cn * Cn + 255) / 256, 256>>>(wo, wo_hi, wo_lo, Cn * Cn);
    convert_kernel<<<(FFN * Cn + 255) / 256, 256>>>(w_gate, wg_hi, wg_lo, FFN * Cn);
    convert_kernel<<<(FFN * Cn + 255) / 256, 256>>>(w_up,   wu_hi, wu_lo, FFN * Cn);
    convert_kernel<<<(Cn * FFN + 255) / 256, 256>>>(w_down, wd_hi, wd_lo, Cn * FFN);

    // 1) rmsnorm1 -> split
    rmsnorm_kernel<<<Tn, 256>>>(x, attn_norm_w, h_hi, h_lo);
    // 2) Q/K/V projections
    gemm_bf16x3<<<dim3(Cn / 128, Tn / 128), 256, GEMM_SMEM>>>(h_hi, h_lo, wq_hi, wq_lo, q, nullptr, Tn, Cn, Cn);
    gemm_bf16x3<<<dim3((NKV * HD) / 128, Tn / 128), 256, GEMM_SMEM>>>(h_hi, h_lo, wk_hi, wk_lo, k, nullptr, Tn, NKV * HD, Cn);
    gemm_bf16x3<<<dim3((NKV * HD) / 128, Tn / 128), 256, GEMM_SMEM>>>(h_hi, h_lo, wv_hi, wv_lo, v, nullptr, Tn, NKV * HD, Cn);
    // 3) RoPE + split q/k, split v
    {
        int total = Tn * (NH + NKV) * 64;
        rope_split_kernel<<<(total + 255) / 256, 256>>>(q, k, rtab, qhi, qlo, khi, klo);
        convert_kernel<<<(Tn * NKV * HD + 255) / 256, 256>>>(v, vhi, vlo, Tn * NKV * HD);
    }
    // 4) tensor-core causal flash attention -> split y
    attn_tc<<<dim3(32, NH), 256, ATTN_SMEM>>>(qhi, qlo, khi, klo, vhi, vlo, y_hi, y_lo);
    // 5) out = x + y @ wo^T
    gemm_bf16x3<<<dim3(Cn / 128, Tn / 128), 256, GEMM_SMEM>>>(y_hi, y_lo, wo_hi, wo_lo, out, x, Tn, Cn, Cn);
    // 6) rmsnorm2 -> split
    rmsnorm_kernel<<<Tn, 256>>>(out, ffn_norm_w, h2_hi, h2_lo);
    // 7) gate / up
    gemm_bf16x3<<<dim3(FFN / 128, Tn / 128), 256, GEMM_SMEM>>>(h2_hi, h2_lo, wg_hi, wg_lo, g, nullptr, Tn, FFN, Cn);
    gemm_bf16x3<<<dim3(FFN / 128, Tn / 128), 256, GEMM_SMEM>>>(h2_hi, h2_lo, wu_hi, wu_lo, u, nullptr, Tn, FFN, Cn);
    // 8) silu(g)*u -> split
    silu_mul_kernel<<<(Tn * FFN / 4 + 255) / 256, 256>>>(g, u, gs_hi, gs_lo);
    // 9) out += gs @ w_down^T
    gemm_bf16x3<<<dim3(Cn / 128, Tn / 128), 256, GEMM_SMEM>>>(gs_hi, gs_lo, wd_hi, wd_lo, out, out, Tn, Cn, FFN);
}

// round 8
// speedup vs baseline: 3.2851x; 1.0584x over previous
#include <cuda_runtime.h>
#include <cuda_bf16.h>
#include <math.h>
#include <stdint.h>

#define Tn   4096
#define Cn   2048
#define NH   16
#define NKV  4
#define HD   128
#define FFN  8192

typedef __nv_bfloat16 bf16;

// ---------------- scratch (static device globals; no allocation) ----------------
static __device__ float  g_q [Tn * Cn];
static __device__ float  g_k [Tn * NKV * HD];
static __device__ float  g_v [Tn * NKV * HD];
static __device__ float  g_g [Tn * FFN];
static __device__ float  g_u [Tn * FFN];
static __device__ float2 g_rope[Tn * 64];

static __device__ bf16 g_h_hi [Tn * Cn],  g_h_lo [Tn * Cn];
static __device__ bf16 g_h2_hi[Tn * Cn],  g_h2_lo[Tn * Cn];
static __device__ bf16 g_y_hi [Tn * Cn],  g_y_lo [Tn * Cn];
static __device__ bf16 g_gs_hi[Tn * FFN], g_gs_lo[Tn * FFN];

static __device__ bf16 g_qhi[Tn * Cn],       g_qlo[Tn * Cn];
static __device__ bf16 g_khi[Tn * NKV * HD], g_klo[Tn * NKV * HD];
static __device__ bf16 g_vhi[Tn * NKV * HD], g_vlo[Tn * NKV * HD];

static __device__ bf16 g_wq_hi[Cn * Cn],        g_wq_lo[Cn * Cn];
static __device__ bf16 g_wk_hi[NKV * HD * Cn],  g_wk_lo[NKV * HD * Cn];
static __device__ bf16 g_wv_hi[NKV * HD * Cn],  g_wv_lo[NKV * HD * Cn];
static __device__ bf16 g_wo_hi[Cn * Cn],        g_wo_lo[Cn * Cn];
static __device__ bf16 g_wg_hi[FFN * Cn],       g_wg_lo[FFN * Cn];
static __device__ bf16 g_wu_hi[FFN * Cn],       g_wu_lo[FFN * Cn];
static __device__ bf16 g_wd_hi[Cn * FFN],       g_wd_lo[Cn * FFN];

__device__ __forceinline__ void split2(float x, bf16& hi, bf16& lo) {
    hi = __float2bfloat16(x);
    lo = __float2bfloat16(x - __bfloat162float(hi));
}

__device__ __forceinline__ uint32_t pack_bf2(bf16 a, bf16 b) {
    __nv_bfloat162 t; t.x = a; t.y = b;
    return *reinterpret_cast<uint32_t*>(&t);
}

// ---------------- common PTX helpers ----------------
__device__ __forceinline__ void cp16(uint32_t dst, const void* src) {
    asm volatile("cp.async.cg.shared.global [%0], [%1], 16;\n" :: "r"(dst), "l"(src));
}

__device__ __forceinline__ void ldm4(uint32_t* r, uint32_t addr) {
    asm volatile("ldmatrix.sync.aligned.m8n8.x4.shared.b16 {%0,%1,%2,%3}, [%4];\n"
                 : "=r"(r[0]), "=r"(r[1]), "=r"(r[2]), "=r"(r[3]) : "r"(addr));
}

__device__ __forceinline__ void ldm4t(uint32_t* r, uint32_t addr) {
    asm volatile("ldmatrix.sync.aligned.m8n8.x4.trans.shared.b16 {%0,%1,%2,%3}, [%4];\n"
                 : "=r"(r[0]), "=r"(r[1]), "=r"(r[2]), "=r"(r[3]) : "r"(addr));
}

__device__ __forceinline__ void mma16816(float* c, const uint32_t* a, const uint32_t* b) {
    asm volatile("mma.sync.aligned.m16n8k16.row.col.f32.bf16.bf16.f32 "
                 "{%0,%1,%2,%3},{%4,%5,%6,%7},{%8,%9},{%0,%1,%2,%3};\n"
                 : "+f"(c[0]), "+f"(c[1]), "+f"(c[2]), "+f"(c[3])
                 : "r"(a[0]), "r"(a[1]), "r"(a[2]), "r"(a[3]), "r"(b[0]), "r"(b[1]));
}

// ---------------- weight / activation fp32 -> (hi, lo) bf16 ----------------
__global__ void convert_kernel(const float* __restrict__ w,
                               bf16* __restrict__ hi, bf16* __restrict__ lo, int n) {
    int i = blockIdx.x * blockDim.x + threadIdx.x;
    if (i < n) split2(w[i], hi[i], lo[i]);
}

// ---------------- RoPE cos/sin table (double sincos — fast-math immune) ----------------
__global__ void rope_table_kernel(float2* __restrict__ tab) {
    int idx = blockIdx.x * blockDim.x + threadIdx.x;
    if (idx >= Tn * 64) return;
    int i = idx & 63;
    int t = idx >> 6;
    double invf_d = pow(500000.0, -((double)(2 * i) / 128.0));
    float  invf_f = (float)invf_d;
    float  ang_f  = (float)t * invf_f;
    double c, s;
    sincos((double)ang_f, &s, &c);
    tab[idx] = make_float2((float)c, (float)s);
}

// ---------------- rmsnorm: one block per row, writes split bf16 ----------------
__global__ void __launch_bounds__(256) rmsnorm_kernel(const float* __restrict__ x,
                                                      const float* __restrict__ w,
                                                      bf16* __restrict__ ohi,
                                                      bf16* __restrict__ olo) {
    const int row = blockIdx.x;
    const float* xr = x + (size_t)row * Cn;
    float s = 0.f;
    for (int i = threadIdx.x; i < Cn; i += 256) {
        float v = xr[i];
        s = fmaf(v, v, s);
    }
    __shared__ float red[8];
    #pragma unroll
    for (int o = 16; o; o >>= 1) s += __shfl_xor_sync(0xffffffffu, s, o);
    if ((threadIdx.x & 31) == 0) red[threadIdx.x >> 5] = s;
    __syncthreads();
    if (threadIdx.x < 32) {
        float v = (threadIdx.x < 8) ? red[threadIdx.x] : 0.f;
        #pragma unroll
        for (int o = 4; o; o >>= 1) v += __shfl_xor_sync(0xffffffffu, v, o);
        if (threadIdx.x == 0) red[0] = v;
    }
    __syncthreads();
    const float scale = rsqrtf(red[0] * (1.0f / Cn) + 1e-5f);
    size_t base = (size_t)row * Cn;
    for (int i = threadIdx.x; i < Cn; i += 256) {
        float v = xr[i] * scale * w[i];
        split2(v, ohi[base + i], olo[base + i]);
    }
}

// =====================================================================
// bf16x3 tensor-core GEMM v3: 128(M) x 256(N) block, warp tile 64x64,
// BK=32, 3-stage cp.async, CTA swizzle for L2 reuse.
// C[m,n] = sum_k A[m,k]*B[n,k] (+ R[m,n])
// =====================================================================
#define STAGES 3
#define G_AHI 0
#define G_ALO 8192
#define G_BHI 16384
#define G_BLO 32768
#define G_STAGE 49152
#define GEMM_SMEM (STAGES * G_STAGE)

__device__ __forceinline__ uint32_t sw(uint32_t row, uint32_t chunk) {
    return (row << 6) + (((chunk ^ (row >> 1)) & 3u) << 4);
}

__global__ void __launch_bounds__(256, 1) gemm_bf16x3(
        const bf16* __restrict__ Ahi, const bf16* __restrict__ Alo,
        const bf16* __restrict__ Bhi, const bf16* __restrict__ Blo,
        float* __restrict__ C, const float* __restrict__ R,
        int M, int N, int K) {
    extern __shared__ __align__(128) char smem_raw[];
    const uint32_t smem_u = (uint32_t)__cvta_generic_to_shared(smem_raw);
    const int tid  = threadIdx.x;
    const int warp = tid >> 5;
    const int lane = tid & 31;
    const int wm   = warp & 1;       // 2 warps along M (64 rows each)
    const int wn   = warp >> 1;      // 4 warps along N (64 cols each)

    // ---- CTA swizzle: 8-row supertiles so concurrent CTAs share A panels ----
    int bx, by;
    {
        int tiles_n = gridDim.x, tiles_m = gridDim.y;
        int lin = blockIdx.y * tiles_n + blockIdx.x;
        int per = 8 * tiles_n;
        int gid = lin / per, rem = lin % per;
        int gm  = tiles_m - gid * 8;
        if (gm > 8) gm = 8;
        by = gid * 8 + rem % gm;
        bx = rem / gm;
    }
    const int bm = by * 128;
    const int bn = bx * 256;

    float acc[4][8][4];
    #pragma unroll
    for (int i = 0; i < 4; i++)
        #pragma unroll
        for (int j = 0; j < 8; j++)
            #pragma unroll
            for (int v = 0; v < 4; v++) acc[i][j][v] = 0.f;

    const int kiters = K >> 5;

    auto load_stage = [&](int stage, int kt) {
        const uint32_t sbase = smem_u + stage * G_STAGE;
        #pragma unroll
        for (int rep = 0; rep < 2; rep++) {          // A: 128 rows x 4 chunks
            int idx = tid + rep * 256;
            int row = idx >> 2;
            int ch  = idx & 3;
            size_t go = (size_t)(bm + row) * K + kt + ch * 8;
            uint32_t so = sw(row, ch);
            cp16(sbase + G_AHI + so, Ahi + go);
            cp16(sbase + G_ALO + so, Alo + go);
        }
        #pragma unroll
        for (int rep = 0; rep < 4; rep++) {          // B: 256 rows x 4 chunks
            int idx = tid + rep * 256;
            int row = idx >> 2;
            int ch  = idx & 3;
            size_t go = (size_t)(bn + row) * K + kt + ch * 8;
            uint32_t so = sw(row, ch);
            cp16(sbase + G_BHI + so, Bhi + go);
            cp16(sbase + G_BLO + so, Blo + go);
        }
    };

    #pragma unroll
    for (int s = 0; s < STAGES - 1; s++) {
        load_stage(s, s * 32);
        asm volatile("cp.async.commit_group;\n");
    }

    for (int it = 0; it < kiters; ++it) {
        asm volatile("cp.async.wait_group %0;\n" :: "n"(STAGES - 2));
        __syncthreads();
        int pf = it + STAGES - 1;
        if (pf < kiters) load_stage(pf % STAGES, pf * 32);
        asm volatile("cp.async.commit_group;\n");

        const uint32_t sb = smem_u + (it % STAGES) * G_STAGE;

        #pragma unroll
        for (int kf = 0; kf < 2; kf++) {
            // A fragments: 4 m-tiles (64 rows), hi + lo
            uint32_t ah[4][4], al[4][4];
            #pragma unroll
            for (int mt = 0; mt < 4; mt++) {
                uint32_t row = wm * 64 + mt * 16 + (lane & 15);
                uint32_t ch  = kf * 2 + (lane >> 4);
                uint32_t off = sw(row, ch);
                ldm4(ah[mt], sb + G_AHI + off);
                ldm4(al[mt], sb + G_ALO + off);
            }
            // B fragments loaded per n-pair to limit live registers
            #pragma unroll
            for (int p = 0; p < 4; p++) {            // covers nt = 2p, 2p+1
                uint32_t rowb = wn * 64 + p * 16 + (lane & 7) + ((lane >> 4) & 1) * 8;
                uint32_t chb  = kf * 2 + ((lane >> 3) & 1);
                uint32_t offb = sw(rowb, chb);
                uint32_t bh[4], bl[4];
                ldm4(bh, sb + G_BHI + offb);
                ldm4(bl, sb + G_BLO + offb);
                // product-major within pair; per-acc order hh, hl, lh (bit-identical)
                #pragma unroll
                for (int mt = 0; mt < 4; mt++) {
                    mma16816(acc[mt][2 * p],     ah[mt], bh);
                    mma16816(acc[mt][2 * p + 1], ah[mt], bh + 2);
                }
                #pragma unroll
                for (int mt = 0; mt < 4; mt++) {
                    mma16816(acc[mt][2 * p],     ah[mt], bl);
                    mma16816(acc[mt][2 * p + 1], ah[mt], bl + 2);
                }
                #pragma unroll
                for (int mt = 0; mt < 4; mt++) {
                    mma16816(acc[mt][2 * p],     al[mt], bh);
                    mma16816(acc[mt][2 * p + 1], al[mt], bh + 2);
                }
            }
        }
    }

    // ---- epilogue ----
    const int rb = bm + wm * 64;
    const int cb = bn + wn * 64;
    #pragma unroll
    for (int mt = 0; mt < 4; mt++)
        #pragma unroll
        for (int nt = 0; nt < 8; nt++) {
            int r0 = rb + mt * 16 + (lane >> 2);
            int c  = cb + nt * 8 + (lane & 3) * 2;
            size_t i0 = (size_t)r0 * N + c;
            size_t i1 = (size_t)(r0 + 8) * N + c;
            float2 v0 = make_float2(acc[mt][nt][0], acc[mt][nt][1]);
            float2 v1 = make_float2(acc[mt][nt][2], acc[mt][nt][3]);
            if (R) {
                float2 q0 = *(const float2*)(R + i0);
                float2 q1 = *(const float2*)(R + i1);
                v0.x += q0.x; v0.y += q0.y;
                v1.x += q1.x; v1.y += q1.y;
            }
            *(float2*)(C + i0) = v0;
            *(float2*)(C + i1) = v1;
        }
}

// ---------------- RoPE + split: fp32 q/k -> rotated split bf16 ----------------
__global__ void rope_split_kernel(const float* __restrict__ q, const float* __restrict__ k,
                                  const float2* __restrict__ tab,
                                  bf16* __restrict__ qhi, bf16* __restrict__ qlo,
                                  bf16* __restrict__ khi, bf16* __restrict__ klo) {
    const int total = Tn * (NH + NKV) * 64;
    int idx = blockIdx.x * blockDim.x + threadIdx.x;
    if (idx >= total) return;
    int i    = idx & 63;
    int rest = idx >> 6;
    int head = rest % (NH + NKV);
    int t    = rest / (NH + NKV);
    float2 cs = tab[t * 64 + i];
    float c = cs.x, s = cs.y;
    if (head < NH) {
        size_t off = (size_t)t * Cn + head * HD + 2 * i;
        float2 ab = *(const float2*)(q + off);
        float a = ab.x, b = ab.y;
        float r0 = fmaf(a, c, -b * s);
        float r1 = fmaf(a, s,  b * c);
        split2(r0, qhi[off], qlo[off]);
        split2(r1, qhi[off + 1], qlo[off + 1]);
    } else {
        size_t off = (size_t)t * (NKV * HD) + (head - NH) * HD + 2 * i;
        float2 ab = *(const float2*)(k + off);
        float a = ab.x, b = ab.y;
        float r0 = fmaf(a, c, -b * s);
        float r1 = fmaf(a, s,  b * c);
        split2(r0, khi[off], klo[off]);
        split2(r1, khi[off + 1], klo[off + 1]);
    }
}

// =====================================================================
// Tensor-core causal flash attention (split precision) — unchanged R7
// =====================================================================
#define AQ_HI 0
#define AQ_LO 32768
#define AKV   65536
#define AKV_STAGE 65536
#define AK_LO 16384
#define AV_HI 32768
#define AV_LO 49152
#define ATTN_SMEM (AKV + 2 * AKV_STAGE)

__device__ __forceinline__ uint32_t sw256(uint32_t row, uint32_t ch) {
    return (row << 8) + ((((ch ^ row) & 7u) | (ch & 8u)) << 4);
}

__global__ void __launch_bounds__(256, 1) attn_tc(
        const bf16* __restrict__ qhi, const bf16* __restrict__ qlo,
        const bf16* __restrict__ khi, const bf16* __restrict__ klo,
        const bf16* __restrict__ vhi, const bf16* __restrict__ vlo,
        bf16* __restrict__ yhi, bf16* __restrict__ ylo) {
    extern __shared__ __align__(128) char smem_raw[];
    const uint32_t sb = (uint32_t)__cvta_generic_to_shared(smem_raw);
    const int qt   = 31 - blockIdx.x;
    const int head = blockIdx.y;
    const int kvh  = head >> 2;
    const int qb   = qt * 128;
    const int tid  = threadIdx.x;
    const int warp = tid >> 5;
    const int lane = tid & 31;
    const int njt  = 2 * qt + 2;

    #pragma unroll
    for (int i = 0; i < 8; i++) {
        int idx = tid + i * 256;
        int row = idx >> 4;
        int ch  = idx & 15;
        size_t g = (size_t)(qb + row) * Cn + head * HD + ch * 8;
        uint32_t off = sw256(row, ch);
        cp16(sb + AQ_HI + off, qhi + g);
        cp16(sb + AQ_LO + off, qlo + g);
    }

    auto load_kv = [&](int jt, int buf) {
        const uint32_t base = sb + AKV + buf * AKV_STAGE;
        #pragma unroll
        for (int i = 0; i < 4; i++) {
            int idx = tid + i * 256;
            int row = idx >> 4;
            int ch  = idx & 15;
            size_t g = (size_t)(jt * 64 + row) * (NKV * HD) + kvh * HD + ch * 8;
            uint32_t off = sw256(row, ch);
            cp16(base + off,          khi + g);
            cp16(base + AK_LO + off,  klo + g);
            cp16(base + AV_HI + off,  vhi + g);
            cp16(base + AV_LO + off,  vlo + g);
        }
    };

    load_kv(0, 0);
    asm volatile("cp.async.commit_group;\n");

    float m0 = -1e30f, m1 = -1e30f, l0 = 0.f, l1 = 0.f;
    float o[16][4];
    #pragma unroll
    for (int nt = 0; nt < 16; nt++)
        #pragma unroll
        for (int e = 0; e < 4; e++) o[nt][e] = 0.f;

    const float cs = 0.12751743621340608f;      // log2(e)/sqrt(128)
    const int r0g = qb + (warp << 4) + (lane >> 2);
    const int r1g = r0g + 8;

    for (int jt = 0; jt < njt; jt++) {
        if (jt + 1 < njt) load_kv(jt + 1, (jt + 1) & 1);
        asm volatile("cp.async.commit_group;\n");
        asm volatile("cp.async.wait_group 1;\n");
        __syncthreads();

        const uint32_t kb   = sb + AKV + (jt & 1) * AKV_STAGE;
        const uint32_t kbl  = kb + AK_LO;
        const uint32_t vb   = kb + AV_HI;
        const uint32_t vbl  = kb + AV_LO;

        float sacc[8][4];
        #pragma unroll
        for (int nt = 0; nt < 8; nt++)
            #pragma unroll
            for (int e = 0; e < 4; e++) sacc[nt][e] = 0.f;

        #pragma unroll
        for (int ks = 0; ks < 8; ks++) {
            uint32_t ah[4], al[4];
            {
                uint32_t row = (warp << 4) + (lane & 15);
                uint32_t ch  = ks * 2 + (lane >> 4);
                uint32_t off = sw256(row, ch);
                ldm4(ah, sb + AQ_HI + off);
                ldm4(al, sb + AQ_LO + off);
            }
            uint32_t bh[8][2], bl[8][2];
            #pragma unroll
            for (int p = 0; p < 4; p++) {
                uint32_t rowb = p * 16 + (lane & 7) + ((lane >> 4) & 1) * 8;
                uint32_t chb  = ks * 2 + ((lane >> 3) & 1);
                uint32_t offb = sw256(rowb, chb);
                uint32_t r[4];
                ldm4(r, kb + offb);
                bh[2 * p][0] = r[0]; bh[2 * p][1] = r[1];
                bh[2 * p + 1][0] = r[2]; bh[2 * p + 1][1] = r[3];
                ldm4(r, kbl + offb);
                bl[2 * p][0] = r[0]; bl[2 * p][1] = r[1];
                bl[2 * p + 1][0] = r[2]; bl[2 * p + 1][1] = r[3];
            }
            #pragma unroll
            for (int nt = 0; nt < 8; nt++) mma16816(sacc[nt], ah, bh[nt]);
            #pragma unroll
            for (int nt = 0; nt < 8; nt++) mma16816(sacc[nt], ah, bl[nt]);
            #pragma unroll
            for (int nt = 0; nt < 8; nt++) mma16816(sacc[nt], al, bh[nt]);
        }

        const bool domask = (jt >= 2 * qt);
        #pragma unroll
        for (int nt = 0; nt < 8; nt++) {
            int cbase = jt * 64 + nt * 8 + (lane & 3) * 2;
            #pragma unroll
            for (int e = 0; e < 4; e++) {
                float v = sacc[nt][e] * cs;
                if (domask) {
                    int col = cbase + (e & 1);
                    int row = (e < 2) ? r0g : r1g;
                    if (col > row) v = -1e30f;
                }
                sacc[nt][e] = v;
            }
        }

        float mx0 = -1e30f, mx1 = -1e30f;
        #pragma unroll
        for (int nt = 0; nt < 8; nt++) {
            mx0 = fmaxf(mx0, fmaxf(sacc[nt][0], sacc[nt][1]));
            mx1 = fmaxf(mx1, fmaxf(sacc[nt][2], sacc[nt][3]));
        }
        mx0 = fmaxf(mx0, __shfl_xor_sync(0xffffffffu, mx0, 1));
        mx0 = fmaxf(mx0, __shfl_xor_sync(0xffffffffu, mx0, 2));
        mx1 = fmaxf(mx1, __shfl_xor_sync(0xffffffffu, mx1, 1));
        mx1 = fmaxf(mx1, __shfl_xor_sync(0xffffffffu, mx1, 2));
        float mn0 = fmaxf(m0, mx0);
        float mn1 = fmaxf(m1, mx1);

        float ls0 = 0.f, ls1 = 0.f;
        #pragma unroll
        for (int nt = 0; nt < 8; nt++) {
            float p0 = exp2f(sacc[nt][0] - mn0);
            float p1 = exp2f(sacc[nt][1] - mn0);
            float p2 = exp2f(sacc[nt][2] - mn1);
            float p3 = exp2f(sacc[nt][3] - mn1);
            ls0 += p0 + p1;
            ls1 += p2 + p3;
            sacc[nt][0] = p0; sacc[nt][1] = p1; sacc[nt][2] = p2; sacc[nt][3] = p3;
        }
        ls0 += __shfl_xor_sync(0xffffffffu, ls0, 1);
        ls0 += __shfl_xor_sync(0xffffffffu, ls0, 2);
        ls1 += __shfl_xor_sync(0xffffffffu, ls1, 1);
        ls1 += __shfl_xor_sync(0xffffffffu, ls1, 2);

        float a0 = exp2f(m0 - mn0);
        float a1 = exp2f(m1 - mn1);
        m0 = mn0; m1 = mn1;
        l0 = l0 * a0 + ls0;
        l1 = l1 * a1 + ls1;
        #pragma unroll
        for (int nt = 0; nt < 16; nt++) {
            o[nt][0] *= a0; o[nt][1] *= a0;
            o[nt][2] *= a1; o[nt][3] *= a1;
        }

        #pragma unroll
        for (int ks = 0; ks < 4; ks++) {
            bf16 h0, q0, h1, q1, h2, q2, h3, q3;
            uint32_t ah[4], al[4];
            split2(sacc[2 * ks][0], h0, q0); split2(sacc[2 * ks][1], h1, q1);
            ah[0] = pack_bf2(h0, h1); al[0] = pack_bf2(q0, q1);
            split2(sacc[2 * ks][2], h0, q0); split2(sacc[2 * ks][3], h1, q1);
            ah[1] = pack_bf2(h0, h1); al[1] = pack_bf2(q0, q1);
            split2(sacc[2 * ks + 1][0], h2, q2); split2(sacc[2 * ks + 1][1], h3, q3);
            ah[2] = pack_bf2(h2, h3); al[2] = pack_bf2(q2, q3);
            split2(sacc[2 * ks + 1][2], h2, q2); split2(sacc[2 * ks + 1][3], h3, q3);
            ah[3] = pack_bf2(h2, h3); al[3] = pack_bf2(q2, q3);

            #pragma unroll
            for (int dq = 0; dq < 4; dq++) {
                uint32_t row = ks * 16 + (lane & 15);
                uint32_t ch0 = (2 * dq) * 2 + (lane >> 4);
                uint32_t ch1 = (2 * dq + 1) * 2 + (lane >> 4);
                uint32_t bh0[4], bl0[4], bh1[4], bl1[4];
                ldm4t(bh0, vb + sw256(row, ch0));
                ldm4t(bl0, vbl + sw256(row, ch0));
                ldm4t(bh1, vb + sw256(row, ch1));
                ldm4t(bl1, vbl + sw256(row, ch1));
                float* o0 = o[4 * dq + 0];
                float* o1 = o[4 * dq + 1];
                float* o2 = o[4 * dq + 2];
                float* o3 = o[4 * dq + 3];
                mma16816(o0, ah, bh0);     mma16816(o1, ah, bh0 + 2);
                mma16816(o2, ah, bh1);     mma16816(o3, ah, bh1 + 2);
                mma16816(o0, al, bh0);     mma16816(o1, al, bh0 + 2);
                mma16816(o2, al, bh1);     mma16816(o3, al, bh1 + 2);
                mma16816(o0, ah, bl0);     mma16816(o1, ah, bl0 + 2);
                mma16816(o2, ah, bl1);     mma16816(o3, ah, bl1 + 2);
            }
        }
        __syncthreads();
    }

    float inv0 = 1.0f / l0;
    float inv1 = 1.0f / l1;
    #pragma unroll
    for (int nt = 0; nt < 16; nt++) {
        int c = head * HD + nt * 8 + (lane & 3) * 2;
        size_t i0 = (size_t)r0g * Cn + c;
        size_t i1 = (size_t)r1g * Cn + c;
        bf16 a, b, e, f;
        split2(o[nt][0] * inv0, a, e);
        split2(o[nt][1] * inv0, b, f);
        *(uint32_t*)(yhi + i0) = pack_bf2(a, b);
        *(uint32_t*)(ylo + i0) = pack_bf2(e, f);
        split2(o[nt][2] * inv1, a, e);
        split2(o[nt][3] * inv1, b, f);
        *(uint32_t*)(yhi + i1) = pack_bf2(a, b);
        *(uint32_t*)(ylo + i1) = pack_bf2(e, f);
    }
}

// ---------------- silu(g) * u -> split bf16 ----------------
__global__ void silu_mul_kernel(const float* __restrict__ g, const float* __restrict__ u,
                                bf16* __restrict__ ohi, bf16* __restrict__ olo) {
    const int n4 = Tn * FFN / 4;
    int i = blockIdx.x * blockDim.x + threadIdx.x;
    if (i >= n4) return;
    float4 gv = ((const float4*)g)[i];
    float4 uv = ((const float4*)u)[i];
    float r0 = gv.x / (1.f + expf(-gv.x)) * uv.x;
    float r1 = gv.y / (1.f + expf(-gv.y)) * uv.y;
    float r2 = gv.z / (1.f + expf(-gv.z)) * uv.z;
    float r3 = gv.w / (1.f + expf(-gv.w)) * uv.w;
    int b = i * 4;
    split2(r0, ohi[b + 0], olo[b + 0]);
    split2(r1, ohi[b + 1], olo[b + 1]);
    split2(r2, ohi[b + 2], olo[b + 2]);
    split2(r3, ohi[b + 3], olo[b + 3]);
}

// ---------------- launch ----------------
extern "C" void kernel_launch(void* const* d_in, const int* in_sizes, int n_in,
                              void* d_out, int out_size) {
    (void)in_sizes; (void)n_in; (void)out_size;
    const float* x           = (const float*)d_in[0];
    const float* attn_norm_w = (const float*)d_in[2];
    const float* wq          = (const float*)d_in[3];
    const float* wk          = (const float*)d_in[4];
    const float* wv          = (const float*)d_in[5];
    const float* wo          = (const float*)d_in[6];
    const float* ffn_norm_w  = (const float*)d_in[7];
    const float* w_gate      = (const float*)d_in[8];
    const float* w_up        = (const float*)d_in[9];
    const float* w_down      = (const float*)d_in[10];
    float* out = (float*)d_out;

    float *q, *k, *v, *g, *u;
    float2* rtab;
    bf16 *h_hi, *h_lo, *h2_hi, *h2_lo, *y_hi, *y_lo, *gs_hi, *gs_lo;
    bf16 *qhi, *qlo, *khi, *klo, *vhi, *vlo;
    bf16 *wq_hi, *wq_lo, *wk_hi, *wk_lo, *wv_hi, *wv_lo, *wo_hi, *wo_lo;
    bf16 *wg_hi, *wg_lo, *wu_hi, *wu_lo, *wd_hi, *wd_lo;

    cudaGetSymbolAddress((void**)&q,  g_q);
    cudaGetSymbolAddress((void**)&k,  g_k);
    cudaGetSymbolAddress((void**)&v,  g_v);
    cudaGetSymbolAddress((void**)&g,  g_g);
    cudaGetSymbolAddress((void**)&u,  g_u);
    cudaGetSymbolAddress((void**)&rtab, g_rope);
    cudaGetSymbolAddress((void**)&h_hi,  g_h_hi);  cudaGetSymbolAddress((void**)&h_lo,  g_h_lo);
    cudaGetSymbolAddress((void**)&h2_hi, g_h2_hi); cudaGetSymbolAddress((void**)&h2_lo, g_h2_lo);
    cudaGetSymbolAddress((void**)&y_hi,  g_y_hi);  cudaGetSymbolAddress((void**)&y_lo,  g_y_lo);
    cudaGetSymbolAddress((void**)&gs_hi, g_gs_hi); cudaGetSymbolAddress((void**)&gs_lo, g_gs_lo);
    cudaGetSymbolAddress((void**)&qhi, g_qhi); cudaGetSymbolAddress((void**)&qlo, g_qlo);
    cudaGetSymbolAddress((void**)&khi, g_khi); cudaGetSymbolAddress((void**)&klo, g_klo);
    cudaGetSymbolAddress((void**)&vhi, g_vhi); cudaGetSymbolAddress((void**)&vlo, g_vlo);
    cudaGetSymbolAddress((void**)&wq_hi, g_wq_hi); cudaGetSymbolAddress((void**)&wq_lo, g_wq_lo);
    cudaGetSymbolAddress((void**)&wk_hi, g_wk_hi); cudaGetSymbolAddress((void**)&wk_lo, g_wk_lo);
    cudaGetSymbolAddress((void**)&wv_hi, g_wv_hi); cudaGetSymbolAddress((void**)&wv_lo, g_wv_lo);
    cudaGetSymbolAddress((void**)&wo_hi, g_wo_hi); cudaGetSymbolAddress((void**)&wo_lo, g_wo_lo);
    cudaGetSymbolAddress((void**)&wg_hi, g_wg_hi); cudaGetSymbolAddress((void**)&wg_lo, g_wg_lo);
    cudaGetSymbolAddress((void**)&wu_hi, g_wu_hi); cudaGetSymbolAddress((void**)&wu_lo, g_wu_lo);
    cudaGetSymbolAddress((void**)&wd_hi, g_wd_hi); cudaGetSymbolAddress((void**)&wd_lo, g_wd_lo);

    cudaFuncSetAttribute(gemm_bf16x3, cudaFuncAttributeMaxDynamicSharedMemorySize, GEMM_SMEM);
    cudaFuncSetAttribute(attn_tc, cudaFuncAttributeMaxDynamicSharedMemorySize, ATTN_SMEM);

    // Launch order arranged so ncu (-s 5 -c 1) captures launch #6 = Q-projection GEMM.
    // 1-5: rope_table, rmsnorm1, converts for wq/wk/wv
    rope_table_kernel<<<(Tn * 64 + 255) / 256, 256>>>(rtab);
    rmsnorm_kernel<<<Tn, 256>>>(x, attn_norm_w, h_hi, h_lo);
    convert_kernel<<<(Cn * Cn + 255) / 256, 256>>>(wq, wq_hi, wq_lo, Cn * Cn);
    convert_kernel<<<(NKV * HD * Cn + 255) / 256, 256>>>(wk, wk_hi, wk_lo, NKV * HD * Cn);
    convert_kernel<<<(NKV * HD * Cn + 255) / 256, 256>>>(wv, wv_hi, wv_lo, NKV * HD * Cn);
    // 6-8: Q/K/V projections
    gemm_bf16x3<<<dim3(Cn / 256, Tn / 128), 256, GEMM_SMEM>>>(h_hi, h_lo, wq_hi, wq_lo, q, nullptr, Tn, Cn, Cn);
    gemm_bf16x3<<<dim3((NKV * HD) / 256, Tn / 128), 256, GEMM_SMEM>>>(h_hi, h_lo, wk_hi, wk_lo, k, nullptr, Tn, NKV * HD, Cn);
    gemm_bf16x3<<<dim3((NKV * HD) / 256, Tn / 128), 256, GEMM_SMEM>>>(h_hi, h_lo, wv_hi, wv_lo, v, nullptr, Tn, NKV * HD, Cn);
    // RoPE + split q/k, split v
    {
        int total = Tn * (NH + NKV) * 64;
        rope_split_kernel<<<(total + 255) / 256, 256>>>(q, k, rtab, qhi, qlo, khi, klo);
        convert_kernel<<<(Tn * NKV * HD + 255) / 256, 256>>>(v, vhi, vlo, Tn * NKV * HD);
    }
    // attention
    attn_tc<<<dim3(32, NH), 256, ATTN_SMEM>>>(qhi, qlo, khi, klo, vhi, vlo, y_hi, y_lo);
    // out = x + y @ wo^T
    convert_kernel<<<(Cn * Cn + 255) / 256, 256>>>(wo, wo_hi, wo_lo, Cn * Cn);
    gemm_bf16x3<<<dim3(Cn / 256, Tn / 128), 256, GEMM_SMEM>>>(y_hi, y_lo, wo_hi, wo_lo, out, x, Tn, Cn, Cn);
    // rmsnorm2 -> split
    rmsnorm_kernel<<<Tn, 256>>>(out, ffn_norm_w, h2_hi, h2_lo);
    // gate / up
    convert_kernel<<<(FFN * Cn + 255) / 256, 256>>>(w_gate, wg_hi, wg_lo, FFN * Cn);
    convert_kernel<<<(FFN * Cn + 255) / 256, 256>>>(w_up,   wu_hi, wu_lo, FFN * Cn);
    gemm_bf16x3<<<dim3(FFN / 256, Tn / 128), 256, GEMM_SMEM>>>(h2_hi, h2_lo, wg_hi, wg_lo, g, nullptr, Tn, FFN, Cn);
    gemm_bf16x3<<<dim3(FFN / 256, Tn / 128), 256, GEMM_SMEM>>>(h2_hi, h2_lo, wu_hi, wu_lo, u, nullptr, Tn, FFN, Cn);
    // silu(g)*u -> split
    silu_mul_kernel<<<(Tn * FFN / 4 + 255) / 256, 256>>>(g, u, gs_hi, gs_lo);
    // out += gs @ w_down^T
    convert_kernel<<<(Cn * FFN + 255) / 256, 256>>>(w_down, wd_hi, wd_lo, Cn * FFN);
    gemm_bf16x3<<<dim3(Cn / 256, Tn / 128), 256, GEMM_SMEM>>>(gs_hi, gs_lo, wd_hi, wd_lo, out, out, Tn, Cn, FFN);
}

// round 9
// speedup vs baseline: 3.3334x; 1.0147x over previous
#include <cuda_runtime.h>
#include <cuda_bf16.h>
#include <math.h>
#include <stdint.h>

#define Tn   4096
#define Cn   2048
#define NH   16
#define NKV  4
#define HD   128
#define FFN  8192

typedef __nv_bfloat16 bf16;

// ---------------- scratch (static device globals; no allocation) ----------------
static __device__ float  g_q [Tn * Cn];
static __device__ float  g_k [Tn * NKV * HD];
static __device__ float  g_v [Tn * NKV * HD];
static __device__ float  g_g [Tn * FFN];
static __device__ float2 g_rope[Tn * 64];

static __device__ bf16 g_h_hi [Tn * Cn],  g_h_lo [Tn * Cn];
static __device__ bf16 g_h2_hi[Tn * Cn],  g_h2_lo[Tn * Cn];
static __device__ bf16 g_y_hi [Tn * Cn],  g_y_lo [Tn * Cn];
static __device__ bf16 g_gs_hi[Tn * FFN], g_gs_lo[Tn * FFN];

static __device__ bf16 g_qhi[Tn * Cn],       g_qlo[Tn * Cn];
static __device__ bf16 g_khi[Tn * NKV * HD], g_klo[Tn * NKV * HD];
static __device__ bf16 g_vhi[Tn * NKV * HD], g_vlo[Tn * NKV * HD];

static __device__ bf16 g_wq_hi[Cn * Cn],        g_wq_lo[Cn * Cn];
static __device__ bf16 g_wk_hi[NKV * HD * Cn],  g_wk_lo[NKV * HD * Cn];
static __device__ bf16 g_wv_hi[NKV * HD * Cn],  g_wv_lo[NKV * HD * Cn];
static __device__ bf16 g_wo_hi[Cn * Cn],        g_wo_lo[Cn * Cn];
static __device__ bf16 g_wg_hi[FFN * Cn],       g_wg_lo[FFN * Cn];
static __device__ bf16 g_wu_hi[FFN * Cn],       g_wu_lo[FFN * Cn];
static __device__ bf16 g_wd_hi[Cn * FFN],       g_wd_lo[Cn * FFN];

__device__ __forceinline__ void split2(float x, bf16& hi, bf16& lo) {
    hi = __float2bfloat16(x);
    lo = __float2bfloat16(x - __bfloat162float(hi));
}

__device__ __forceinline__ uint32_t pack_bf2(bf16 a, bf16 b) {
    __nv_bfloat162 t; t.x = a; t.y = b;
    return *reinterpret_cast<uint32_t*>(&t);
}

// ---------------- common PTX helpers ----------------
__device__ __forceinline__ void cp16(uint32_t dst, const void* src) {
    asm volatile("cp.async.cg.shared.global [%0], [%1], 16;\n" :: "r"(dst), "l"(src));
}

__device__ __forceinline__ void ldm4(uint32_t* r, uint32_t addr) {
    asm volatile("ldmatrix.sync.aligned.m8n8.x4.shared.b16 {%0,%1,%2,%3}, [%4];\n"
                 : "=r"(r[0]), "=r"(r[1]), "=r"(r[2]), "=r"(r[3]) : "r"(addr));
}

__device__ __forceinline__ void ldm4t(uint32_t* r, uint32_t addr) {
    asm volatile("ldmatrix.sync.aligned.m8n8.x4.trans.shared.b16 {%0,%1,%2,%3}, [%4];\n"
                 : "=r"(r[0]), "=r"(r[1]), "=r"(r[2]), "=r"(r[3]) : "r"(addr));
}

__device__ __forceinline__ void mma16816(float* c, const uint32_t* a, const uint32_t* b) {
    asm volatile("mma.sync.aligned.m16n8k16.row.col.f32.bf16.bf16.f32 "
                 "{%0,%1,%2,%3},{%4,%5,%6,%7},{%8,%9},{%0,%1,%2,%3};\n"
                 : "+f"(c[0]), "+f"(c[1]), "+f"(c[2]), "+f"(c[3])
                 : "r"(a[0]), "r"(a[1]), "r"(a[2]), "r"(a[3]), "r"(b[0]), "r"(b[1]));
}

// ---------------- vectorized fp32 -> (hi, lo) bf16, 8 elems/thread ----------------
__global__ void convert_kernel(const float* __restrict__ w,
                               bf16* __restrict__ hi, bf16* __restrict__ lo, int n) {
    int i = (blockIdx.x * blockDim.x + threadIdx.x) * 8;
    if (i >= n) return;
    float4 a = *(const float4*)(w + i);
    float4 b = *(const float4*)(w + i + 4);
    bf16 h[8], l[8];
    split2(a.x, h[0], l[0]); split2(a.y, h[1], l[1]);
    split2(a.z, h[2], l[2]); split2(a.w, h[3], l[3]);
    split2(b.x, h[4], l[4]); split2(b.y, h[5], l[5]);
    split2(b.z, h[6], l[6]); split2(b.w, h[7], l[7]);
    uint4 ho, lo4;
    ho.x = pack_bf2(h[0], h[1]); ho.y = pack_bf2(h[2], h[3]);
    ho.z = pack_bf2(h[4], h[5]); ho.w = pack_bf2(h[6], h[7]);
    lo4.x = pack_bf2(l[0], l[1]); lo4.y = pack_bf2(l[2], l[3]);
    lo4.z = pack_bf2(l[4], l[5]); lo4.w = pack_bf2(l[6], l[7]);
    *(uint4*)(hi + i) = ho;
    *(uint4*)(lo + i) = lo4;
}

// ---------------- RoPE cos/sin table (double sincos — fast-math immune) ----------------
__global__ void rope_table_kernel(float2* __restrict__ tab) {
    int idx = blockIdx.x * blockDim.x + threadIdx.x;
    if (idx >= Tn * 64) return;
    int i = idx & 63;
    int t = idx >> 6;
    double invf_d = pow(500000.0, -((double)(2 * i) / 128.0));
    float  invf_f = (float)invf_d;
    float  ang_f  = (float)t * invf_f;
    double c, s;
    sincos((double)ang_f, &s, &c);
    tab[idx] = make_float2((float)c, (float)s);
}

// ---------------- rmsnorm: one block per row, writes split bf16 ----------------
__global__ void __launch_bounds__(256) rmsnorm_kernel(const float* __restrict__ x,
                                                      const float* __restrict__ w,
                                                      bf16* __restrict__ ohi,
                                                      bf16* __restrict__ olo) {
    const int row = blockIdx.x;
    const float* xr = x + (size_t)row * Cn;
    float s = 0.f;
    for (int i = threadIdx.x; i < Cn; i += 256) {
        float v = xr[i];
        s = fmaf(v, v, s);
    }
    __shared__ float red[8];
    #pragma unroll
    for (int o = 16; o; o >>= 1) s += __shfl_xor_sync(0xffffffffu, s, o);
    if ((threadIdx.x & 31) == 0) red[threadIdx.x >> 5] = s;
    __syncthreads();
    if (threadIdx.x < 32) {
        float v = (threadIdx.x < 8) ? red[threadIdx.x] : 0.f;
        #pragma unroll
        for (int o = 4; o; o >>= 1) v += __shfl_xor_sync(0xffffffffu, v, o);
        if (threadIdx.x == 0) red[0] = v;
    }
    __syncthreads();
    const float scale = rsqrtf(red[0] * (1.0f / Cn) + 1e-5f);
    size_t base = (size_t)row * Cn;
    for (int i = threadIdx.x; i < Cn; i += 256) {
        float v = xr[i] * scale * w[i];
        split2(v, ohi[base + i], olo[base + i]);
    }
}

// =====================================================================
// bf16x3 tensor-core GEMM: 128(M) x 256(N), warp 64x64, 4-stage cp.async,
// CTA swizzle. mode 0: C = acc (+R). mode 1: silu(Gate)*acc -> split Ohi/Olo.
// =====================================================================
#define STAGES 4
#define G_AHI 0
#define G_ALO 8192
#define G_BHI 16384
#define G_BLO 32768
#define G_STAGE 49152
#define GEMM_SMEM (STAGES * G_STAGE)

__device__ __forceinline__ uint32_t sw(uint32_t row, uint32_t chunk) {
    return (row << 6) + (((chunk ^ (row >> 1)) & 3u) << 4);
}

__global__ void __launch_bounds__(256, 1) gemm_bf16x3(
        const bf16* __restrict__ Ahi, const bf16* __restrict__ Alo,
        const bf16* __restrict__ Bhi, const bf16* __restrict__ Blo,
        float* __restrict__ C, const float* __restrict__ R,
        bf16* __restrict__ Ohi, bf16* __restrict__ Olo,
        const float* __restrict__ Gate, int mode,
        int M, int N, int K) {
    extern __shared__ __align__(128) char smem_raw[];
    const uint32_t smem_u = (uint32_t)__cvta_generic_to_shared(smem_raw);
    const int tid  = threadIdx.x;
    const int warp = tid >> 5;
    const int lane = tid & 31;
    const int wm   = warp & 1;       // 2 warps along M (64 rows each)
    const int wn   = warp >> 1;      // 4 warps along N (64 cols each)

    // ---- CTA swizzle: 8-row supertiles so concurrent CTAs share A panels ----
    int bx, by;
    {
        int tiles_n = gridDim.x, tiles_m = gridDim.y;
        int lin = blockIdx.y * tiles_n + blockIdx.x;
        int per = 8 * tiles_n;
        int gid = lin / per, rem = lin % per;
        int gm  = tiles_m - gid * 8;
        if (gm > 8) gm = 8;
        by = gid * 8 + rem % gm;
        bx = rem / gm;
    }
    const int bm = by * 128;
    const int bn = bx * 256;

    float acc[4][8][4];
    #pragma unroll
    for (int i = 0; i < 4; i++)
        #pragma unroll
        for (int j = 0; j < 8; j++)
            #pragma unroll
            for (int v = 0; v < 4; v++) acc[i][j][v] = 0.f;

    const int kiters = K >> 5;

    auto load_stage = [&](int stage, int kt) {
        const uint32_t sbase = smem_u + stage * G_STAGE;
        #pragma unroll
        for (int rep = 0; rep < 2; rep++) {          // A: 128 rows x 4 chunks
            int idx = tid + rep * 256;
            int row = idx >> 2;
            int ch  = idx & 3;
            size_t go = (size_t)(bm + row) * K + kt + ch * 8;
            uint32_t so = sw(row, ch);
            cp16(sbase + G_AHI + so, Ahi + go);
            cp16(sbase + G_ALO + so, Alo + go);
        }
        #pragma unroll
        for (int rep = 0; rep < 4; rep++) {          // B: 256 rows x 4 chunks
            int idx = tid + rep * 256;
            int row = idx >> 2;
            int ch  = idx & 3;
            size_t go = (size_t)(bn + row) * K + kt + ch * 8;
            uint32_t so = sw(row, ch);
            cp16(sbase + G_BHI + so, Bhi + go);
            cp16(sbase + G_BLO + so, Blo + go);
        }
    };

    #pragma unroll
    for (int s = 0; s < STAGES - 1; s++) {
        load_stage(s, s * 32);
        asm volatile("cp.async.commit_group;\n");
    }

    for (int it = 0; it < kiters; ++it) {
        asm volatile("cp.async.wait_group %0;\n" :: "n"(STAGES - 2));
        __syncthreads();
        int pf = it + STAGES - 1;
        if (pf < kiters) load_stage(pf % STAGES, pf * 32);
        asm volatile("cp.async.commit_group;\n");

        const uint32_t sb = smem_u + (it % STAGES) * G_STAGE;

        #pragma unroll
        for (int kf = 0; kf < 2; kf++) {
            uint32_t ah[4][4], al[4][4];
            #pragma unroll
            for (int mt = 0; mt < 4; mt++) {
                uint32_t row = wm * 64 + mt * 16 + (lane & 15);
                uint32_t ch  = kf * 2 + (lane >> 4);
                uint32_t off = sw(row, ch);
                ldm4(ah[mt], sb + G_AHI + off);
                ldm4(al[mt], sb + G_ALO + off);
            }
            #pragma unroll
            for (int p = 0; p < 4; p++) {            // covers nt = 2p, 2p+1
                uint32_t rowb = wn * 64 + p * 16 + (lane & 7) + ((lane >> 4) & 1) * 8;
                uint32_t chb  = kf * 2 + ((lane >> 3) & 1);
                uint32_t offb = sw(rowb, chb);
                uint32_t bh[4], bl[4];
                ldm4(bh, sb + G_BHI + offb);
                ldm4(bl, sb + G_BLO + offb);
                // product-major; per-acc order hh, hl, lh (bit-identical)
                #pragma unroll
                for (int mt = 0; mt < 4; mt++) {
                    mma16816(acc[mt][2 * p],     ah[mt], bh);
                    mma16816(acc[mt][2 * p + 1], ah[mt], bh + 2);
                }
                #pragma unroll
                for (int mt = 0; mt < 4; mt++) {
                    mma16816(acc[mt][2 * p],     ah[mt], bl);
                    mma16816(acc[mt][2 * p + 1], ah[mt], bl + 2);
                }
                #pragma unroll
                for (int mt = 0; mt < 4; mt++) {
                    mma16816(acc[mt][2 * p],     al[mt], bh);
                    mma16816(acc[mt][2 * p + 1], al[mt], bh + 2);
                }
            }
        }
    }

    // ---- epilogue ----
    const int rb = bm + wm * 64;
    const int cb = bn + wn * 64;
    #pragma unroll
    for (int mt = 0; mt < 4; mt++)
        #pragma unroll
        for (int nt = 0; nt < 8; nt++) {
            int r0 = rb + mt * 16 + (lane >> 2);
            int c  = cb + nt * 8 + (lane & 3) * 2;
            size_t i0 = (size_t)r0 * N + c;
            size_t i1 = (size_t)(r0 + 8) * N + c;
            if (mode == 0) {
                float2 v0 = make_float2(acc[mt][nt][0], acc[mt][nt][1]);
                float2 v1 = make_float2(acc[mt][nt][2], acc[mt][nt][3]);
                if (R) {
                    float2 q0 = *(const float2*)(R + i0);
                    float2 q1 = *(const float2*)(R + i1);
                    v0.x += q0.x; v0.y += q0.y;
                    v1.x += q1.x; v1.y += q1.y;
                }
                *(float2*)(C + i0) = v0;
                *(float2*)(C + i1) = v1;
            } else {
                // silu(Gate) * acc -> split bf16
                float2 g0 = *(const float2*)(Gate + i0);
                float2 g1 = *(const float2*)(Gate + i1);
                float r00 = g0.x / (1.f + expf(-g0.x)) * acc[mt][nt][0];
                float r01 = g0.y / (1.f + expf(-g0.y)) * acc[mt][nt][1];
                float r10 = g1.x / (1.f + expf(-g1.x)) * acc[mt][nt][2];
                float r11 = g1.y / (1.f + expf(-g1.y)) * acc[mt][nt][3];
                bf16 a, b, e, f;
                split2(r00, a, e); split2(r01, b, f);
                *(uint32_t*)(Ohi + i0) = pack_bf2(a, b);
                *(uint32_t*)(Olo + i0) = pack_bf2(e, f);
                split2(r10, a, e); split2(r11, b, f);
                *(uint32_t*)(Ohi + i1) = pack_bf2(a, b);
                *(uint32_t*)(Olo + i1) = pack_bf2(e, f);
            }
        }
}

// ---------------- RoPE + split: fp32 q/k -> rotated split bf16 ----------------
__global__ void rope_split_kernel(const float* __restrict__ q, const float* __restrict__ k,
                                  const float2* __restrict__ tab,
                                  bf16* __restrict__ qhi, bf16* __restrict__ qlo,
                                  bf16* __restrict__ khi, bf16* __restrict__ klo) {
    const int total = Tn * (NH + NKV) * 64;
    int idx = blockIdx.x * blockDim.x + threadIdx.x;
    if (idx >= total) return;
    int i    = idx & 63;
    int rest = idx >> 6;
    int head = rest % (NH + NKV);
    int t    = rest / (NH + NKV);
    float2 cs = tab[t * 64 + i];
    float c = cs.x, s = cs.y;
    if (head < NH) {
        size_t off = (size_t)t * Cn + head * HD + 2 * i;
        float2 ab = *(const float2*)(q + off);
        float a = ab.x, b = ab.y;
        float r0 = fmaf(a, c, -b * s);
        float r1 = fmaf(a, s,  b * c);
        split2(r0, qhi[off], qlo[off]);
        split2(r1, qhi[off + 1], qlo[off + 1]);
    } else {
        size_t off = (size_t)t * (NKV * HD) + (head - NH) * HD + 2 * i;
        float2 ab = *(const float2*)(k + off);
        float a = ab.x, b = ab.y;
        float r0 = fmaf(a, c, -b * s);
        float r1 = fmaf(a, s,  b * c);
        split2(r0, khi[off], klo[off]);
        split2(r1, khi[off + 1], klo[off + 1]);
    }
}

// =====================================================================
// Tensor-core causal flash attention (split precision) — unchanged R8
// =====================================================================
#define AQ_HI 0
#define AQ_LO 32768
#define AKV   65536
#define AKV_STAGE 65536
#define AK_LO 16384
#define AV_HI 32768
#define AV_LO 49152
#define ATTN_SMEM (AKV + 2 * AKV_STAGE)

__device__ __forceinline__ uint32_t sw256(uint32_t row, uint32_t ch) {
    return (row << 8) + ((((ch ^ row) & 7u) | (ch & 8u)) << 4);
}

__global__ void __launch_bounds__(256, 1) attn_tc(
        const bf16* __restrict__ qhi, const bf16* __restrict__ qlo,
        const bf16* __restrict__ khi, const bf16* __restrict__ klo,
        const bf16* __restrict__ vhi, const bf16* __restrict__ vlo,
        bf16* __restrict__ yhi, bf16* __restrict__ ylo) {
    extern __shared__ __align__(128) char smem_raw[];
    const uint32_t sb = (uint32_t)__cvta_generic_to_shared(smem_raw);
    const int qt   = 31 - blockIdx.x;
    const int head = blockIdx.y;
    const int kvh  = head >> 2;
    const int qb   = qt * 128;
    const int tid  = threadIdx.x;
    const int warp = tid >> 5;
    const int lane = tid & 31;
    const int njt  = 2 * qt + 2;

    #pragma unroll
    for (int i = 0; i < 8; i++) {
        int idx = tid + i * 256;
        int row = idx >> 4;
        int ch  = idx & 15;
        size_t g = (size_t)(qb + row) * Cn + head * HD + ch * 8;
        uint32_t off = sw256(row, ch);
        cp16(sb + AQ_HI + off, qhi + g);
        cp16(sb + AQ_LO + off, qlo + g);
    }

    auto load_kv = [&](int jt, int buf) {
        const uint32_t base = sb + AKV + buf * AKV_STAGE;
        #pragma unroll
        for (int i = 0; i < 4; i++) {
            int idx = tid + i * 256;
            int row = idx >> 4;
            int ch  = idx & 15;
            size_t g = (size_t)(jt * 64 + row) * (NKV * HD) + kvh * HD + ch * 8;
            uint32_t off = sw256(row, ch);
            cp16(base + off,          khi + g);
            cp16(base + AK_LO + off,  klo + g);
            cp16(base + AV_HI + off,  vhi + g);
            cp16(base + AV_LO + off,  vlo + g);
        }
    };

    load_kv(0, 0);
    asm volatile("cp.async.commit_group;\n");

    float m0 = -1e30f, m1 = -1e30f, l0 = 0.f, l1 = 0.f;
    float o[16][4];
    #pragma unroll
    for (int nt = 0; nt < 16; nt++)
        #pragma unroll
        for (int e = 0; e < 4; e++) o[nt][e] = 0.f;

    const float cs = 0.12751743621340608f;      // log2(e)/sqrt(128)
    const int r0g = qb + (warp << 4) + (lane >> 2);
    const int r1g = r0g + 8;

    for (int jt = 0; jt < njt; jt++) {
        if (jt + 1 < njt) load_kv(jt + 1, (jt + 1) & 1);
        asm volatile("cp.async.commit_group;\n");
        asm volatile("cp.async.wait_group 1;\n");
        __syncthreads();

        const uint32_t kb   = sb + AKV + (jt & 1) * AKV_STAGE;
        const uint32_t kbl  = kb + AK_LO;
        const uint32_t vb   = kb + AV_HI;
        const uint32_t vbl  = kb + AV_LO;

        float sacc[8][4];
        #pragma unroll
        for (int nt = 0; nt < 8; nt++)
            #pragma unroll
            for (int e = 0; e < 4; e++) sacc[nt][e] = 0.f;

        #pragma unroll
        for (int ks = 0; ks < 8; ks++) {
            uint32_t ah[4], al[4];
            {
                uint32_t row = (warp << 4) + (lane & 15);
                uint32_t ch  = ks * 2 + (lane >> 4);
                uint32_t off = sw256(row, ch);
                ldm4(ah, sb + AQ_HI + off);
                ldm4(al, sb + AQ_LO + off);
            }
            uint32_t bh[8][2], bl[8][2];
            #pragma unroll
            for (int p = 0; p < 4; p++) {
                uint32_t rowb = p * 16 + (lane & 7) + ((lane >> 4) & 1) * 8;
                uint32_t chb  = ks * 2 + ((lane >> 3) & 1);
                uint32_t offb = sw256(rowb, chb);
                uint32_t r[4];
                ldm4(r, kb + offb);
                bh[2 * p][0] = r[0]; bh[2 * p][1] = r[1];
                bh[2 * p + 1][0] = r[2]; bh[2 * p + 1][1] = r[3];
                ldm4(r, kbl + offb);
                bl[2 * p][0] = r[0]; bl[2 * p][1] = r[1];
                bl[2 * p + 1][0] = r[2]; bl[2 * p + 1][1] = r[3];
            }
            #pragma unroll
            for (int nt = 0; nt < 8; nt++) mma16816(sacc[nt], ah, bh[nt]);
            #pragma unroll
            for (int nt = 0; nt < 8; nt++) mma16816(sacc[nt], ah, bl[nt]);
            #pragma unroll
            for (int nt = 0; nt < 8; nt++) mma16816(sacc[nt], al, bh[nt]);
        }

        const bool domask = (jt >= 2 * qt);
        #pragma unroll
        for (int nt = 0; nt < 8; nt++) {
            int cbase = jt * 64 + nt * 8 + (lane & 3) * 2;
            #pragma unroll
            for (int e = 0; e < 4; e++) {
                float v = sacc[nt][e] * cs;
                if (domask) {
                    int col = cbase + (e & 1);
                    int row = (e < 2) ? r0g : r1g;
                    if (col > row) v = -1e30f;
                }
                sacc[nt][e] = v;
            }
        }

        float mx0 = -1e30f, mx1 = -1e30f;
        #pragma unroll
        for (int nt = 0; nt < 8; nt++) {
            mx0 = fmaxf(mx0, fmaxf(sacc[nt][0], sacc[nt][1]));
            mx1 = fmaxf(mx1, fmaxf(sacc[nt][2], sacc[nt][3]));
        }
        mx0 = fmaxf(mx0, __shfl_xor_sync(0xffffffffu, mx0, 1));
        mx0 = fmaxf(mx0, __shfl_xor_sync(0xffffffffu, mx0, 2));
        mx1 = fmaxf(mx1, __shfl_xor_sync(0xffffffffu, mx1, 1));
        mx1 = fmaxf(mx1, __shfl_xor_sync(0xffffffffu, mx1, 2));
        float mn0 = fmaxf(m0, mx0);
        float mn1 = fmaxf(m1, mx1);

        float ls0 = 0.f, ls1 = 0.f;
        #pragma unroll
        for (int nt = 0; nt < 8; nt++) {
            float p0 = exp2f(sacc[nt][0] - mn0);
            float p1 = exp2f(sacc[nt][1] - mn0);
            float p2 = exp2f(sacc[nt][2] - mn1);
            float p3 = exp2f(sacc[nt][3] - mn1);
            ls0 += p0 + p1;
            ls1 += p2 + p3;
            sacc[nt][0] = p0; sacc[nt][1] = p1; sacc[nt][2] = p2; sacc[nt][3] = p3;
        }
        ls0 += __shfl_xor_sync(0xffffffffu, ls0, 1);
        ls0 += __shfl_xor_sync(0xffffffffu, ls0, 2);
        ls1 += __shfl_xor_sync(0xffffffffu, ls1, 1);
        ls1 += __shfl_xor_sync(0xffffffffu, ls1, 2);

        float a0 = exp2f(m0 - mn0);
        float a1 = exp2f(m1 - mn1);
        m0 = mn0; m1 = mn1;
        l0 = l0 * a0 + ls0;
        l1 = l1 * a1 + ls1;
        #pragma unroll
        for (int nt = 0; nt < 16; nt++) {
            o[nt][0] *= a0; o[nt][1] *= a0;
            o[nt][2] *= a1; o[nt][3] *= a1;
        }

        #pragma unroll
        for (int ks = 0; ks < 4; ks++) {
            bf16 h0, q0, h1, q1, h2, q2, h3, q3;
            uint32_t ah[4], al[4];
            split2(sacc[2 * ks][0], h0, q0); split2(sacc[2 * ks][1], h1, q1);
            ah[0] = pack_bf2(h0, h1); al[0] = pack_bf2(q0, q1);
            split2(sacc[2 * ks][2], h0, q0); split2(sacc[2 * ks][3], h1, q1);
            ah[1] = pack_bf2(h0, h1); al[1] = pack_bf2(q0, q1);
            split2(sacc[2 * ks + 1][0], h2, q2); split2(sacc[2 * ks + 1][1], h3, q3);
            ah[2] = pack_bf2(h2, h3); al[2] = pack_bf2(q2, q3);
            split2(sacc[2 * ks + 1][2], h2, q2); split2(sacc[2 * ks + 1][3], h3, q3);
            ah[3] = pack_bf2(h2, h3); al[3] = pack_bf2(q2, q3);

            #pragma unroll
            for (int dq = 0; dq < 4; dq++) {
                uint32_t row = ks * 16 + (lane & 15);
                uint32_t ch0 = (2 * dq) * 2 + (lane >> 4);
                uint32_t ch1 = (2 * dq + 1) * 2 + (lane >> 4);
                uint32_t bh0[4], bl0[4], bh1[4], bl1[4];
                ldm4t(bh0, vb + sw256(row, ch0));
                ldm4t(bl0, vbl + sw256(row, ch0));
                ldm4t(bh1, vb + sw256(row, ch1));
                ldm4t(bl1, vbl + sw256(row, ch1));
                float* o0 = o[4 * dq + 0];
                float* o1 = o[4 * dq + 1];
                float* o2 = o[4 * dq + 2];
                float* o3 = o[4 * dq + 3];
                mma16816(o0, ah, bh0);     mma16816(o1, ah, bh0 + 2);
                mma16816(o2, ah, bh1);     mma16816(o3, ah, bh1 + 2);
                mma16816(o0, al, bh0);     mma16816(o1, al, bh0 + 2);
                mma16816(o2, al, bh1);     mma16816(o3, al, bh1 + 2);
                mma16816(o0, ah, bl0);     mma16816(o1, ah, bl0 + 2);
                mma16816(o2, ah, bl1);     mma16816(o3, ah, bl1 + 2);
            }
        }
        __syncthreads();
    }

    float inv0 = 1.0f / l0;
    float inv1 = 1.0f / l1;
    #pragma unroll
    for (int nt = 0; nt < 16; nt++) {
        int c = head * HD + nt * 8 + (lane & 3) * 2;
        size_t i0 = (size_t)r0g * Cn + c;
        size_t i1 = (size_t)r1g * Cn + c;
        bf16 a, b, e, f;
        split2(o[nt][0] * inv0, a, e);
        split2(o[nt][1] * inv0, b, f);
        *(uint32_t*)(yhi + i0) = pack_bf2(a, b);
        *(uint32_t*)(ylo + i0) = pack_bf2(e, f);
        split2(o[nt][2] * inv1, a, e);
        split2(o[nt][3] * inv1, b, f);
        *(uint32_t*)(yhi + i1) = pack_bf2(a, b);
        *(uint32_t*)(ylo + i1) = pack_bf2(e, f);
    }
}

// ---------------- launch ----------------
extern "C" void kernel_launch(void* const* d_in, const int* in_sizes, int n_in,
                              void* d_out, int out_size) {
    (void)in_sizes; (void)n_in; (void)out_size;
    const float* x           = (const float*)d_in[0];
    const float* attn_norm_w = (const float*)d_in[2];
    const float* wq          = (const float*)d_in[3];
    const float* wk          = (const float*)d_in[4];
    const float* wv          = (const float*)d_in[5];
    const float* wo          = (const float*)d_in[6];
    const float* ffn_norm_w  = (const float*)d_in[7];
    const float* w_gate      = (const float*)d_in[8];
    const float* w_up        = (const float*)d_in[9];
    const float* w_down      = (const float*)d_in[10];
    float* out = (float*)d_out;

    float *q, *k, *v, *g;
    float2* rtab;
    bf16 *h_hi, *h_lo, *h2_hi, *h2_lo, *y_hi, *y_lo, *gs_hi, *gs_lo;
    bf16 *qhi, *qlo, *khi, *klo, *vhi, *vlo;
    bf16 *wq_hi, *wq_lo, *wk_hi, *wk_lo, *wv_hi, *wv_lo, *wo_hi, *wo_lo;
    bf16 *wg_hi, *wg_lo, *wu_hi, *wu_lo, *wd_hi, *wd_lo;

    cudaGetSymbolAddress((void**)&q,  g_q);
    cudaGetSymbolAddress((void**)&k,  g_k);
    cudaGetSymbolAddress((void**)&v,  g_v);
    cudaGetSymbolAddress((void**)&g,  g_g);
    cudaGetSymbolAddress((void**)&rtab, g_rope);
    cudaGetSymbolAddress((void**)&h_hi,  g_h_hi);  cudaGetSymbolAddress((void**)&h_lo,  g_h_lo);
    cudaGetSymbolAddress((void**)&h2_hi, g_h2_hi); cudaGetSymbolAddress((void**)&h2_lo, g_h2_lo);
    cudaGetSymbolAddress((void**)&y_hi,  g_y_hi);  cudaGetSymbolAddress((void**)&y_lo,  g_y_lo);
    cudaGetSymbolAddress((void**)&gs_hi, g_gs_hi); cudaGetSymbolAddress((void**)&gs_lo, g_gs_lo);
    cudaGetSymbolAddress((void**)&qhi, g_qhi); cudaGetSymbolAddress((void**)&qlo, g_qlo);
    cudaGetSymbolAddress((void**)&khi, g_khi); cudaGetSymbolAddress((void**)&klo, g_klo);
    cudaGetSymbolAddress((void**)&vhi, g_vhi); cudaGetSymbolAddress((void**)&vlo, g_vlo);
    cudaGetSymbolAddress((void**)&wq_hi, g_wq_hi); cudaGetSymbolAddress((void**)&wq_lo, g_wq_lo);
    cudaGetSymbolAddress((void**)&wk_hi, g_wk_hi); cudaGetSymbolAddress((void**)&wk_lo, g_wk_lo);
    cudaGetSymbolAddress((void**)&wv_hi, g_wv_hi); cudaGetSymbolAddress((void**)&wv_lo, g_wv_lo);
    cudaGetSymbolAddress((void**)&wo_hi, g_wo_hi); cudaGetSymbolAddress((void**)&wo_lo, g_wo_lo);
    cudaGetSymbolAddress((void**)&wg_hi, g_wg_hi); cudaGetSymbolAddress((void**)&wg_lo, g_wg_lo);
    cudaGetSymbolAddress((void**)&wu_hi, g_wu_hi); cudaGetSymbolAddress((void**)&wu_lo, g_wu_lo);
    cudaGetSymbolAddress((void**)&wd_hi, g_wd_hi); cudaGetSymbolAddress((void**)&wd_lo, g_wd_lo);

    cudaFuncSetAttribute(gemm_bf16x3, cudaFuncAttributeMaxDynamicSharedMemorySize, GEMM_SMEM);
    cudaFuncSetAttribute(attn_tc, cudaFuncAttributeMaxDynamicSharedMemorySize, ATTN_SMEM);

    #define CONV(src, dhi, dlo, n) \
        convert_kernel<<<((n) / 8 + 255) / 256, 256>>>(src, dhi, dlo, n)
    #define GEMM0(A_hi, A_lo, B_hi, B_lo, Cp, Rp, Mm, Nn, Kk) \
        gemm_bf16x3<<<dim3((Nn) / 256, (Mm) / 128), 256, GEMM_SMEM>>>( \
            A_hi, A_lo, B_hi, B_lo, Cp, Rp, nullptr, nullptr, nullptr, 0, Mm, Nn, Kk)

    // launches 1-4
    rope_table_kernel<<<(Tn * 64 + 255) / 256, 256>>>(rtab);
    rmsnorm_kernel<<<Tn, 256>>>(x, attn_norm_w, h_hi, h_lo);
    CONV(wq, wq_hi, wq_lo, Cn * Cn);
    CONV(wk, wk_hi, wk_lo, NKV * HD * Cn);
    // launches 5 & 6 are both GEMMs -> ncu capture lands on a GEMM either way
    GEMM0(h_hi, h_lo, wq_hi, wq_lo, q, nullptr, Tn, Cn, Cn);
    GEMM0(h_hi, h_lo, wk_hi, wk_lo, k, nullptr, Tn, NKV * HD, Cn);
    CONV(wv, wv_hi, wv_lo, NKV * HD * Cn);
    GEMM0(h_hi, h_lo, wv_hi, wv_lo, v, nullptr, Tn, NKV * HD, Cn);
    // RoPE + split q/k, split v
    {
        int total = Tn * (NH + NKV) * 64;
        rope_split_kernel<<<(total + 255) / 256, 256>>>(q, k, rtab, qhi, qlo, khi, klo);
        CONV(v, vhi, vlo, Tn * NKV * HD);
    }
    // attention
    attn_tc<<<dim3(32, NH), 256, ATTN_SMEM>>>(qhi, qlo, khi, klo, vhi, vlo, y_hi, y_lo);
    // out = x + y @ wo^T
    CONV(wo, wo_hi, wo_lo, Cn * Cn);
    GEMM0(y_hi, y_lo, wo_hi, wo_lo, out, x, Tn, Cn, Cn);
    // rmsnorm2 -> split
    rmsnorm_kernel<<<Tn, 256>>>(out, ffn_norm_w, h2_hi, h2_lo);
    // gate (fp32) then up (fused silu epilogue -> split bf16)
    CONV(w_gate, wg_hi, wg_lo, FFN * Cn);
    CONV(w_up,   wu_hi, wu_lo, FFN * Cn);
    GEMM0(h2_hi, h2_lo, wg_hi, wg_lo, g, nullptr, Tn, FFN, Cn);
    gemm_bf16x3<<<dim3(FFN / 256, Tn / 128), 256, GEMM_SMEM>>>(
        h2_hi, h2_lo, wu_hi, wu_lo, nullptr, nullptr, gs_hi, gs_lo, g, 1, Tn, FFN, Cn);
    // out += gs @ w_down^T
    CONV(w_down, wd_hi, wd_lo, Cn * FFN);
    GEMM0(gs_hi, gs_lo, wd_hi, wd_lo, out, out, Tn, Cn, FFN);

    #undef CONV
    #undef GEMM0
}

// round 11
// speedup vs baseline: 4.4070x; 1.3221x over previous
#include <cuda_runtime.h>
#include <cuda_bf16.h>
#include <cuda_fp16.h>
#include <math.h>
#include <stdint.h>

#define Tn   4096
#define Cn   2048
#define NH   16
#define NKV  4
#define HD   128
#define FFN  8192

typedef __nv_bfloat16 bf16;
typedef __half fp16;

// ---------------- scratch (static device globals; no allocation) ----------------
static __device__ float  g_q [Tn * Cn];
static __device__ float  g_k [Tn * NKV * HD];
static __device__ float  g_v [Tn * NKV * HD];
static __device__ float  g_g [Tn * FFN];
static __device__ float2 g_rope[Tn * 64];

// GEMM activations: fp16 split
static __device__ fp16 g_h_hi [Tn * Cn],  g_h_lo [Tn * Cn];
static __device__ fp16 g_h2_hi[Tn * Cn],  g_h2_lo[Tn * Cn];
static __device__ fp16 g_y_hi [Tn * Cn],  g_y_lo [Tn * Cn];
static __device__ fp16 g_gs_hi[Tn * FFN], g_gs_lo[Tn * FFN];

// attention operands: bf16 split (proven x3 path)
static __device__ bf16 g_qhi[Tn * Cn],       g_qlo[Tn * Cn];
static __device__ bf16 g_khi[Tn * NKV * HD], g_klo[Tn * NKV * HD];
static __device__ bf16 g_vhi[Tn * NKV * HD], g_vlo[Tn * NKV * HD];

// GEMM weights: single fp16
static __device__ fp16 g_wq_h[Cn * Cn];
static __device__ fp16 g_wk_h[NKV * HD * Cn];
static __device__ fp16 g_wv_h[NKV * HD * Cn];
static __device__ fp16 g_wo_h[Cn * Cn];
static __device__ fp16 g_wg_h[FFN * Cn];
static __device__ fp16 g_wu_h[FFN * Cn];
static __device__ fp16 g_wd_h[Cn * FFN];

__device__ __forceinline__ void split2(float x, bf16& hi, bf16& lo) {
    hi = __float2bfloat16(x);
    lo = __float2bfloat16(x - __bfloat162float(hi));
}
__device__ __forceinline__ void split2h(float x, fp16& hi, fp16& lo) {
    hi = __float2half(x);
    lo = __float2half(x - __half2float(hi));
}
__device__ __forceinline__ uint32_t pack_bf2(bf16 a, bf16 b) {
    __nv_bfloat162 t; t.x = a; t.y = b;
    return *reinterpret_cast<uint32_t*>(&t);
}
__device__ __forceinline__ uint32_t pack_h2(fp16 a, fp16 b) {
    __half2 t; t.x = a; t.y = b;
    return *reinterpret_cast<uint32_t*>(&t);
}

// ---------------- common PTX helpers ----------------
__device__ __forceinline__ void cp16(uint32_t dst, const void* src) {
    asm volatile("cp.async.cg.shared.global [%0], [%1], 16;\n" :: "r"(dst), "l"(src));
}
__device__ __forceinline__ void ldm4(uint32_t* r, uint32_t addr) {
    asm volatile("ldmatrix.sync.aligned.m8n8.x4.shared.b16 {%0,%1,%2,%3}, [%4];\n"
                 : "=r"(r[0]), "=r"(r[1]), "=r"(r[2]), "=r"(r[3]) : "r"(addr));
}
__device__ __forceinline__ void ldm4t(uint32_t* r, uint32_t addr) {
    asm volatile("ldmatrix.sync.aligned.m8n8.x4.trans.shared.b16 {%0,%1,%2,%3}, [%4];\n"
                 : "=r"(r[0]), "=r"(r[1]), "=r"(r[2]), "=r"(r[3]) : "r"(addr));
}
// bf16 mma (attention)
__device__ __forceinline__ void mma16816(float* c, const uint32_t* a, const uint32_t* b) {
    asm volatile("mma.sync.aligned.m16n8k16.row.col.f32.bf16.bf16.f32 "
                 "{%0,%1,%2,%3},{%4,%5,%6,%7},{%8,%9},{%0,%1,%2,%3};\n"
                 : "+f"(c[0]), "+f"(c[1]), "+f"(c[2]), "+f"(c[3])
                 : "r"(a[0]), "r"(a[1]), "r"(a[2]), "r"(a[3]), "r"(b[0]), "r"(b[1]));
}
// fp16 mma (GEMM)
__device__ __forceinline__ void mma16816h(float* c, const uint32_t* a, const uint32_t* b) {
    asm volatile("mma.sync.aligned.m16n8k16.row.col.f32.f16.f16.f32 "
                 "{%0,%1,%2,%3},{%4,%5,%6,%7},{%8,%9},{%0,%1,%2,%3};\n"
                 : "+f"(c[0]), "+f"(c[1]), "+f"(c[2]), "+f"(c[3])
                 : "r"(a[0]), "r"(a[1]), "r"(a[2]), "r"(a[3]), "r"(b[0]), "r"(b[1]));
}

// ---------------- weight fp32 -> single fp16 (8 elems/thread) ----------------
__global__ void convert_w_kernel(const float* __restrict__ w, fp16* __restrict__ o, int n) {
    int i = (blockIdx.x * blockDim.x + threadIdx.x) * 8;
    if (i >= n) return;
    float4 a = *(const float4*)(w + i);
    float4 b = *(const float4*)(w + i + 4);
    uint4 p;
    p.x = pack_h2(__float2half(a.x), __float2half(a.y));
    p.y = pack_h2(__float2half(a.z), __float2half(a.w));
    p.z = pack_h2(__float2half(b.x), __float2half(b.y));
    p.w = pack_h2(__float2half(b.z), __float2half(b.w));
    *(uint4*)(o + i) = p;
}

// ---------------- fp32 -> (hi, lo) bf16 (for attention V) ----------------
__global__ void convert_bf_kernel(const float* __restrict__ w,
                                  bf16* __restrict__ hi, bf16* __restrict__ lo, int n) {
    int i = (blockIdx.x * blockDim.x + threadIdx.x) * 8;
    if (i >= n) return;
    float4 a = *(const float4*)(w + i);
    float4 b = *(const float4*)(w + i + 4);
    bf16 h[8], l[8];
    split2(a.x, h[0], l[0]); split2(a.y, h[1], l[1]);
    split2(a.z, h[2], l[2]); split2(a.w, h[3], l[3]);
    split2(b.x, h[4], l[4]); split2(b.y, h[5], l[5]);
    split2(b.z, h[6], l[6]); split2(b.w, h[7], l[7]);
    uint4 ho, lo4;
    ho.x = pack_bf2(h[0], h[1]); ho.y = pack_bf2(h[2], h[3]);
    ho.z = pack_bf2(h[4], h[5]); ho.w = pack_bf2(h[6], h[7]);
    lo4.x = pack_bf2(l[0], l[1]); lo4.y = pack_bf2(l[2], l[3]);
    lo4.z = pack_bf2(l[4], l[5]); lo4.w = pack_bf2(l[6], l[7]);
    *(uint4*)(hi + i) = ho;
    *(uint4*)(lo + i) = lo4;
}

// ---------------- RoPE cos/sin table (double sincos — fast-math immune) ----------------
__global__ void rope_table_kernel(float2* __restrict__ tab) {
    int idx = blockIdx.x * blockDim.x + threadIdx.x;
    if (idx >= Tn * 64) return;
    int i = idx & 63;
    int t = idx >> 6;
    double invf_d = pow(500000.0, -((double)(2 * i) / 128.0));
    float  invf_f = (float)invf_d;
    float  ang_f  = (float)t * invf_f;
    double c, s;
    sincos((double)ang_f, &s, &c);
    tab[idx] = make_float2((float)c, (float)s);
}

// ---------------- rmsnorm: one block per row, writes split fp16 ----------------
__global__ void __launch_bounds__(256) rmsnorm_kernel(const float* __restrict__ x,
                                                      const float* __restrict__ w,
                                                      fp16* __restrict__ ohi,
                                                      fp16* __restrict__ olo) {
    const int row = blockIdx.x;
    const float* xr = x + (size_t)row * Cn;
    float s = 0.f;
    for (int i = threadIdx.x; i < Cn; i += 256) {
        float v = xr[i];
        s = fmaf(v, v, s);
    }
    __shared__ float red[8];
    #pragma unroll
    for (int o = 16; o; o >>= 1) s += __shfl_xor_sync(0xffffffffu, s, o);
    if ((threadIdx.x & 31) == 0) red[threadIdx.x >> 5] = s;
    __syncthreads();
    if (threadIdx.x < 32) {
        float v = (threadIdx.x < 8) ? red[threadIdx.x] : 0.f;
        #pragma unroll
        for (int o = 4; o; o >>= 1) v += __shfl_xor_sync(0xffffffffu, v, o);
        if (threadIdx.x == 0) red[0] = v;
    }
    __syncthreads();
    const float scale = rsqrtf(red[0] * (1.0f / Cn) + 1e-5f);
    size_t base = (size_t)row * Cn;
    for (int i = threadIdx.x; i < Cn; i += 256) {
        float v = xr[i] * scale * w[i];
        split2h(v, ohi[base + i], olo[base + i]);
    }
}

// =====================================================================
// fp16x2 tensor-core GEMM: A = Ahi+Alo (fp16 split), B single fp16.
// 128(M) x 256(N), warp 64x64, BK=32, 4-stage cp.async, CTA swizzle.
// mode 0: C = acc (+R). mode 1: silu(Gate)*acc -> split fp16 Ohi/Olo.
// =====================================================================
#define STAGES 4
#define G_AHI 0
#define G_ALO 8192
#define G_B   16384
#define G_STAGE 32768
#define GEMM_SMEM (STAGES * G_STAGE)

__device__ __forceinline__ uint32_t sw(uint32_t row, uint32_t chunk) {
    return (row << 6) + (((chunk ^ (row >> 1)) & 3u) << 4);
}

__global__ void __launch_bounds__(256, 1) gemm_fp16x2(
        const fp16* __restrict__ Ahi, const fp16* __restrict__ Alo,
        const fp16* __restrict__ B,
        float* __restrict__ C, const float* __restrict__ R,
        fp16* __restrict__ Ohi, fp16* __restrict__ Olo,
        const float* __restrict__ Gate, int mode,
        int M, int N, int K) {
    extern __shared__ __align__(128) char smem_raw[];
    const uint32_t smem_u = (uint32_t)__cvta_generic_to_shared(smem_raw);
    const int tid  = threadIdx.x;
    const int warp = tid >> 5;
    const int lane = tid & 31;
    const int wm   = warp & 1;       // 2 warps along M (64 rows each)
    const int wn   = warp >> 1;      // 4 warps along N (64 cols each)

    int bx, by;
    {
        int tiles_n = gridDim.x, tiles_m = gridDim.y;
        int lin = blockIdx.y * tiles_n + blockIdx.x;
        int per = 8 * tiles_n;
        int gid = lin / per, rem = lin % per;
        int gm  = tiles_m - gid * 8;
        if (gm > 8) gm = 8;
        by = gid * 8 + rem % gm;
        bx = rem / gm;
    }
    const int bm = by * 128;
    const int bn = bx * 256;

    float acc[4][8][4];
    #pragma unroll
    for (int i = 0; i < 4; i++)
        #pragma unroll
        for (int j = 0; j < 8; j++)
            #pragma unroll
            for (int v = 0; v < 4; v++) acc[i][j][v] = 0.f;

    const int kiters = K >> 5;

    auto load_stage = [&](int stage, int kt) {
        const uint32_t sbase = smem_u + stage * G_STAGE;
        #pragma unroll
        for (int rep = 0; rep < 2; rep++) {          // A hi+lo: 128 rows x 4 chunks
            int idx = tid + rep * 256;
            int row = idx >> 2;
            int ch  = idx & 3;
            size_t go = (size_t)(bm + row) * K + kt + ch * 8;
            uint32_t so = sw(row, ch);
            cp16(sbase + G_AHI + so, Ahi + go);
            cp16(sbase + G_ALO + so, Alo + go);
        }
        #pragma unroll
        for (int rep = 0; rep < 4; rep++) {          // B: 256 rows x 4 chunks
            int idx = tid + rep * 256;
            int row = idx >> 2;
            int ch  = idx & 3;
            size_t go = (size_t)(bn + row) * K + kt + ch * 8;
            cp16(sbase + G_B + sw(row, ch), B + go);
        }
    };

    #pragma unroll
    for (int s = 0; s < STAGES - 1; s++) {
        load_stage(s, s * 32);
        asm volatile("cp.async.commit_group;\n");
    }

    for (int it = 0; it < kiters; ++it) {
        asm volatile("cp.async.wait_group %0;\n" :: "n"(STAGES - 2));
        __syncthreads();
        int pf = it + STAGES - 1;
        if (pf < kiters) load_stage(pf % STAGES, pf * 32);
        asm volatile("cp.async.commit_group;\n");

        const uint32_t sb = smem_u + (it % STAGES) * G_STAGE;

        #pragma unroll
        for (int kf = 0; kf < 2; kf++) {
            uint32_t ah[4][4], al[4][4];
            #pragma unroll
            for (int mt = 0; mt < 4; mt++) {
                uint32_t row = wm * 64 + mt * 16 + (lane & 15);
                uint32_t ch  = kf * 2 + (lane >> 4);
                uint32_t off = sw(row, ch);
                ldm4(ah[mt], sb + G_AHI + off);
                ldm4(al[mt], sb + G_ALO + off);
            }
            #pragma unroll
            for (int p = 0; p < 4; p++) {            // covers nt = 2p, 2p+1
                uint32_t rowb = wn * 64 + p * 16 + (lane & 7) + ((lane >> 4) & 1) * 8;
                uint32_t chb  = kf * 2 + ((lane >> 3) & 1);
                uint32_t bfr[4];
                ldm4(bfr, sb + G_B + sw(rowb, chb));
                // per-acc order: hi*B then lo*B
                #pragma unroll
                for (int mt = 0; mt < 4; mt++) {
                    mma16816h(acc[mt][2 * p],     ah[mt], bfr);
                    mma16816h(acc[mt][2 * p + 1], ah[mt], bfr + 2);
                }
                #pragma unroll
                for (int mt = 0; mt < 4; mt++) {
                    mma16816h(acc[mt][2 * p],     al[mt], bfr);
                    mma16816h(acc[mt][2 * p + 1], al[mt], bfr + 2);
                }
            }
        }
    }

    // ---- epilogue ----
    const int rb = bm + wm * 64;
    const int cb = bn + wn * 64;
    #pragma unroll
    for (int mt = 0; mt < 4; mt++)
        #pragma unroll
        for (int nt = 0; nt < 8; nt++) {
            int r0 = rb + mt * 16 + (lane >> 2);
            int c  = cb + nt * 8 + (lane & 3) * 2;
            size_t i0 = (size_t)r0 * N + c;
            size_t i1 = (size_t)(r0 + 8) * N + c;
            if (mode == 0) {
                float2 v0 = make_float2(acc[mt][nt][0], acc[mt][nt][1]);
                float2 v1 = make_float2(acc[mt][nt][2], acc[mt][nt][3]);
                if (R) {
                    float2 q0 = *(const float2*)(R + i0);
                    float2 q1 = *(const float2*)(R + i1);
                    v0.x += q0.x; v0.y += q0.y;
                    v1.x += q1.x; v1.y += q1.y;
                }
                *(float2*)(C + i0) = v0;
                *(float2*)(C + i1) = v1;
            } else {
                float2 g0 = *(const float2*)(Gate + i0);
                float2 g1 = *(const float2*)(Gate + i1);
                float r00 = g0.x / (1.f + expf(-g0.x)) * acc[mt][nt][0];
                float r01 = g0.y / (1.f + expf(-g0.y)) * acc[mt][nt][1];
                float r10 = g1.x / (1.f + expf(-g1.x)) * acc[mt][nt][2];
                float r11 = g1.y / (1.f + expf(-g1.y)) * acc[mt][nt][3];
                fp16 a, b, e, f;
                split2h(r00, a, e); split2h(r01, b, f);
                *(uint32_t*)(Ohi + i0) = pack_h2(a, b);
                *(uint32_t*)(Olo + i0) = pack_h2(e, f);
                split2h(r10, a, e); split2h(r11, b, f);
                *(uint32_t*)(Ohi + i1) = pack_h2(a, b);
                *(uint32_t*)(Olo + i1) = pack_h2(e, f);
            }
        }
}

// ---------------- RoPE + split: fp32 q/k -> rotated split bf16 (attention) ----------------
__global__ void rope_split_kernel(const float* __restrict__ q, const float* __restrict__ k,
                                  const float2* __restrict__ tab,
                                  bf16* __restrict__ qhi, bf16* __restrict__ qlo,
                                  bf16* __restrict__ khi, bf16* __restrict__ klo) {
    const int total = Tn * (NH + NKV) * 64;
    int idx = blockIdx.x * blockDim.x + threadIdx.x;
    if (idx >= total) return;
    int i    = idx & 63;
    int rest = idx >> 6;
    int head = rest % (NH + NKV);
    int t    = rest / (NH + NKV);
    float2 cs = tab[t * 64 + i];
    float c = cs.x, s = cs.y;
    if (head < NH) {
        size_t off = (size_t)t * Cn + head * HD + 2 * i;
        float2 ab = *(const float2*)(q + off);
        float a = ab.x, b = ab.y;
        float r0 = fmaf(a, c, -b * s);
        float r1 = fmaf(a, s,  b * c);
        split2(r0, qhi[off], qlo[off]);
        split2(r1, qhi[off + 1], qlo[off + 1]);
    } else {
        size_t off = (size_t)t * (NKV * HD) + (head - NH) * HD + 2 * i;
        float2 ab = *(const float2*)(k + off);
        float a = ab.x, b = ab.y;
        float r0 = fmaf(a, c, -b * s);
        float r1 = fmaf(a, s,  b * c);
        split2(r0, khi[off], klo[off]);
        split2(r1, khi[off + 1], klo[off + 1]);
    }
}

// =====================================================================
// Tensor-core causal flash attention (bf16 split x3) — y output fp16 split
// =====================================================================
#define AQ_HI 0
#define AQ_LO 32768
#define AKV   65536
#define AKV_STAGE 65536
#define AK_LO 16384
#define AV_HI 32768
#define AV_LO 49152
#define ATTN_SMEM (AKV + 2 * AKV_STAGE)

__device__ __forceinline__ uint32_t sw256(uint32_t row, uint32_t ch) {
    return (row << 8) + ((((ch ^ row) & 7u) | (ch & 8u)) << 4);
}

__global__ void __launch_bounds__(256, 1) attn_tc(
        const bf16* __restrict__ qhi, const bf16* __restrict__ qlo,
        const bf16* __restrict__ khi, const bf16* __restrict__ klo,
        const bf16* __restrict__ vhi, const bf16* __restrict__ vlo,
        fp16* __restrict__ yhi, fp16* __restrict__ ylo) {
    extern __shared__ __align__(128) char smem_raw[];
    const uint32_t sb = (uint32_t)__cvta_generic_to_shared(smem_raw);
    const int qt   = 31 - blockIdx.x;
    const int head = blockIdx.y;
    const int kvh  = head >> 2;
    const int qb   = qt * 128;
    const int tid  = threadIdx.x;
    const int warp = tid >> 5;
    const int lane = tid & 31;
    const int njt  = 2 * qt + 2;

    #pragma unroll
    for (int i = 0; i < 8; i++) {
        int idx = tid + i * 256;
        int row = idx >> 4;
        int ch  = idx & 15;
        size_t g = (size_t)(qb + row) * Cn + head * HD + ch * 8;
        uint32_t off = sw256(row, ch);
        cp16(sb + AQ_HI + off, qhi + g);
        cp16(sb + AQ_LO + off, qlo + g);
    }

    auto load_kv = [&](int jt, int buf) {
        const uint32_t base = sb + AKV + buf * AKV_STAGE;
        #pragma unroll
        for (int i = 0; i < 4; i++) {
            int idx = tid + i * 256;
            int row = idx >> 4;
            int ch  = idx & 15;
            size_t g = (size_t)(jt * 64 + row) * (NKV * HD) + kvh * HD + ch * 8;
            uint32_t off = sw256(row, ch);
            cp16(base + off,          khi + g);
            cp16(base + AK_LO + off,  klo + g);
            cp16(base + AV_HI + off,  vhi + g);
            cp16(base + AV_LO + off,  vlo + g);
        }
    };

    load_kv(0, 0);
    asm volatile("cp.async.commit_group;\n");

    float m0 = -1e30f, m1 = -1e30f, l0 = 0.f, l1 = 0.f;
    float o[16][4];
    #pragma unroll
    for (int nt = 0; nt < 16; nt++)
        #pragma unroll
        for (int e = 0; e < 4; e++) o[nt][e] = 0.f;

    const float cs = 0.12751743621340608f;      // log2(e)/sqrt(128)
    const int r0g = qb + (warp << 4) + (lane >> 2);
    const int r1g = r0g + 8;

    for (int jt = 0; jt < njt; jt++) {
        if (jt + 1 < njt) load_kv(jt + 1, (jt + 1) & 1);
        asm volatile("cp.async.commit_group;\n");
        asm volatile("cp.async.wait_group 1;\n");
        __syncthreads();

        const uint32_t kb   = sb + AKV + (jt & 1) * AKV_STAGE;
        const uint32_t kbl  = kb + AK_LO;
        const uint32_t vb   = kb + AV_HI;
        const uint32_t vbl  = kb + AV_LO;

        float sacc[8][4];
        #pragma unroll
        for (int nt = 0; nt < 8; nt++)
            #pragma unroll
            for (int e = 0; e < 4; e++) sacc[nt][e] = 0.f;

        #pragma unroll
        for (int ks = 0; ks < 8; ks++) {
            uint32_t ah[4], al[4];
            {
                uint32_t row = (warp << 4) + (lane & 15);
                uint32_t ch  = ks * 2 + (lane >> 4);
                uint32_t off = sw256(row, ch);
                ldm4(ah, sb + AQ_HI + off);
                ldm4(al, sb + AQ_LO + off);
            }
            uint32_t bh[8][2], bl[8][2];
            #pragma unroll
            for (int p = 0; p < 4; p++) {
                uint32_t rowb = p * 16 + (lane & 7) + ((lane >> 4) & 1) * 8;
                uint32_t chb  = ks * 2 + ((lane >> 3) & 1);
                uint32_t offb = sw256(rowb, chb);
                uint32_t r[4];
                ldm4(r, kb + offb);
                bh[2 * p][0] = r[0]; bh[2 * p][1] = r[1];
                bh[2 * p + 1][0] = r[2]; bh[2 * p + 1][1] = r[3];
                ldm4(r, kbl + offb);
                bl[2 * p][0] = r[0]; bl[2 * p][1] = r[1];
                bl[2 * p + 1][0] = r[2]; bl[2 * p + 1][1] = r[3];
            }
            #pragma unroll
            for (int nt = 0; nt < 8; nt++) mma16816(sacc[nt], ah, bh[nt]);
            #pragma unroll
            for (int nt = 0; nt < 8; nt++) mma16816(sacc[nt], ah, bl[nt]);
            #pragma unroll
            for (int nt = 0; nt < 8; nt++) mma16816(sacc[nt], al, bh[nt]);
        }

        const bool domask = (jt >= 2 * qt);
        #pragma unroll
        for (int nt = 0; nt < 8; nt++) {
            int cbase = jt * 64 + nt * 8 + (lane & 3) * 2;
            #pragma unroll
            for (int e = 0; e < 4; e++) {
                float v = sacc[nt][e] * cs;
                if (domask) {
                    int col = cbase + (e & 1);
                    int row = (e < 2) ? r0g : r1g;
                    if (col > row) v = -1e30f;
                }
                sacc[nt][e] = v;
            }
        }

        float mx0 = -1e30f, mx1 = -1e30f;
        #pragma unroll
        for (int nt = 0; nt < 8; nt++) {
            mx0 = fmaxf(mx0, fmaxf(sacc[nt][0], sacc[nt][1]));
            mx1 = fmaxf(mx1, fmaxf(sacc[nt][2], sacc[nt][3]));
        }
        mx0 = fmaxf(mx0, __shfl_xor_sync(0xffffffffu, mx0, 1));
        mx0 = fmaxf(mx0, __shfl_xor_sync(0xffffffffu, mx0, 2));
        mx1 = fmaxf(mx1, __shfl_xor_sync(0xffffffffu, mx1, 1));
        mx1 = fmaxf(mx1, __shfl_xor_sync(0xffffffffu, mx1, 2));
        float mn0 = fmaxf(m0, mx0);
        float mn1 = fmaxf(m1, mx1);

        float ls0 = 0.f, ls1 = 0.f;
        #pragma unroll
        for (int nt = 0; nt < 8; nt++) {
            float p0 = exp2f(sacc[nt][0] - mn0);
            float p1 = exp2f(sacc[nt][1] - mn0);
            float p2 = exp2f(sacc[nt][2] - mn1);
            float p3 = exp2f(sacc[nt][3] - mn1);
            ls0 += p0 + p1;
            ls1 += p2 + p3;
            sacc[nt][0] = p0; sacc[nt][1] = p1; sacc[nt][2] = p2; sacc[nt][3] = p3;
        }
        ls0 += __shfl_xor_sync(0xffffffffu, ls0, 1);
        ls0 += __shfl_xor_sync(0xffffffffu, ls0, 2);
        ls1 += __shfl_xor_sync(0xffffffffu, ls1, 1);
        ls1 += __shfl_xor_sync(0xffffffffu, ls1, 2);

        float a0 = exp2f(m0 - mn0);
        float a1 = exp2f(m1 - mn1);
        m0 = mn0; m1 = mn1;
        l0 = l0 * a0 + ls0;
        l1 = l1 * a1 + ls1;
        #pragma unroll
        for (int nt = 0; nt < 16; nt++) {
            o[nt][0] *= a0; o[nt][1] *= a0;
            o[nt][2] *= a1; o[nt][3] *= a1;
        }

        #pragma unroll
        for (int ks = 0; ks < 4; ks++) {
            bf16 h0, q0, h1, q1, h2, q2, h3, q3;
            uint32_t ah[4], al[4];
            split2(sacc[2 * ks][0], h0, q0); split2(sacc[2 * ks][1], h1, q1);
            ah[0] = pack_bf2(h0, h1); al[0] = pack_bf2(q0, q1);
            split2(sacc[2 * ks][2], h0, q0); split2(sacc[2 * ks][3], h1, q1);
            ah[1] = pack_bf2(h0, h1); al[1] = pack_bf2(q0, q1);
            split2(sacc[2 * ks + 1][0], h2, q2); split2(sacc[2 * ks + 1][1], h3, q3);
            ah[2] = pack_bf2(h2, h3); al[2] = pack_bf2(q2, q3);
            split2(sacc[2 * ks + 1][2], h2, q2); split2(sacc[2 * ks + 1][3], h3, q3);
            ah[3] = pack_bf2(h2, h3); al[3] = pack_bf2(q2, q3);

            #pragma unroll
            for (int dq = 0; dq < 4; dq++) {
                uint32_t row = ks * 16 + (lane & 15);
                uint32_t ch0 = (2 * dq) * 2 + (lane >> 4);
                uint32_t ch1 = (2 * dq + 1) * 2 + (lane >> 4);
                uint32_t bh0[4], bl0[4], bh1[4], bl1[4];
                ldm4t(bh0, vb + sw256(row, ch0));
                ldm4t(bl0, vbl + sw256(row, ch0));
                ldm4t(bh1, vb + sw256(row, ch1));
                ldm4t(bl1, vbl + sw256(row, ch1));
                float* o0 = o[4 * dq + 0];
                float* o1 = o[4 * dq + 1];
                float* o2 = o[4 * dq + 2];
                float* o3 = o[4 * dq + 3];
                mma16816(o0, ah, bh0);     mma16816(o1, ah, bh0 + 2);
                mma16816(o2, ah, bh1);     mma16816(o3, ah, bh1 + 2);
                mma16816(o0, al, bh0);     mma16816(o1, al, bh0 + 2);
                mma16816(o2, al, bh1);     mma16816(o3, al, bh1 + 2);
                mma16816(o0, ah, bl0);     mma16816(o1, ah, bl0 + 2);
                mma16816(o2, ah, bl1);     mma16816(o3, ah, bl1 + 2);
            }
        }
        __syncthreads();
    }

    float inv0 = 1.0f / l0;
    float inv1 = 1.0f / l1;
    #pragma unroll
    for (int nt = 0; nt < 16; nt++) {
        int c = head * HD + nt * 8 + (lane & 3) * 2;
        size_t i0 = (size_t)r0g * Cn + c;
        size_t i1 = (size_t)r1g * Cn + c;
        fp16 a, b, e, f;
        split2h(o[nt][0] * inv0, a, e);
        split2h(o[nt][1] * inv0, b, f);
        *(uint32_t*)(yhi + i0) = pack_h2(a, b);
        *(uint32_t*)(ylo + i0) = pack_h2(e, f);
        split2h(o[nt][2] * inv1, a, e);
        split2h(o[nt][3] * inv1, b, f);
        *(uint32_t*)(yhi + i1) = pack_h2(a, b);
        *(uint32_t*)(ylo + i1) = pack_h2(e, f);
    }
}

// ---------------- launch ----------------
extern "C" void kernel_launch(void* const* d_in, const int* in_sizes, int n_in,
                              void* d_out, int out_size) {
    (void)in_sizes; (void)n_in; (void)out_size;
    const float* x           = (const float*)d_in[0];
    const float* attn_norm_w = (const float*)d_in[2];
    const float* wq          = (const float*)d_in[3];
    const float* wk          = (const float*)d_in[4];
    const float* wv          = (const float*)d_in[5];
    const float* wo          = (const float*)d_in[6];
    const float* ffn_norm_w  = (const float*)d_in[7];
    const float* w_gate      = (const float*)d_in[8];
    const float* w_up        = (const float*)d_in[9];
    const float* w_down      = (const float*)d_in[10];
    float* out = (float*)d_out;

    float *q, *k, *v, *g;
    float2* rtab;
    fp16 *h_hi, *h_lo, *h2_hi, *h2_lo, *y_hi, *y_lo, *gs_hi, *gs_lo;
    bf16 *qhi, *qlo, *khi, *klo, *vhi, *vlo;
    fp16 *wq_h, *wk_h, *wv_h, *wo_h, *wg_h, *wu_h, *wd_h;

    cudaGetSymbolAddress((void**)&q,  g_q);
    cudaGetSymbolAddress((void**)&k,  g_k);
    cudaGetSymbolAddress((void**)&v,  g_v);
    cudaGetSymbolAddress((void**)&g,  g_g);
    cudaGetSymbolAddress((void**)&rtab, g_rope);
    cudaGetSymbolAddress((void**)&h_hi,  g_h_hi);  cudaGetSymbolAddress((void**)&h_lo,  g_h_lo);
    cudaGetSymbolAddress((void**)&h2_hi, g_h2_hi); cudaGetSymbolAddress((void**)&h2_lo, g_h2_lo);
    cudaGetSymbolAddress((void**)&y_hi,  g_y_hi);  cudaGetSymbolAddress((void**)&y_lo,  g_y_lo);
    cudaGetSymbolAddress((void**)&gs_hi, g_gs_hi); cudaGetSymbolAddress((void**)&gs_lo, g_gs_lo);
    cudaGetSymbolAddress((void**)&qhi, g_qhi); cudaGetSymbolAddress((void**)&qlo, g_qlo);
    cudaGetSymbolAddress((void**)&khi, g_khi); cudaGetSymbolAddress((void**)&klo, g_klo);
    cudaGetSymbolAddress((void**)&vhi, g_vhi); cudaGetSymbolAddress((void**)&vlo, g_vlo);
    cudaGetSymbolAddress((void**)&wq_h, g_wq_h);
    cudaGetSymbolAddress((void**)&wk_h, g_wk_h);
    cudaGetSymbolAddress((void**)&wv_h, g_wv_h);
    cudaGetSymbolAddress((void**)&wo_h, g_wo_h);
    cudaGetSymbolAddress((void**)&wg_h, g_wg_h);
    cudaGetSymbolAddress((void**)&wu_h, g_wu_h);
    cudaGetSymbolAddress((void**)&wd_h, g_wd_h);

    cudaFuncSetAttribute(gemm_fp16x2, cudaFuncAttributeMaxDynamicSharedMemorySize, GEMM_SMEM);
    cudaFuncSetAttribute(attn_tc, cudaFuncAttributeMaxDynamicSharedMemorySize, ATTN_SMEM);

    #define CONVW(src, dst, n) \
        convert_w_kernel<<<((n) / 8 + 255) / 256, 256>>>(src, dst, n)
    #define GEMM0(A_hi, A_lo, Bw, Cp, Rp, Mm, Nn, Kk) \
        gemm_fp16x2<<<dim3((Nn) / 256, (Mm) / 128), 256, GEMM_SMEM>>>( \
            A_hi, A_lo, Bw, Cp, Rp, nullptr, nullptr, nullptr, 0, Mm, Nn, Kk)

    rope_table_kernel<<<(Tn * 64 + 255) / 256, 256>>>(rtab);
    rmsnorm_kernel<<<Tn, 256>>>(x, attn_norm_w, h_hi, h_lo);
    CONVW(wq, wq_h, Cn * Cn);
    CONVW(wk, wk_h, NKV * HD * Cn);
    CONVW(wv, wv_h, NKV * HD * Cn);
    // Q/K/V projections (fp32 outputs for RoPE)
    GEMM0(h_hi, h_lo, wq_h, q, nullptr, Tn, Cn, Cn);
    GEMM0(h_hi, h_lo, wk_h, k, nullptr, Tn, NKV * HD, Cn);
    GEMM0(h_hi, h_lo, wv_h, v, nullptr, Tn, NKV * HD, Cn);
    // RoPE + split q/k (bf16), split v (bf16)
    {
        int total = Tn * (NH + NKV) * 64;
        rope_split_kernel<<<(total + 255) / 256, 256>>>(q, k, rtab, qhi, qlo, khi, klo);
        convert_bf_kernel<<<((Tn * NKV * HD) / 8 + 255) / 256, 256>>>(v, vhi, vlo, Tn * NKV * HD);
    }
    // attention -> y fp16 split
    attn_tc<<<dim3(32, NH), 256, ATTN_SMEM>>>(qhi, qlo, khi, klo, vhi, vlo, y_hi, y_lo);
    // out = x + y @ wo^T
    CONVW(wo, wo_h, Cn * Cn);
    GEMM0(y_hi, y_lo, wo_h, out, x, Tn, Cn, Cn);
    // rmsnorm2 -> fp16 split
    rmsnorm_kernel<<<Tn, 256>>>(out, ffn_norm_w, h2_hi, h2_lo);
    // gate (fp32) then up (fused silu epilogue -> fp16 split)
    CONVW(w_gate, wg_h, FFN * Cn);
    CONVW(w_up,   wu_h, FFN * Cn);
    GEMM0(h2_hi, h2_lo, wg_h, g, nullptr, Tn, FFN, Cn);
    gemm_fp16x2<<<dim3(FFN / 256, Tn / 128), 256, GEMM_SMEM>>>(
        h2_hi, h2_lo, wu_h, nullptr, nullptr, gs_hi, gs_lo, g, 1, Tn, FFN, Cn);
    // out += gs @ w_down^T
    CONVW(w_down, wd_h, Cn * FFN);
    GEMM0(gs_hi, gs_lo, wd_h, out, out, Tn, Cn, FFN);

    #undef CONVW
    #undef GEMM0
}

// round 12
// speedup vs baseline: 4.6862x; 1.0634x over previous
#include <cuda_runtime.h>
#include <cuda_bf16.h>
#include <cuda_fp16.h>
#include <math.h>
#include <stdint.h>

#define Tn   4096
#define Cn   2048
#define NH   16
#define NKV  4
#define HD   128
#define FFN  8192

typedef __nv_bfloat16 bf16;
typedef __half fp16;

// ---------------- scratch (static device globals; no allocation) ----------------
static __device__ float2 g_rope[Tn * 64];

// GEMM activations: fp16 split
static __device__ fp16 g_h_hi [Tn * Cn],  g_h_lo [Tn * Cn];
static __device__ fp16 g_h2_hi[Tn * Cn],  g_h2_lo[Tn * Cn];
static __device__ fp16 g_y_hi [Tn * Cn],  g_y_lo [Tn * Cn];
static __device__ fp16 g_gs_hi[Tn * FFN], g_gs_lo[Tn * FFN];

// attention operands: bf16 split
static __device__ bf16 g_qhi[Tn * Cn],       g_qlo[Tn * Cn];
static __device__ bf16 g_khi[Tn * NKV * HD], g_klo[Tn * NKV * HD];
static __device__ bf16 g_vhi[Tn * NKV * HD], g_vlo[Tn * NKV * HD];

// GEMM weights: single fp16
static __device__ fp16 g_wqkv_h[(Cn + 2 * NKV * HD) * Cn];  // rows: 0..2047 wq, 2048..2559 wk, 2560..3071 wv
static __device__ fp16 g_wo_h[Cn * Cn];
static __device__ fp16 g_wgu_h[2 * FFN * Cn];               // interleaved: row 2j = wg[j], 2j+1 = wu[j]
static __device__ fp16 g_wd_h[Cn * FFN];

__device__ __forceinline__ void split2(float x, bf16& hi, bf16& lo) {
    hi = __float2bfloat16(x);
    lo = __float2bfloat16(x - __bfloat162float(hi));
}
__device__ __forceinline__ void split2h(float x, fp16& hi, fp16& lo) {
    hi = __float2half(x);
    lo = __float2half(x - __half2float(hi));
}
__device__ __forceinline__ uint32_t pack_bf2(bf16 a, bf16 b) {
    __nv_bfloat162 t; t.x = a; t.y = b;
    return *reinterpret_cast<uint32_t*>(&t);
}
__device__ __forceinline__ uint32_t pack_h2(fp16 a, fp16 b) {
    __half2 t; t.x = a; t.y = b;
    return *reinterpret_cast<uint32_t*>(&t);
}

// ---------------- common PTX helpers ----------------
__device__ __forceinline__ void cp16(uint32_t dst, const void* src) {
    asm volatile("cp.async.cg.shared.global [%0], [%1], 16;\n" :: "r"(dst), "l"(src));
}
__device__ __forceinline__ void ldm4(uint32_t* r, uint32_t addr) {
    asm volatile("ldmatrix.sync.aligned.m8n8.x4.shared.b16 {%0,%1,%2,%3}, [%4];\n"
                 : "=r"(r[0]), "=r"(r[1]), "=r"(r[2]), "=r"(r[3]) : "r"(addr));
}
__device__ __forceinline__ void ldm4t(uint32_t* r, uint32_t addr) {
    asm volatile("ldmatrix.sync.aligned.m8n8.x4.trans.shared.b16 {%0,%1,%2,%3}, [%4];\n"
                 : "=r"(r[0]), "=r"(r[1]), "=r"(r[2]), "=r"(r[3]) : "r"(addr));
}
__device__ __forceinline__ void mma16816(float* c, const uint32_t* a, const uint32_t* b) {
    asm volatile("mma.sync.aligned.m16n8k16.row.col.f32.bf16.bf16.f32 "
                 "{%0,%1,%2,%3},{%4,%5,%6,%7},{%8,%9},{%0,%1,%2,%3};\n"
                 : "+f"(c[0]), "+f"(c[1]), "+f"(c[2]), "+f"(c[3])
                 : "r"(a[0]), "r"(a[1]), "r"(a[2]), "r"(a[3]), "r"(b[0]), "r"(b[1]));
}
__device__ __forceinline__ void mma16816h(float* c, const uint32_t* a, const uint32_t* b) {
    asm volatile("mma.sync.aligned.m16n8k16.row.col.f32.f16.f16.f32 "
                 "{%0,%1,%2,%3},{%4,%5,%6,%7},{%8,%9},{%0,%1,%2,%3};\n"
                 : "+f"(c[0]), "+f"(c[1]), "+f"(c[2]), "+f"(c[3])
                 : "r"(a[0]), "r"(a[1]), "r"(a[2]), "r"(a[3]), "r"(b[0]), "r"(b[1]));
}

// ---------------- weight fp32 -> single fp16 (8 elems/thread) ----------------
__global__ void convert_w_kernel(const float* __restrict__ w, fp16* __restrict__ o, int n) {
    int i = (blockIdx.x * blockDim.x + threadIdx.x) * 8;
    if (i >= n) return;
    float4 a = *(const float4*)(w + i);
    float4 b = *(const float4*)(w + i + 4);
    uint4 p;
    p.x = pack_h2(__float2half(a.x), __float2half(a.y));
    p.y = pack_h2(__float2half(a.z), __float2half(a.w));
    p.z = pack_h2(__float2half(b.x), __float2half(b.y));
    p.w = pack_h2(__float2half(b.z), __float2half(b.w));
    *(uint4*)(o + i) = p;
}

// ---------------- weight fp32 -> fp16 with row interleave (dst row = 2*row + off) ----------------
__global__ void convert_w_pair_kernel(const float* __restrict__ w, fp16* __restrict__ o,
                                      int n, int off) {
    int i = (blockIdx.x * blockDim.x + threadIdx.x) * 8;
    if (i >= n) return;
    int row = i / Cn;
    int col = i - row * Cn;           // Cn % 8 == 0, so all 8 elems in one row
    size_t di = (size_t)(2 * row + off) * Cn + col;
    float4 a = *(const float4*)(w + i);
    float4 b = *(const float4*)(w + i + 4);
    uint4 p;
    p.x = pack_h2(__float2half(a.x), __float2half(a.y));
    p.y = pack_h2(__float2half(a.z), __float2half(a.w));
    p.z = pack_h2(__float2half(b.x), __float2half(b.y));
    p.w = pack_h2(__float2half(b.z), __float2half(b.w));
    *(uint4*)(o + di) = p;
}

// ---------------- RoPE cos/sin table (double sincos — fast-math immune) ----------------
__global__ void rope_table_kernel(float2* __restrict__ tab) {
    int idx = blockIdx.x * blockDim.x + threadIdx.x;
    if (idx >= Tn * 64) return;
    int i = idx & 63;
    int t = idx >> 6;
    double invf_d = pow(500000.0, -((double)(2 * i) / 128.0));
    float  invf_f = (float)invf_d;
    float  ang_f  = (float)t * invf_f;
    double c, s;
    sincos((double)ang_f, &s, &c);
    tab[idx] = make_float2((float)c, (float)s);
}

// ---------------- rmsnorm: one block per row, writes split fp16 ----------------
__global__ void __launch_bounds__(256) rmsnorm_kernel(const float* __restrict__ x,
                                                      const float* __restrict__ w,
                                                      fp16* __restrict__ ohi,
                                                      fp16* __restrict__ olo) {
    const int row = blockIdx.x;
    const float* xr = x + (size_t)row * Cn;
    float s = 0.f;
    for (int i = threadIdx.x; i < Cn; i += 256) {
        float v = xr[i];
        s = fmaf(v, v, s);
    }
    __shared__ float red[8];
    #pragma unroll
    for (int o = 16; o; o >>= 1) s += __shfl_xor_sync(0xffffffffu, s, o);
    if ((threadIdx.x & 31) == 0) red[threadIdx.x >> 5] = s;
    __syncthreads();
    if (threadIdx.x < 32) {
        float v = (threadIdx.x < 8) ? red[threadIdx.x] : 0.f;
        #pragma unroll
        for (int o = 4; o; o >>= 1) v += __shfl_xor_sync(0xffffffffu, v, o);
        if (threadIdx.x == 0) red[0] = v;
    }
    __syncthreads();
    const float scale = rsqrtf(red[0] * (1.0f / Cn) + 1e-5f);
    size_t base = (size_t)row * Cn;
    for (int i = threadIdx.x; i < Cn; i += 256) {
        float v = xr[i] * scale * w[i];
        split2h(v, ohi[base + i], olo[base + i]);
    }
}

// =====================================================================
// fp16x2 tensor-core GEMM: A = Ahi+Alo (fp16 split), B single fp16.
// 128(M) x 256(N), warp 64x64, BK=32, 4-stage cp.async, CTA swizzle.
// mode 0: C = acc (+R)
// mode 2: QKV epilogue — RoPE (q/k) or plain (v) -> split bf16 buffers
// mode 3: gate/up interleaved — silu(acc_even)*acc_odd -> split fp16
// =====================================================================
#define STAGES 4
#define G_AHI 0
#define G_ALO 8192
#define G_B   16384
#define G_STAGE 32768
#define GEMM_SMEM (STAGES * G_STAGE)

__device__ __forceinline__ uint32_t sw(uint32_t row, uint32_t chunk) {
    return (row << 6) + (((chunk ^ (row >> 1)) & 3u) << 4);
}

__global__ void __launch_bounds__(256, 1) gemm_fp16x2(
        const fp16* __restrict__ Ahi, const fp16* __restrict__ Alo,
        const fp16* __restrict__ B,
        float* __restrict__ C, const float* __restrict__ R,
        fp16* __restrict__ Ohi, fp16* __restrict__ Olo,
        const float2* __restrict__ tab,
        bf16* __restrict__ Qh, bf16* __restrict__ Ql,
        bf16* __restrict__ Kh, bf16* __restrict__ Kl,
        bf16* __restrict__ Vh, bf16* __restrict__ Vl,
        int mode, int M, int N, int K) {
    extern __shared__ __align__(128) char smem_raw[];
    const uint32_t smem_u = (uint32_t)__cvta_generic_to_shared(smem_raw);
    const int tid  = threadIdx.x;
    const int warp = tid >> 5;
    const int lane = tid & 31;
    const int wm   = warp & 1;
    const int wn   = warp >> 1;

    int bx, by;
    {
        int tiles_n = gridDim.x, tiles_m = gridDim.y;
        int lin = blockIdx.y * tiles_n + blockIdx.x;
        int per = 8 * tiles_n;
        int gid = lin / per, rem = lin % per;
        int gm  = tiles_m - gid * 8;
        if (gm > 8) gm = 8;
        by = gid * 8 + rem % gm;
        bx = rem / gm;
    }
    const int bm = by * 128;
    const int bn = bx * 256;

    float acc[4][8][4];
    #pragma unroll
    for (int i = 0; i < 4; i++)
        #pragma unroll
        for (int j = 0; j < 8; j++)
            #pragma unroll
            for (int v = 0; v < 4; v++) acc[i][j][v] = 0.f;

    const int kiters = K >> 5;

    auto load_stage = [&](int stage, int kt) {
        const uint32_t sbase = smem_u + stage * G_STAGE;
        #pragma unroll
        for (int rep = 0; rep < 2; rep++) {
            int idx = tid + rep * 256;
            int row = idx >> 2;
            int ch  = idx & 3;
            size_t go = (size_t)(bm + row) * K + kt + ch * 8;
            uint32_t so = sw(row, ch);
            cp16(sbase + G_AHI + so, Ahi + go);
            cp16(sbase + G_ALO + so, Alo + go);
        }
        #pragma unroll
        for (int rep = 0; rep < 4; rep++) {
            int idx = tid + rep * 256;
            int row = idx >> 2;
            int ch  = idx & 3;
            size_t go = (size_t)(bn + row) * K + kt + ch * 8;
            cp16(sbase + G_B + sw(row, ch), B + go);
        }
    };

    #pragma unroll
    for (int s = 0; s < STAGES - 1; s++) {
        load_stage(s, s * 32);
        asm volatile("cp.async.commit_group;\n");
    }

    for (int it = 0; it < kiters; ++it) {
        asm volatile("cp.async.wait_group %0;\n" :: "n"(STAGES - 2));
        __syncthreads();
        int pf = it + STAGES - 1;
        if (pf < kiters) load_stage(pf % STAGES, pf * 32);
        asm volatile("cp.async.commit_group;\n");

        const uint32_t sb = smem_u + (it % STAGES) * G_STAGE;

        #pragma unroll
        for (int kf = 0; kf < 2; kf++) {
            uint32_t ah[4][4], al[4][4];
            #pragma unroll
            for (int mt = 0; mt < 4; mt++) {
                uint32_t row = wm * 64 + mt * 16 + (lane & 15);
                uint32_t ch  = kf * 2 + (lane >> 4);
                uint32_t off = sw(row, ch);
                ldm4(ah[mt], sb + G_AHI + off);
                ldm4(al[mt], sb + G_ALO + off);
            }
            #pragma unroll
            for (int p = 0; p < 4; p++) {
                uint32_t rowb = wn * 64 + p * 16 + (lane & 7) + ((lane >> 4) & 1) * 8;
                uint32_t chb  = kf * 2 + ((lane >> 3) & 1);
                uint32_t bfr[4];
                ldm4(bfr, sb + G_B + sw(rowb, chb));
                #pragma unroll
                for (int mt = 0; mt < 4; mt++) {
                    mma16816h(acc[mt][2 * p],     ah[mt], bfr);
                    mma16816h(acc[mt][2 * p + 1], ah[mt], bfr + 2);
                }
                #pragma unroll
                for (int mt = 0; mt < 4; mt++) {
                    mma16816h(acc[mt][2 * p],     al[mt], bfr);
                    mma16816h(acc[mt][2 * p + 1], al[mt], bfr + 2);
                }
            }
        }
    }

    // ---- epilogue ----
    const int rb = bm + wm * 64;
    const int cb = bn + wn * 64;
    #pragma unroll
    for (int mt = 0; mt < 4; mt++)
        #pragma unroll
        for (int nt = 0; nt < 8; nt++) {
            int r0 = rb + mt * 16 + (lane >> 2);
            int r1 = r0 + 8;
            int c  = cb + nt * 8 + (lane & 3) * 2;   // even global col
            if (mode == 0) {
                size_t i0 = (size_t)r0 * N + c;
                size_t i1 = (size_t)r1 * N + c;
                float2 v0 = make_float2(acc[mt][nt][0], acc[mt][nt][1]);
                float2 v1 = make_float2(acc[mt][nt][2], acc[mt][nt][3]);
                if (R) {
                    float2 q0 = *(const float2*)(R + i0);
                    float2 q1 = *(const float2*)(R + i1);
                    v0.x += q0.x; v0.y += q0.y;
                    v1.x += q1.x; v1.y += q1.y;
                }
                *(float2*)(C + i0) = v0;
                *(float2*)(C + i1) = v1;
            } else if (mode == 2) {
                // QKV: cols [0,2048) q (rope), [2048,2560) k (rope), [2560,3072) v (split only)
                if (bn < 2048) {
                    int i = (c & 127) >> 1;
                    float2 cs0 = tab[(size_t)r0 * 64 + i];
                    float2 cs1 = tab[(size_t)r1 * 64 + i];
                    float a0 = acc[mt][nt][0], b0 = acc[mt][nt][1];
                    float a1 = acc[mt][nt][2], b1 = acc[mt][nt][3];
                    float x0 = fmaf(a0, cs0.x, -b0 * cs0.y);
                    float y0 = fmaf(a0, cs0.y,  b0 * cs0.x);
                    float x1 = fmaf(a1, cs1.x, -b1 * cs1.y);
                    float y1 = fmaf(a1, cs1.y,  b1 * cs1.x);
                    bf16 h0, l0, h1, l1;
                    size_t i0 = (size_t)r0 * Cn + c;
                    size_t i1 = (size_t)r1 * Cn + c;
                    split2(x0, h0, l0); split2(y0, h1, l1);
                    *(uint32_t*)(Qh + i0) = pack_bf2(h0, h1);
                    *(uint32_t*)(Ql + i0) = pack_bf2(l0, l1);
                    split2(x1, h0, l0); split2(y1, h1, l1);
                    *(uint32_t*)(Qh + i1) = pack_bf2(h0, h1);
                    *(uint32_t*)(Ql + i1) = pack_bf2(l0, l1);
                } else if (bn < 2560) {
                    int ck = c - 2048;
                    int i = (ck & 127) >> 1;
                    float2 cs0 = tab[(size_t)r0 * 64 + i];
                    float2 cs1 = tab[(size_t)r1 * 64 + i];
                    float a0 = acc[mt][nt][0], b0 = acc[mt][nt][1];
                    float a1 = acc[mt][nt][2], b1 = acc[mt][nt][3];
                    float x0 = fmaf(a0, cs0.x, -b0 * cs0.y);
                    float y0 = fmaf(a0, cs0.y,  b0 * cs0.x);
                    float x1 = fmaf(a1, cs1.x, -b1 * cs1.y);
                    float y1 = fmaf(a1, cs1.y,  b1 * cs1.x);
                    bf16 h0, l0, h1, l1;
                    size_t i0 = (size_t)r0 * (NKV * HD) + ck;
                    size_t i1 = (size_t)r1 * (NKV * HD) + ck;
                    split2(x0, h0, l0); split2(y0, h1, l1);
                    *(uint32_t*)(Kh + i0) = pack_bf2(h0, h1);
                    *(uint32_t*)(Kl + i0) = pack_bf2(l0, l1);
                    split2(x1, h0, l0); split2(y1, h1, l1);
                    *(uint32_t*)(Kh + i1) = pack_bf2(h0, h1);
                    *(uint32_t*)(Kl + i1) = pack_bf2(l0, l1);
                } else {
                    int cv = c - 2560;
                    bf16 h0, l0, h1, l1;
                    size_t i0 = (size_t)r0 * (NKV * HD) + cv;
                    size_t i1 = (size_t)r1 * (NKV * HD) + cv;
                    split2(acc[mt][nt][0], h0, l0); split2(acc[mt][nt][1], h1, l1);
                    *(uint32_t*)(Vh + i0) = pack_bf2(h0, h1);
                    *(uint32_t*)(Vl + i0) = pack_bf2(l0, l1);
                    split2(acc[mt][nt][2], h0, l0); split2(acc[mt][nt][3], h1, l1);
                    *(uint32_t*)(Vh + i1) = pack_bf2(h0, h1);
                    *(uint32_t*)(Vl + i1) = pack_bf2(l0, l1);
                }
            } else {
                // mode 3: acc[0]=gate, acc[1]=up (col c even = gate_{c/2})
                int gcol = c >> 1;
                float ga0 = acc[mt][nt][0], up0 = acc[mt][nt][1];
                float ga1 = acc[mt][nt][2], up1 = acc[mt][nt][3];
                float v0 = ga0 / (1.f + expf(-ga0)) * up0;
                float v1 = ga1 / (1.f + expf(-ga1)) * up1;
                fp16 h, l;
                size_t i0 = (size_t)r0 * FFN + gcol;
                size_t i1 = (size_t)r1 * FFN + gcol;
                split2h(v0, h, l);
                Ohi[i0] = h; Olo[i0] = l;
                split2h(v1, h, l);
                Ohi[i1] = h; Olo[i1] = l;
            }
        }
}

// =====================================================================
// Tensor-core causal flash attention (bf16 split x3) — y output fp16 split
// =====================================================================
#define AQ_HI 0
#define AQ_LO 32768
#define AKV   65536
#define AKV_STAGE 65536
#define AK_LO 16384
#define AV_HI 32768
#define AV_LO 49152
#define ATTN_SMEM (AKV + 2 * AKV_STAGE)

__device__ __forceinline__ uint32_t sw256(uint32_t row, uint32_t ch) {
    return (row << 8) + ((((ch ^ row) & 7u) | (ch & 8u)) << 4);
}

__global__ void __launch_bounds__(256, 1) attn_tc(
        const bf16* __restrict__ qhi, const bf16* __restrict__ qlo,
        const bf16* __restrict__ khi, const bf16* __restrict__ klo,
        const bf16* __restrict__ vhi, const bf16* __restrict__ vlo,
        fp16* __restrict__ yhi, fp16* __restrict__ ylo) {
    extern __shared__ __align__(128) char smem_raw[];
    const uint32_t sb = (uint32_t)__cvta_generic_to_shared(smem_raw);
    const int qt   = 31 - blockIdx.x;
    const int head = blockIdx.y;
    const int kvh  = head >> 2;
    const int qb   = qt * 128;
    const int tid  = threadIdx.x;
    const int warp = tid >> 5;
    const int lane = tid & 31;
    const int njt  = 2 * qt + 2;

    #pragma unroll
    for (int i = 0; i < 8; i++) {
        int idx = tid + i * 256;
        int row = idx >> 4;
        int ch  = idx & 15;
        size_t g = (size_t)(qb + row) * Cn + head * HD + ch * 8;
        uint32_t off = sw256(row, ch);
        cp16(sb + AQ_HI + off, qhi + g);
        cp16(sb + AQ_LO + off, qlo + g);
    }

    auto load_kv = [&](int jt, int buf) {
        const uint32_t base = sb + AKV + buf * AKV_STAGE;
        #pragma unroll
        for (int i = 0; i < 4; i++) {
            int idx = tid + i * 256;
            int row = idx >> 4;
            int ch  = idx & 15;
            size_t g = (size_t)(jt * 64 + row) * (NKV * HD) + kvh * HD + ch * 8;
            uint32_t off = sw256(row, ch);
            cp16(base + off,          khi + g);
            cp16(base + AK_LO + off,  klo + g);
            cp16(base + AV_HI + off,  vhi + g);
            cp16(base + AV_LO + off,  vlo + g);
        }
    };

    load_kv(0, 0);
    asm volatile("cp.async.commit_group;\n");

    float m0 = -1e30f, m1 = -1e30f, l0 = 0.f, l1 = 0.f;
    float o[16][4];
    #pragma unroll
    for (int nt = 0; nt < 16; nt++)
        #pragma unroll
        for (int e = 0; e < 4; e++) o[nt][e] = 0.f;

    const float cs = 0.12751743621340608f;      // log2(e)/sqrt(128)
    const int r0g = qb + (warp << 4) + (lane >> 2);
    const int r1g = r0g + 8;

    for (int jt = 0; jt < njt; jt++) {
        if (jt + 1 < njt) load_kv(jt + 1, (jt + 1) & 1);
        asm volatile("cp.async.commit_group;\n");
        asm volatile("cp.async.wait_group 1;\n");
        __syncthreads();

        const uint32_t kb   = sb + AKV + (jt & 1) * AKV_STAGE;
        const uint32_t kbl  = kb + AK_LO;
        const uint32_t vb   = kb + AV_HI;
        const uint32_t vbl  = kb + AV_LO;

        float sacc[8][4];
        #pragma unroll
        for (int nt = 0; nt < 8; nt++)
            #pragma unroll
            for (int e = 0; e < 4; e++) sacc[nt][e] = 0.f;

        #pragma unroll
        for (int ks = 0; ks < 8; ks++) {
            uint32_t ah[4], al[4];
            {
                uint32_t row = (warp << 4) + (lane & 15);
                uint32_t ch  = ks * 2 + (lane >> 4);
                uint32_t off = sw256(row, ch);
                ldm4(ah, sb + AQ_HI + off);
                ldm4(al, sb + AQ_LO + off);
            }
            uint32_t bh[8][2], bl[8][2];
            #pragma unroll
            for (int p = 0; p < 4; p++) {
                uint32_t rowb = p * 16 + (lane & 7) + ((lane >> 4) & 1) * 8;
                uint32_t chb  = ks * 2 + ((lane >> 3) & 1);
                uint32_t offb = sw256(rowb, chb);
                uint32_t r[4];
                ldm4(r, kb + offb);
                bh[2 * p][0] = r[0]; bh[2 * p][1] = r[1];
                bh[2 * p + 1][0] = r[2]; bh[2 * p + 1][1] = r[3];
                ldm4(r, kbl + offb);
                bl[2 * p][0] = r[0]; bl[2 * p][1] = r[1];
                bl[2 * p + 1][0] = r[2]; bl[2 * p + 1][1] = r[3];
            }
            #pragma unroll
            for (int nt = 0; nt < 8; nt++) mma16816(sacc[nt], ah, bh[nt]);
            #pragma unroll
            for (int nt = 0; nt < 8; nt++) mma16816(sacc[nt], ah, bl[nt]);
            #pragma unroll
            for (int nt = 0; nt < 8; nt++) mma16816(sacc[nt], al, bh[nt]);
        }

        const bool domask = (jt >= 2 * qt);
        #pragma unroll
        for (int nt = 0; nt < 8; nt++) {
            int cbase = jt * 64 + nt * 8 + (lane & 3) * 2;
            #pragma unroll
            for (int e = 0; e < 4; e++) {
                float v = sacc[nt][e] * cs;
                if (domask) {
                    int col = cbase + (e & 1);
                    int row = (e < 2) ? r0g : r1g;
                    if (col > row) v = -1e30f;
                }
                sacc[nt][e] = v;
            }
        }

        float mx0 = -1e30f, mx1 = -1e30f;
        #pragma unroll
        for (int nt = 0; nt < 8; nt++) {
            mx0 = fmaxf(mx0, fmaxf(sacc[nt][0], sacc[nt][1]));
            mx1 = fmaxf(mx1, fmaxf(sacc[nt][2], sacc[nt][3]));
        }
        mx0 = fmaxf(mx0, __shfl_xor_sync(0xffffffffu, mx0, 1));
        mx0 = fmaxf(mx0, __shfl_xor_sync(0xffffffffu, mx0, 2));
        mx1 = fmaxf(mx1, __shfl_xor_sync(0xffffffffu, mx1, 1));
        mx1 = fmaxf(mx1, __shfl_xor_sync(0xffffffffu, mx1, 2));
        float mn0 = fmaxf(m0, mx0);
        float mn1 = fmaxf(m1, mx1);

        float ls0 = 0.f, ls1 = 0.f;
        #pragma unroll
        for (int nt = 0; nt < 8; nt++) {
            float p0 = exp2f(sacc[nt][0] - mn0);
            float p1 = exp2f(sacc[nt][1] - mn0);
            float p2 = exp2f(sacc[nt][2] - mn1);
            float p3 = exp2f(sacc[nt][3] - mn1);
            ls0 += p0 + p1;
            ls1 += p2 + p3;
            sacc[nt][0] = p0; sacc[nt][1] = p1; sacc[nt][2] = p2; sacc[nt][3] = p3;
        }
        ls0 += __shfl_xor_sync(0xffffffffu, ls0, 1);
        ls0 += __shfl_xor_sync(0xffffffffu, ls0, 2);
        ls1 += __shfl_xor_sync(0xffffffffu, ls1, 1);
        ls1 += __shfl_xor_sync(0xffffffffu, ls1, 2);

        float a0 = exp2f(m0 - mn0);
        float a1 = exp2f(m1 - mn1);
        m0 = mn0; m1 = mn1;
        l0 = l0 * a0 + ls0;
        l1 = l1 * a1 + ls1;
        #pragma unroll
        for (int nt = 0; nt < 16; nt++) {
            o[nt][0] *= a0; o[nt][1] *= a0;
            o[nt][2] *= a1; o[nt][3] *= a1;
        }

        #pragma unroll
        for (int ks = 0; ks < 4; ks++) {
            bf16 h0, q0, h1, q1, h2, q2, h3, q3;
            uint32_t ah[4], al[4];
            split2(sacc[2 * ks][0], h0, q0); split2(sacc[2 * ks][1], h1, q1);
            ah[0] = pack_bf2(h0, h1); al[0] = pack_bf2(q0, q1);
            split2(sacc[2 * ks][2], h0, q0); split2(sacc[2 * ks][3], h1, q1);
            ah[1] = pack_bf2(h0, h1); al[1] = pack_bf2(q0, q1);
            split2(sacc[2 * ks + 1][0], h2, q2); split2(sacc[2 * ks + 1][1], h3, q3);
            ah[2] = pack_bf2(h2, h3); al[2] = pack_bf2(q2, q3);
            split2(sacc[2 * ks + 1][2], h2, q2); split2(sacc[2 * ks + 1][3], h3, q3);
            ah[3] = pack_bf2(h2, h3); al[3] = pack_bf2(q2, q3);

            #pragma unroll
            for (int dq = 0; dq < 4; dq++) {
                uint32_t row = ks * 16 + (lane & 15);
                uint32_t ch0 = (2 * dq) * 2 + (lane >> 4);
                uint32_t ch1 = (2 * dq + 1) * 2 + (lane >> 4);
                uint32_t bh0[4], bl0[4], bh1[4], bl1[4];
                ldm4t(bh0, vb + sw256(row, ch0));
                ldm4t(bl0, vbl + sw256(row, ch0));
                ldm4t(bh1, vb + sw256(row, ch1));
                ldm4t(bl1, vbl + sw256(row, ch1));
                float* o0 = o[4 * dq + 0];
                float* o1 = o[4 * dq + 1];
                float* o2 = o[4 * dq + 2];
                float* o3 = o[4 * dq + 3];
                mma16816(o0, ah, bh0);     mma16816(o1, ah, bh0 + 2);
                mma16816(o2, ah, bh1);     mma16816(o3, ah, bh1 + 2);
                mma16816(o0, al, bh0);     mma16816(o1, al, bh0 + 2);
                mma16816(o2, al, bh1);     mma16816(o3, al, bh1 + 2);
                mma16816(o0, ah, bl0);     mma16816(o1, ah, bl0 + 2);
                mma16816(o2, ah, bl1);     mma16816(o3, ah, bl1 + 2);
            }
        }
        __syncthreads();
    }

    float inv0 = 1.0f / l0;
    float inv1 = 1.0f / l1;
    #pragma unroll
    for (int nt = 0; nt < 16; nt++) {
        int c = head * HD + nt * 8 + (lane & 3) * 2;
        size_t i0 = (size_t)r0g * Cn + c;
        size_t i1 = (size_t)r1g * Cn + c;
        fp16 a, b, e, f;
        split2h(o[nt][0] * inv0, a, e);
        split2h(o[nt][1] * inv0, b, f);
        *(uint32_t*)(yhi + i0) = pack_h2(a, b);
        *(uint32_t*)(ylo + i0) = pack_h2(e, f);
        split2h(o[nt][2] * inv1, a, e);
        split2h(o[nt][3] * inv1, b, f);
        *(uint32_t*)(yhi + i1) = pack_h2(a, b);
        *(uint32_t*)(ylo + i1) = pack_h2(e, f);
    }
}

// ---------------- launch ----------------
extern "C" void kernel_launch(void* const* d_in, const int* in_sizes, int n_in,
                              void* d_out, int out_size) {
    (void)in_sizes; (void)n_in; (void)out_size;
    const float* x           = (const float*)d_in[0];
    const float* attn_norm_w = (const float*)d_in[2];
    const float* wq          = (const float*)d_in[3];
    const float* wk          = (const float*)d_in[4];
    const float* wv          = (const float*)d_in[5];
    const float* wo          = (const float*)d_in[6];
    const float* ffn_norm_w  = (const float*)d_in[7];
    const float* w_gate      = (const float*)d_in[8];
    const float* w_up        = (const float*)d_in[9];
    const float* w_down      = (const float*)d_in[10];
    float* out = (float*)d_out;

    float2* rtab;
    fp16 *h_hi, *h_lo, *h2_hi, *h2_lo, *y_hi, *y_lo, *gs_hi, *gs_lo;
    bf16 *qhi, *qlo, *khi, *klo, *vhi, *vlo;
    fp16 *wqkv_h, *wo_h, *wgu_h, *wd_h;

    cudaGetSymbolAddress((void**)&rtab, g_rope);
    cudaGetSymbolAddress((void**)&h_hi,  g_h_hi);  cudaGetSymbolAddress((void**)&h_lo,  g_h_lo);
    cudaGetSymbolAddress((void**)&h2_hi, g_h2_hi); cudaGetSymbolAddress((void**)&h2_lo, g_h2_lo);
    cudaGetSymbolAddress((void**)&y_hi,  g_y_hi);  cudaGetSymbolAddress((void**)&y_lo,  g_y_lo);
    cudaGetSymbolAddress((void**)&gs_hi, g_gs_hi); cudaGetSymbolAddress((void**)&gs_lo, g_gs_lo);
    cudaGetSymbolAddress((void**)&qhi, g_qhi); cudaGetSymbolAddress((void**)&qlo, g_qlo);
    cudaGetSymbolAddress((void**)&khi, g_khi); cudaGetSymbolAddress((void**)&klo, g_klo);
    cudaGetSymbolAddress((void**)&vhi, g_vhi); cudaGetSymbolAddress((void**)&vlo, g_vlo);
    cudaGetSymbolAddress((void**)&wqkv_h, g_wqkv_h);
    cudaGetSymbolAddress((void**)&wo_h, g_wo_h);
    cudaGetSymbolAddress((void**)&wgu_h, g_wgu_h);
    cudaGetSymbolAddress((void**)&wd_h, g_wd_h);

    cudaFuncSetAttribute(gemm_fp16x2, cudaFuncAttributeMaxDynamicSharedMemorySize, GEMM_SMEM);
    cudaFuncSetAttribute(attn_tc, cudaFuncAttributeMaxDynamicSharedMemorySize, ATTN_SMEM);

    #define CONVW(src, dst, n) \
        convert_w_kernel<<<((n) / 8 + 255) / 256, 256>>>(src, dst, n)
    #define GEMM0(A_hi, A_lo, Bw, Cp, Rp, Mm, Nn, Kk) \
        gemm_fp16x2<<<dim3((Nn) / 256, (Mm) / 128), 256, GEMM_SMEM>>>( \
            A_hi, A_lo, Bw, Cp, Rp, nullptr, nullptr, nullptr, \
            nullptr, nullptr, nullptr, nullptr, nullptr, nullptr, 0, Mm, Nn, Kk)

    rope_table_kernel<<<(Tn * 64 + 255) / 256, 256>>>(rtab);
    rmsnorm_kernel<<<Tn, 256>>>(x, attn_norm_w, h_hi, h_lo);
    // QKV weights concatenated: rows [0,2048) wq, [2048,2560) wk, [2560,3072) wv
    CONVW(wq, wqkv_h, Cn * Cn);
    CONVW(wk, wqkv_h + (size_t)Cn * Cn, NKV * HD * Cn);
    CONVW(wv, wqkv_h + (size_t)(Cn + NKV * HD) * Cn, NKV * HD * Cn);
    // merged QKV GEMM with RoPE/split epilogue -> q/k/v bf16 split buffers
    gemm_fp16x2<<<dim3((Cn + 2 * NKV * HD) / 256, Tn / 128), 256, GEMM_SMEM>>>(
        h_hi, h_lo, wqkv_h, nullptr, nullptr, nullptr, nullptr,
        rtab, qhi, qlo, khi, klo, vhi, vlo, 2, Tn, Cn + 2 * NKV * HD, Cn);
    // attention -> y fp16 split
    attn_tc<<<dim3(32, NH), 256, ATTN_SMEM>>>(qhi, qlo, khi, klo, vhi, vlo, y_hi, y_lo);
    // out = x + y @ wo^T
    CONVW(wo, wo_h, Cn * Cn);
    GEMM0(y_hi, y_lo, wo_h, out, x, Tn, Cn, Cn);
    // rmsnorm2 -> fp16 split
    rmsnorm_kernel<<<Tn, 256>>>(out, ffn_norm_w, h2_hi, h2_lo);
    // gate/up interleaved weights; fused silu(gate)*up GEMM -> gs fp16 split
    convert_w_pair_kernel<<<((FFN * Cn) / 8 + 255) / 256, 256>>>(w_gate, wgu_h, FFN * Cn, 0);
    convert_w_pair_kernel<<<((FFN * Cn) / 8 + 255) / 256, 256>>>(w_up,   wgu_h, FFN * Cn, 1);
    gemm_fp16x2<<<dim3((2 * FFN) / 256, Tn / 128), 256, GEMM_SMEM>>>(
        h2_hi, h2_lo, wgu_h, nullptr, nullptr, gs_hi, gs_lo,
        nullptr, nullptr, nullptr, nullptr, nullptr, nullptr, nullptr, 3, Tn, 2 * FFN, Cn);
    // out += gs @ w_down^T
    CONVW(w_down, wd_h, Cn * FFN);
    GEMM0(gs_hi, gs_lo, wd_h, out, out, Tn, Cn, FFN);

    #undef CONVW
    #undef GEMM0
}

// round 13
// speedup vs baseline: 6.9859x; 1.4907x over previous
#include <cuda_runtime.h>
#include <cuda_bf16.h>
#include <cuda_fp16.h>
#include <math.h>
#include <stdint.h>

#define Tn   4096
#define Cn   2048
#define NH   16
#define NKV  4
#define HD   128
#define FFN  8192

typedef __nv_bfloat16 bf16;
typedef __half fp16;

// ---------------- scratch (static device globals; no allocation) ----------------
static __device__ float2 g_rope[Tn * 64];

// GEMM activations: single fp16
static __device__ fp16 g_h  [Tn * Cn];
static __device__ fp16 g_h2 [Tn * Cn];
static __device__ fp16 g_y  [Tn * Cn];
static __device__ fp16 g_gs [Tn * FFN];

// attention operands: bf16 split (proven x3 path)
static __device__ bf16 g_qhi[Tn * Cn],       g_qlo[Tn * Cn];
static __device__ bf16 g_khi[Tn * NKV * HD], g_klo[Tn * NKV * HD];
static __device__ bf16 g_vhi[Tn * NKV * HD], g_vlo[Tn * NKV * HD];

// GEMM weights: single fp16
static __device__ fp16 g_wqkv_h[(Cn + 2 * NKV * HD) * Cn];  // rows: wq | wk | wv
static __device__ fp16 g_wo_h[Cn * Cn];
static __device__ fp16 g_wgu_h[2 * FFN * Cn];               // interleaved: 2j = wg[j], 2j+1 = wu[j]
static __device__ fp16 g_wd_h[Cn * FFN];

__device__ __forceinline__ void split2(float x, bf16& hi, bf16& lo) {
    hi = __float2bfloat16(x);
    lo = __float2bfloat16(x - __bfloat162float(hi));
}
__device__ __forceinline__ uint32_t pack_bf2(bf16 a, bf16 b) {
    __nv_bfloat162 t; t.x = a; t.y = b;
    return *reinterpret_cast<uint32_t*>(&t);
}
__device__ __forceinline__ uint32_t pack_h2(fp16 a, fp16 b) {
    __half2 t; t.x = a; t.y = b;
    return *reinterpret_cast<uint32_t*>(&t);
}

// ---------------- common PTX helpers ----------------
__device__ __forceinline__ void cp16(uint32_t dst, const void* src) {
    asm volatile("cp.async.cg.shared.global [%0], [%1], 16;\n" :: "r"(dst), "l"(src));
}
__device__ __forceinline__ void ldm4(uint32_t* r, uint32_t addr) {
    asm volatile("ldmatrix.sync.aligned.m8n8.x4.shared.b16 {%0,%1,%2,%3}, [%4];\n"
                 : "=r"(r[0]), "=r"(r[1]), "=r"(r[2]), "=r"(r[3]) : "r"(addr));
}
__device__ __forceinline__ void ldm4t(uint32_t* r, uint32_t addr) {
    asm volatile("ldmatrix.sync.aligned.m8n8.x4.trans.shared.b16 {%0,%1,%2,%3}, [%4];\n"
                 : "=r"(r[0]), "=r"(r[1]), "=r"(r[2]), "=r"(r[3]) : "r"(addr));
}
__device__ __forceinline__ void mma16816(float* c, const uint32_t* a, const uint32_t* b) {
    asm volatile("mma.sync.aligned.m16n8k16.row.col.f32.bf16.bf16.f32 "
                 "{%0,%1,%2,%3},{%4,%5,%6,%7},{%8,%9},{%0,%1,%2,%3};\n"
                 : "+f"(c[0]), "+f"(c[1]), "+f"(c[2]), "+f"(c[3])
                 : "r"(a[0]), "r"(a[1]), "r"(a[2]), "r"(a[3]), "r"(b[0]), "r"(b[1]));
}
__device__ __forceinline__ void mma16816h(float* c, const uint32_t* a, const uint32_t* b) {
    asm volatile("mma.sync.aligned.m16n8k16.row.col.f32.f16.f16.f32 "
                 "{%0,%1,%2,%3},{%4,%5,%6,%7},{%8,%9},{%0,%1,%2,%3};\n"
                 : "+f"(c[0]), "+f"(c[1]), "+f"(c[2]), "+f"(c[3])
                 : "r"(a[0]), "r"(a[1]), "r"(a[2]), "r"(a[3]), "r"(b[0]), "r"(b[1]));
}

// ---------------- weight fp32 -> single fp16 (8 elems/thread) ----------------
__global__ void convert_w_kernel(const float* __restrict__ w, fp16* __restrict__ o, int n) {
    int i = (blockIdx.x * blockDim.x + threadIdx.x) * 8;
    if (i >= n) return;
    float4 a = *(const float4*)(w + i);
    float4 b = *(const float4*)(w + i + 4);
    uint4 p;
    p.x = pack_h2(__float2half(a.x), __float2half(a.y));
    p.y = pack_h2(__float2half(a.z), __float2half(a.w));
    p.z = pack_h2(__float2half(b.x), __float2half(b.y));
    p.w = pack_h2(__float2half(b.z), __float2half(b.w));
    *(uint4*)(o + i) = p;
}

// ---------------- weight fp32 -> fp16 with row interleave (dst row = 2*row + off) ----------------
__global__ void convert_w_pair_kernel(const float* __restrict__ w, fp16* __restrict__ o,
                                      int n, int off) {
    int i = (blockIdx.x * blockDim.x + threadIdx.x) * 8;
    if (i >= n) return;
    int row = i / Cn;
    int col = i - row * Cn;
    size_t di = (size_t)(2 * row + off) * Cn + col;
    float4 a = *(const float4*)(w + i);
    float4 b = *(const float4*)(w + i + 4);
    uint4 p;
    p.x = pack_h2(__float2half(a.x), __float2half(a.y));
    p.y = pack_h2(__float2half(a.z), __float2half(a.w));
    p.z = pack_h2(__float2half(b.x), __float2half(b.y));
    p.w = pack_h2(__float2half(b.z), __float2half(b.w));
    *(uint4*)(o + di) = p;
}

// ---------------- RoPE cos/sin table (double sincos — fast-math immune) ----------------
__global__ void rope_table_kernel(float2* __restrict__ tab) {
    int idx = blockIdx.x * blockDim.x + threadIdx.x;
    if (idx >= Tn * 64) return;
    int i = idx & 63;
    int t = idx >> 6;
    double invf_d = pow(500000.0, -((double)(2 * i) / 128.0));
    float  invf_f = (float)invf_d;
    float  ang_f  = (float)t * invf_f;
    double c, s;
    sincos((double)ang_f, &s, &c);
    tab[idx] = make_float2((float)c, (float)s);
}

// ---------------- rmsnorm: one block per row, writes single fp16 ----------------
__global__ void __launch_bounds__(256) rmsnorm_kernel(const float* __restrict__ x,
                                                      const float* __restrict__ w,
                                                      fp16* __restrict__ o) {
    const int row = blockIdx.x;
    const float* xr = x + (size_t)row * Cn;
    float s = 0.f;
    for (int i = threadIdx.x; i < Cn; i += 256) {
        float v = xr[i];
        s = fmaf(v, v, s);
    }
    __shared__ float red[8];
    #pragma unroll
    for (int o2 = 16; o2; o2 >>= 1) s += __shfl_xor_sync(0xffffffffu, s, o2);
    if ((threadIdx.x & 31) == 0) red[threadIdx.x >> 5] = s;
    __syncthreads();
    if (threadIdx.x < 32) {
        float v = (threadIdx.x < 8) ? red[threadIdx.x] : 0.f;
        #pragma unroll
        for (int o2 = 4; o2; o2 >>= 1) v += __shfl_xor_sync(0xffffffffu, v, o2);
        if (threadIdx.x == 0) red[0] = v;
    }
    __syncthreads();
    const float scale = rsqrtf(red[0] * (1.0f / Cn) + 1e-5f);
    size_t base = (size_t)row * Cn;
    for (int i = threadIdx.x; i < Cn; i += 256)
        o[base + i] = __float2half(xr[i] * scale * w[i]);
}

// =====================================================================
// fp16 tensor-core GEMM: A single fp16, B single fp16, fp32 accumulate.
// 128(M) x 256(N), warp 64x64, BK=32, 5-stage cp.async, CTA swizzle.
// mode 0: C = acc (+R)
// mode 2: QKV epilogue — RoPE (q/k) or plain (v) -> split bf16 buffers
// mode 3: gate/up interleaved — silu(acc_even)*acc_odd -> single fp16
// =====================================================================
#define STAGES 5
#define G_A   0
#define G_B   8192
#define G_STAGE 24576
#define GEMM_SMEM (STAGES * G_STAGE)

__device__ __forceinline__ uint32_t sw(uint32_t row, uint32_t chunk) {
    return (row << 6) + (((chunk ^ (row >> 1)) & 3u) << 4);
}

__global__ void __launch_bounds__(256, 1) gemm_fp16(
        const fp16* __restrict__ A, const fp16* __restrict__ B,
        float* __restrict__ C, const float* __restrict__ R,
        fp16* __restrict__ O,
        const float2* __restrict__ tab,
        bf16* __restrict__ Qh, bf16* __restrict__ Ql,
        bf16* __restrict__ Kh, bf16* __restrict__ Kl,
        bf16* __restrict__ Vh, bf16* __restrict__ Vl,
        int mode, int M, int N, int K) {
    extern __shared__ __align__(128) char smem_raw[];
    const uint32_t smem_u = (uint32_t)__cvta_generic_to_shared(smem_raw);
    const int tid  = threadIdx.x;
    const int warp = tid >> 5;
    const int lane = tid & 31;
    const int wm   = warp & 1;
    const int wn   = warp >> 1;

    int bx, by;
    {
        int tiles_n = gridDim.x, tiles_m = gridDim.y;
        int lin = blockIdx.y * tiles_n + blockIdx.x;
        int per = 8 * tiles_n;
        int gid = lin / per, rem = lin % per;
        int gm  = tiles_m - gid * 8;
        if (gm > 8) gm = 8;
        by = gid * 8 + rem % gm;
        bx = rem / gm;
    }
    const int bm = by * 128;
    const int bn = bx * 256;

    float acc[4][8][4];
    #pragma unroll
    for (int i = 0; i < 4; i++)
        #pragma unroll
        for (int j = 0; j < 8; j++)
            #pragma unroll
            for (int v = 0; v < 4; v++) acc[i][j][v] = 0.f;

    const int kiters = K >> 5;

    auto load_stage = [&](int stage, int kt) {
        const uint32_t sbase = smem_u + stage * G_STAGE;
        #pragma unroll
        for (int rep = 0; rep < 2; rep++) {          // A: 128 rows x 4 chunks
            int idx = tid + rep * 256;
            int row = idx >> 2;
            int ch  = idx & 3;
            size_t go = (size_t)(bm + row) * K + kt + ch * 8;
            cp16(sbase + G_A + sw(row, ch), A + go);
        }
        #pragma unroll
        for (int rep = 0; rep < 4; rep++) {          // B: 256 rows x 4 chunks
            int idx = tid + rep * 256;
            int row = idx >> 2;
            int ch  = idx & 3;
            size_t go = (size_t)(bn + row) * K + kt + ch * 8;
            cp16(sbase + G_B + sw(row, ch), B + go);
        }
    };

    #pragma unroll
    for (int s = 0; s < STAGES - 1; s++) {
        load_stage(s, s * 32);
        asm volatile("cp.async.commit_group;\n");
    }

    for (int it = 0; it < kiters; ++it) {
        asm volatile("cp.async.wait_group %0;\n" :: "n"(STAGES - 2));
        __syncthreads();
        int pf = it + STAGES - 1;
        if (pf < kiters) load_stage(pf % STAGES, pf * 32);
        asm volatile("cp.async.commit_group;\n");

        const uint32_t sb = smem_u + (it % STAGES) * G_STAGE;

        #pragma unroll
        for (int kf = 0; kf < 2; kf++) {
            uint32_t ah[4][4];
            #pragma unroll
            for (int mt = 0; mt < 4; mt++) {
                uint32_t row = wm * 64 + mt * 16 + (lane & 15);
                uint32_t ch  = kf * 2 + (lane >> 4);
                ldm4(ah[mt], sb + G_A + sw(row, ch));
            }
            #pragma unroll
            for (int p = 0; p < 4; p++) {            // covers nt = 2p, 2p+1
                uint32_t rowb = wn * 64 + p * 16 + (lane & 7) + ((lane >> 4) & 1) * 8;
                uint32_t chb  = kf * 2 + ((lane >> 3) & 1);
                uint32_t bfr[4];
                ldm4(bfr, sb + G_B + sw(rowb, chb));
                #pragma unroll
                for (int mt = 0; mt < 4; mt++) {
                    mma16816h(acc[mt][2 * p],     ah[mt], bfr);
                    mma16816h(acc[mt][2 * p + 1], ah[mt], bfr + 2);
                }
            }
        }
    }

    // ---- epilogue ----
    const int rb = bm + wm * 64;
    const int cb = bn + wn * 64;
    #pragma unroll
    for (int mt = 0; mt < 4; mt++)
        #pragma unroll
        for (int nt = 0; nt < 8; nt++) {
            int r0 = rb + mt * 16 + (lane >> 2);
            int r1 = r0 + 8;
            int c  = cb + nt * 8 + (lane & 3) * 2;   // even global col
            if (mode == 0) {
                size_t i0 = (size_t)r0 * N + c;
                size_t i1 = (size_t)r1 * N + c;
                float2 v0 = make_float2(acc[mt][nt][0], acc[mt][nt][1]);
                float2 v1 = make_float2(acc[mt][nt][2], acc[mt][nt][3]);
                if (R) {
                    float2 q0 = *(const float2*)(R + i0);
                    float2 q1 = *(const float2*)(R + i1);
                    v0.x += q0.x; v0.y += q0.y;
                    v1.x += q1.x; v1.y += q1.y;
                }
                *(float2*)(C + i0) = v0;
                *(float2*)(C + i1) = v1;
            } else if (mode == 2) {
                // QKV: cols [0,2048) q (rope), [2048,2560) k (rope), [2560,3072) v
                if (bn < 2048) {
                    int i = (c & 127) >> 1;
                    float2 cs0 = tab[(size_t)r0 * 64 + i];
                    float2 cs1 = tab[(size_t)r1 * 64 + i];
                    float a0 = acc[mt][nt][0], b0 = acc[mt][nt][1];
                    float a1 = acc[mt][nt][2], b1 = acc[mt][nt][3];
                    float x0 = fmaf(a0, cs0.x, -b0 * cs0.y);
                    float y0 = fmaf(a0, cs0.y,  b0 * cs0.x);
                    float x1 = fmaf(a1, cs1.x, -b1 * cs1.y);
                    float y1 = fmaf(a1, cs1.y,  b1 * cs1.x);
                    bf16 h0, l0, h1, l1;
                    size_t i0 = (size_t)r0 * Cn + c;
                    size_t i1 = (size_t)r1 * Cn + c;
                    split2(x0, h0, l0); split2(y0, h1, l1);
                    *(uint32_t*)(Qh + i0) = pack_bf2(h0, h1);
                    *(uint32_t*)(Ql + i0) = pack_bf2(l0, l1);
                    split2(x1, h0, l0); split2(y1, h1, l1);
                    *(uint32_t*)(Qh + i1) = pack_bf2(h0, h1);
                    *(uint32_t*)(Ql + i1) = pack_bf2(l0, l1);
                } else if (bn < 2560) {
                    int ck = c - 2048;
                    int i = (ck & 127) >> 1;
                    float2 cs0 = tab[(size_t)r0 * 64 + i];
                    float2 cs1 = tab[(size_t)r1 * 64 + i];
                    float a0 = acc[mt][nt][0], b0 = acc[mt][nt][1];
                    float a1 = acc[mt][nt][2], b1 = acc[mt][nt][3];
                    float x0 = fmaf(a0, cs0.x, -b0 * cs0.y);
                    float y0 = fmaf(a0, cs0.y,  b0 * cs0.x);
                    float x1 = fmaf(a1, cs1.x, -b1 * cs1.y);
                    float y1 = fmaf(a1, cs1.y,  b1 * cs1.x);
                    bf16 h0, l0, h1, l1;
                    size_t i0 = (size_t)r0 * (NKV * HD) + ck;
                    size_t i1 = (size_t)r1 * (NKV * HD) + ck;
                    split2(x0, h0, l0); split2(y0, h1, l1);
                    *(uint32_t*)(Kh + i0) = pack_bf2(h0, h1);
                    *(uint32_t*)(Kl + i0) = pack_bf2(l0, l1);
                    split2(x1, h0, l0); split2(y1, h1, l1);
                    *(uint32_t*)(Kh + i1) = pack_bf2(h0, h1);
                    *(uint32_t*)(Kl + i1) = pack_bf2(l0, l1);
                } else {
                    int cv = c - 2560;
                    bf16 h0, l0, h1, l1;
                    size_t i0 = (size_t)r0 * (NKV * HD) + cv;
                    size_t i1 = (size_t)r1 * (NKV * HD) + cv;
                    split2(acc[mt][nt][0], h0, l0); split2(acc[mt][nt][1], h1, l1);
                    *(uint32_t*)(Vh + i0) = pack_bf2(h0, h1);
                    *(uint32_t*)(Vl + i0) = pack_bf2(l0, l1);
                    split2(acc[mt][nt][2], h0, l0); split2(acc[mt][nt][3], h1, l1);
                    *(uint32_t*)(Vh + i1) = pack_bf2(h0, h1);
                    *(uint32_t*)(Vl + i1) = pack_bf2(l0, l1);
                }
            } else {
                // mode 3: acc[0]=gate, acc[1]=up (even col c -> gate_{c/2})
                int gcol = c >> 1;
                float ga0 = acc[mt][nt][0], up0 = acc[mt][nt][1];
                float ga1 = acc[mt][nt][2], up1 = acc[mt][nt][3];
                float v0 = ga0 / (1.f + expf(-ga0)) * up0;
                float v1 = ga1 / (1.f + expf(-ga1)) * up1;
                O[(size_t)r0 * FFN + gcol] = __float2half(v0);
                O[(size_t)r1 * FFN + gcol] = __float2half(v1);
            }
        }
}

// =====================================================================
// Tensor-core causal flash attention (bf16 split x3) — y output single fp16
// =====================================================================
#define AQ_HI 0
#define AQ_LO 32768
#define AKV   65536
#define AKV_STAGE 65536
#define AK_LO 16384
#define AV_HI 32768
#define AV_LO 49152
#define ATTN_SMEM (AKV + 2 * AKV_STAGE)

__device__ __forceinline__ uint32_t sw256(uint32_t row, uint32_t ch) {
    return (row << 8) + ((((ch ^ row) & 7u) | (ch & 8u)) << 4);
}

__global__ void __launch_bounds__(256, 1) attn_tc(
        const bf16* __restrict__ qhi, const bf16* __restrict__ qlo,
        const bf16* __restrict__ khi, const bf16* __restrict__ klo,
        const bf16* __restrict__ vhi, const bf16* __restrict__ vlo,
        fp16* __restrict__ y) {
    extern __shared__ __align__(128) char smem_raw[];
    const uint32_t sb = (uint32_t)__cvta_generic_to_shared(smem_raw);
    const int qt   = 31 - blockIdx.x;
    const int head = blockIdx.y;
    const int kvh  = head >> 2;
    const int qb   = qt * 128;
    const int tid  = threadIdx.x;
    const int warp = tid >> 5;
    const int lane = tid & 31;
    const int njt  = 2 * qt + 2;

    #pragma unroll
    for (int i = 0; i < 8; i++) {
        int idx = tid + i * 256;
        int row = idx >> 4;
        int ch  = idx & 15;
        size_t g = (size_t)(qb + row) * Cn + head * HD + ch * 8;
        uint32_t off = sw256(row, ch);
        cp16(sb + AQ_HI + off, qhi + g);
        cp16(sb + AQ_LO + off, qlo + g);
    }

    auto load_kv = [&](int jt, int buf) {
        const uint32_t base = sb + AKV + buf * AKV_STAGE;
        #pragma unroll
        for (int i = 0; i < 4; i++) {
            int idx = tid + i * 256;
            int row = idx >> 4;
            int ch  = idx & 15;
            size_t g = (size_t)(jt * 64 + row) * (NKV * HD) + kvh * HD + ch * 8;
            uint32_t off = sw256(row, ch);
            cp16(base + off,          khi + g);
            cp16(base + AK_LO + off,  klo + g);
            cp16(base + AV_HI + off,  vhi + g);
            cp16(base + AV_LO + off,  vlo + g);
        }
    };

    load_kv(0, 0);
    asm volatile("cp.async.commit_group;\n");

    float m0 = -1e30f, m1 = -1e30f, l0 = 0.f, l1 = 0.f;
    float o[16][4];
    #pragma unroll
    for (int nt = 0; nt < 16; nt++)
        #pragma unroll
        for (int e = 0; e < 4; e++) o[nt][e] = 0.f;

    const float cs = 0.12751743621340608f;      // log2(e)/sqrt(128)
    const int r0g = qb + (warp << 4) + (lane >> 2);
    const int r1g = r0g + 8;

    for (int jt = 0; jt < njt; jt++) {
        if (jt + 1 < njt) load_kv(jt + 1, (jt + 1) & 1);
        asm volatile("cp.async.commit_group;\n");
        asm volatile("cp.async.wait_group 1;\n");
        __syncthreads();

        const uint32_t kb   = sb + AKV + (jt & 1) * AKV_STAGE;
        const uint32_t kbl  = kb + AK_LO;
        const uint32_t vb   = kb + AV_HI;
        const uint32_t vbl  = kb + AV_LO;

        float sacc[8][4];
        #pragma unroll
        for (int nt = 0; nt < 8; nt++)
            #pragma unroll
            for (int e = 0; e < 4; e++) sacc[nt][e] = 0.f;

        #pragma unroll
        for (int ks = 0; ks < 8; ks++) {
            uint32_t ah[4], al[4];
            {
                uint32_t row = (warp << 4) + (lane & 15);
                uint32_t ch  = ks * 2 + (lane >> 4);
                uint32_t off = sw256(row, ch);
                ldm4(ah, sb + AQ_HI + off);
                ldm4(al, sb + AQ_LO + off);
            }
            uint32_t bh[8][2], bl[8][2];
            #pragma unroll
            for (int p = 0; p < 4; p++) {
                uint32_t rowb = p * 16 + (lane & 7) + ((lane >> 4) & 1) * 8;
                uint32_t chb  = ks * 2 + ((lane >> 3) & 1);
                uint32_t offb = sw256(rowb, chb);
                uint32_t r[4];
                ldm4(r, kb + offb);
                bh[2 * p][0] = r[0]; bh[2 * p][1] = r[1];
                bh[2 * p + 1][0] = r[2]; bh[2 * p + 1][1] = r[3];
                ldm4(r, kbl + offb);
                bl[2 * p][0] = r[0]; bl[2 * p][1] = r[1];
                bl[2 * p + 1][0] = r[2]; bl[2 * p + 1][1] = r[3];
            }
            #pragma unroll
            for (int nt = 0; nt < 8; nt++) mma16816(sacc[nt], ah, bh[nt]);
            #pragma unroll
            for (int nt = 0; nt < 8; nt++) mma16816(sacc[nt], ah, bl[nt]);
            #pragma unroll
            for (int nt = 0; nt < 8; nt++) mma16816(sacc[nt], al, bh[nt]);
        }

        const bool domask = (jt >= 2 * qt);
        #pragma unroll
        for (int nt = 0; nt < 8; nt++) {
            int cbase = jt * 64 + nt * 8 + (lane & 3) * 2;
            #pragma unroll
            for (int e = 0; e < 4; e++) {
                float v = sacc[nt][e] * cs;
                if (domask) {
                    int col = cbase + (e & 1);
                    int row = (e < 2) ? r0g : r1g;
                    if (col > row) v = -1e30f;
                }
                sacc[nt][e] = v;
            }
        }

        float mx0 = -1e30f, mx1 = -1e30f;
        #pragma unroll
        for (int nt = 0; nt < 8; nt++) {
            mx0 = fmaxf(mx0, fmaxf(sacc[nt][0], sacc[nt][1]));
            mx1 = fmaxf(mx1, fmaxf(sacc[nt][2], sacc[nt][3]));
        }
        mx0 = fmaxf(mx0, __shfl_xor_sync(0xffffffffu, mx0, 1));
        mx0 = fmaxf(mx0, __shfl_xor_sync(0xffffffffu, mx0, 2));
        mx1 = fmaxf(mx1, __shfl_xor_sync(0xffffffffu, mx1, 1));
        mx1 = fmaxf(mx1, __shfl_xor_sync(0xffffffffu, mx1, 2));
        float mn0 = fmaxf(m0, mx0);
        float mn1 = fmaxf(m1, mx1);

        float ls0 = 0.f, ls1 = 0.f;
        #pragma unroll
        for (int nt = 0; nt < 8; nt++) {
            float p0 = exp2f(sacc[nt][0] - mn0);
            float p1 = exp2f(sacc[nt][1] - mn0);
            float p2 = exp2f(sacc[nt][2] - mn1);
            float p3 = exp2f(sacc[nt][3] - mn1);
            ls0 += p0 + p1;
            ls1 += p2 + p3;
            sacc[nt][0] = p0; sacc[nt][1] = p1; sacc[nt][2] = p2; sacc[nt][3] = p3;
        }
        ls0 += __shfl_xor_sync(0xffffffffu, ls0, 1);
        ls0 += __shfl_xor_sync(0xffffffffu, ls0, 2);
        ls1 += __shfl_xor_sync(0xffffffffu, ls1, 1);
        ls1 += __shfl_xor_sync(0xffffffffu, ls1, 2);

        float a0 = exp2f(m0 - mn0);
        float a1 = exp2f(m1 - mn1);
        m0 = mn0; m1 = mn1;
        l0 = l0 * a0 + ls0;
        l1 = l1 * a1 + ls1;
        #pragma unroll
        for (int nt = 0; nt < 16; nt++) {
            o[nt][0] *= a0; o[nt][1] *= a0;
            o[nt][2] *= a1; o[nt][3] *= a1;
        }

        #pragma unroll
        for (int ks = 0; ks < 4; ks++) {
            bf16 h0, q0, h1, q1, h2, q2, h3, q3;
            uint32_t ah[4], al[4];
            split2(sacc[2 * ks][0], h0, q0); split2(sacc[2 * ks][1], h1, q1);
            ah[0] = pack_bf2(h0, h1); al[0] = pack_bf2(q0, q1);
            split2(sacc[2 * ks][2], h0, q0); split2(sacc[2 * ks][3], h1, q1);
            ah[1] = pack_bf2(h0, h1); al[1] = pack_bf2(q0, q1);
            split2(sacc[2 * ks + 1][0], h2, q2); split2(sacc[2 * ks + 1][1], h3, q3);
            ah[2] = pack_bf2(h2, h3); al[2] = pack_bf2(q2, q3);
            split2(sacc[2 * ks + 1][2], h2, q2); split2(sacc[2 * ks + 1][3], h3, q3);
            ah[3] = pack_bf2(h2, h3); al[3] = pack_bf2(q2, q3);

            #pragma unroll
            for (int dq = 0; dq < 4; dq++) {
                uint32_t row = ks * 16 + (lane & 15);
                uint32_t ch0 = (2 * dq) * 2 + (lane >> 4);
                uint32_t ch1 = (2 * dq + 1) * 2 + (lane >> 4);
                uint32_t bh0[4], bl0[4], bh1[4], bl1[4];
                ldm4t(bh0, vb + sw256(row, ch0));
                ldm4t(bl0, vbl + sw256(row, ch0));
                ldm4t(bh1, vb + sw256(row, ch1));
                ldm4t(bl1, vbl + sw256(row, ch1));
                float* o0 = o[4 * dq + 0];
                float* o1 = o[4 * dq + 1];
                float* o2 = o[4 * dq + 2];
                float* o3 = o[4 * dq + 3];
                mma16816(o0, ah, bh0);     mma16816(o1, ah, bh0 + 2);
                mma16816(o2, ah, bh1);     mma16816(o3, ah, bh1 + 2);
                mma16816(o0, al, bh0);     mma16816(o1, al, bh0 + 2);
                mma16816(o2, al, bh1);     mma16816(o3, al, bh1 + 2);
                mma16816(o0, ah, bl0);     mma16816(o1, ah, bl0 + 2);
                mma16816(o2, ah, bl1);     mma16816(o3, ah, bl1 + 2);
            }
        }
        __syncthreads();
    }

    float inv0 = 1.0f / l0;
    float inv1 = 1.0f / l1;
    #pragma unroll
    for (int nt = 0; nt < 16; nt++) {
        int c = head * HD + nt * 8 + (lane & 3) * 2;
        size_t i0 = (size_t)r0g * Cn + c;
        size_t i1 = (size_t)r1g * Cn + c;
        *(uint32_t*)(y + i0) = pack_h2(__float2half(o[nt][0] * inv0),
                                       __float2half(o[nt][1] * inv0));
        *(uint32_t*)(y + i1) = pack_h2(__float2half(o[nt][2] * inv1),
                                       __float2half(o[nt][3] * inv1));
    }
}

// ---------------- launch ----------------
extern "C" void kernel_launch(void* const* d_in, const int* in_sizes, int n_in,
                              void* d_out, int out_size) {
    (void)in_sizes; (void)n_in; (void)out_size;
    const float* x           = (const float*)d_in[0];
    const float* attn_norm_w = (const float*)d_in[2];
    const float* wq          = (const float*)d_in[3];
    const float* wk          = (const float*)d_in[4];
    const float* wv          = (const float*)d_in[5];
    const float* wo          = (const float*)d_in[6];
    const float* ffn_norm_w  = (const float*)d_in[7];
    const float* w_gate      = (const float*)d_in[8];
    const float* w_up        = (const float*)d_in[9];
    const float* w_down      = (const float*)d_in[10];
    float* out = (float*)d_out;

    float2* rtab;
    fp16 *h, *h2, *y, *gs;
    bf16 *qhi, *qlo, *khi, *klo, *vhi, *vlo;
    fp16 *wqkv_h, *wo_h, *wgu_h, *wd_h;

    cudaGetSymbolAddress((void**)&rtab, g_rope);
    cudaGetSymbolAddress((void**)&h,  g_h);
    cudaGetSymbolAddress((void**)&h2, g_h2);
    cudaGetSymbolAddress((void**)&y,  g_y);
    cudaGetSymbolAddress((void**)&gs, g_gs);
    cudaGetSymbolAddress((void**)&qhi, g_qhi); cudaGetSymbolAddress((void**)&qlo, g_qlo);
    cudaGetSymbolAddress((void**)&khi, g_khi); cudaGetSymbolAddress((void**)&klo, g_klo);
    cudaGetSymbolAddress((void**)&vhi, g_vhi); cudaGetSymbolAddress((void**)&vlo, g_vlo);
    cudaGetSymbolAddress((void**)&wqkv_h, g_wqkv_h);
    cudaGetSymbolAddress((void**)&wo_h, g_wo_h);
    cudaGetSymbolAddress((void**)&wgu_h, g_wgu_h);
    cudaGetSymbolAddress((void**)&wd_h, g_wd_h);

    cudaFuncSetAttribute(gemm_fp16, cudaFuncAttributeMaxDynamicSharedMemorySize, GEMM_SMEM);
    cudaFuncSetAttribute(attn_tc, cudaFuncAttributeMaxDynamicSharedMemorySize, ATTN_SMEM);

    #define CONVW(src, dst, n) \
        convert_w_kernel<<<((n) / 8 + 255) / 256, 256>>>(src, dst, n)
    #define GEMM0(Aa, Bw, Cp, Rp, Mm, Nn, Kk) \
        gemm_fp16<<<dim3((Nn) / 256, (Mm) / 128), 256, GEMM_SMEM>>>( \
            Aa, Bw, Cp, Rp, nullptr, nullptr, \
            nullptr, nullptr, nullptr, nullptr, nullptr, nullptr, 0, Mm, Nn, Kk)

    rope_table_kernel<<<(Tn * 64 + 255) / 256, 256>>>(rtab);
    rmsnorm_kernel<<<Tn, 256>>>(x, attn_norm_w, h);
    // QKV weights concatenated: rows [0,2048) wq, [2048,2560) wk, [2560,3072) wv
    CONVW(wq, wqkv_h, Cn * Cn);
    CONVW(wk, wqkv_h + (size_t)Cn * Cn, NKV * HD * Cn);
    CONVW(wv, wqkv_h + (size_t)(Cn + NKV * HD) * Cn, NKV * HD * Cn);
    // merged QKV GEMM with RoPE/split epilogue -> q/k/v bf16 split buffers
    gemm_fp16<<<dim3((Cn + 2 * NKV * HD) / 256, Tn / 128), 256, GEMM_SMEM>>>(
        h, wqkv_h, nullptr, nullptr, nullptr,
        rtab, qhi, qlo, khi, klo, vhi, vlo, 2, Tn, Cn + 2 * NKV * HD, Cn);
    // attention -> y single fp16
    attn_tc<<<dim3(32, NH), 256, ATTN_SMEM>>>(qhi, qlo, khi, klo, vhi, vlo, y);
    // out = x + y @ wo^T
    CONVW(wo, wo_h, Cn * Cn);
    GEMM0(y, wo_h, out, x, Tn, Cn, Cn);
    // rmsnorm2 -> single fp16
    rmsnorm_kernel<<<Tn, 256>>>(out, ffn_norm_w, h2);
    // gate/up interleaved weights; fused silu(gate)*up GEMM -> gs single fp16
    convert_w_pair_kernel<<<((FFN * Cn) / 8 + 255) / 256, 256>>>(w_gate, wgu_h, FFN * Cn, 0);
    convert_w_pair_kernel<<<((FFN * Cn) / 8 + 255) / 256, 256>>>(w_up,   wgu_h, FFN * Cn, 1);
    gemm_fp16<<<dim3((2 * FFN) / 256, Tn / 128), 256, GEMM_SMEM>>>(
        h2, wgu_h, nullptr, nullptr, gs,
        nullptr, nullptr, nullptr, nullptr, nullptr, nullptr, nullptr, 3, Tn, 2 * FFN, Cn);
    // out += gs @ w_down^T
    CONVW(w_down, wd_h, Cn * FFN);
    GEMM0(gs, wd_h, out, out, Tn, Cn, FFN);

    #undef CONVW
    #undef GEMM0
}

// round 14
// speedup vs baseline: 8.2174x; 1.1763x over previous
#include <cuda_runtime.h>
#include <cuda_fp16.h>
#include <math.h>
#include <stdint.h>

#define Tn   4096
#define Cn   2048
#define NH   16
#define NKV  4
#define HD   128
#define FFN  8192

typedef __half fp16;

// ---------------- scratch (static device globals; no allocation) ----------------
static __device__ float2 g_rope[Tn * 64];

// activations: single fp16
static __device__ fp16 g_h  [Tn * Cn];
static __device__ fp16 g_h2 [Tn * Cn];
static __device__ fp16 g_y  [Tn * Cn];
static __device__ fp16 g_gs [Tn * FFN];

// attention operands: single fp16
static __device__ fp16 g_qh[Tn * Cn];
static __device__ fp16 g_kh[Tn * NKV * HD];
static __device__ fp16 g_vh[Tn * NKV * HD];

// weights: single fp16
static __device__ fp16 g_wqkv_h[(Cn + 2 * NKV * HD) * Cn];  // rows: wq | wk | wv
static __device__ fp16 g_wo_h[Cn * Cn];
static __device__ fp16 g_wgu_h[2 * FFN * Cn];               // interleaved: 2j = wg[j], 2j+1 = wu[j]
static __device__ fp16 g_wd_h[Cn * FFN];

__device__ __forceinline__ uint32_t pack_h2(fp16 a, fp16 b) {
    __half2 t; t.x = a; t.y = b;
    return *reinterpret_cast<uint32_t*>(&t);
}

// ---------------- common PTX helpers ----------------
__device__ __forceinline__ void cp16(uint32_t dst, const void* src) {
    asm volatile("cp.async.cg.shared.global [%0], [%1], 16;\n" :: "r"(dst), "l"(src));
}
__device__ __forceinline__ void ldm4(uint32_t* r, uint32_t addr) {
    asm volatile("ldmatrix.sync.aligned.m8n8.x4.shared.b16 {%0,%1,%2,%3}, [%4];\n"
                 : "=r"(r[0]), "=r"(r[1]), "=r"(r[2]), "=r"(r[3]) : "r"(addr));
}
__device__ __forceinline__ void ldm4t(uint32_t* r, uint32_t addr) {
    asm volatile("ldmatrix.sync.aligned.m8n8.x4.trans.shared.b16 {%0,%1,%2,%3}, [%4];\n"
                 : "=r"(r[0]), "=r"(r[1]), "=r"(r[2]), "=r"(r[3]) : "r"(addr));
}
__device__ __forceinline__ void mma16816h(float* c, const uint32_t* a, const uint32_t* b) {
    asm volatile("mma.sync.aligned.m16n8k16.row.col.f32.f16.f16.f32 "
                 "{%0,%1,%2,%3},{%4,%5,%6,%7},{%8,%9},{%0,%1,%2,%3};\n"
                 : "+f"(c[0]), "+f"(c[1]), "+f"(c[2]), "+f"(c[3])
                 : "r"(a[0]), "r"(a[1]), "r"(a[2]), "r"(a[3]), "r"(b[0]), "r"(b[1]));
}

// ---------------- weight fp32 -> single fp16 (8 elems/thread) ----------------
__global__ void convert_w_kernel(const float* __restrict__ w, fp16* __restrict__ o, int n) {
    int i = (blockIdx.x * blockDim.x + threadIdx.x) * 8;
    if (i >= n) return;
    float4 a = *(const float4*)(w + i);
    float4 b = *(const float4*)(w + i + 4);
    uint4 p;
    p.x = pack_h2(__float2half(a.x), __float2half(a.y));
    p.y = pack_h2(__float2half(a.z), __float2half(a.w));
    p.z = pack_h2(__float2half(b.x), __float2half(b.y));
    p.w = pack_h2(__float2half(b.z), __float2half(b.w));
    *(uint4*)(o + i) = p;
}

// ---------------- weight fp32 -> fp16 with row interleave (dst row = 2*row + off) ----------------
__global__ void convert_w_pair_kernel(const float* __restrict__ w, fp16* __restrict__ o,
                                      int n, int off) {
    int i = (blockIdx.x * blockDim.x + threadIdx.x) * 8;
    if (i >= n) return;
    int row = i / Cn;
    int col = i - row * Cn;
    size_t di = (size_t)(2 * row + off) * Cn + col;
    float4 a = *(const float4*)(w + i);
    float4 b = *(const float4*)(w + i + 4);
    uint4 p;
    p.x = pack_h2(__float2half(a.x), __float2half(a.y));
    p.y = pack_h2(__float2half(a.z), __float2half(a.w));
    p.z = pack_h2(__float2half(b.x), __float2half(b.y));
    p.w = pack_h2(__float2half(b.z), __float2half(b.w));
    *(uint4*)(o + di) = p;
}

// ---------------- RoPE cos/sin table (double sincos — fast-math immune) ----------------
__global__ void rope_table_kernel(float2* __restrict__ tab) {
    int idx = blockIdx.x * blockDim.x + threadIdx.x;
    if (idx >= Tn * 64) return;
    int i = idx & 63;
    int t = idx >> 6;
    double invf_d = pow(500000.0, -((double)(2 * i) / 128.0));
    float  invf_f = (float)invf_d;
    float  ang_f  = (float)t * invf_f;
    double c, s;
    sincos((double)ang_f, &s, &c);
    tab[idx] = make_float2((float)c, (float)s);
}

// ---------------- rmsnorm: one block per row, writes single fp16 ----------------
__global__ void __launch_bounds__(256) rmsnorm_kernel(const float* __restrict__ x,
                                                      const float* __restrict__ w,
                                                      fp16* __restrict__ o) {
    const int row = blockIdx.x;
    const float* xr = x + (size_t)row * Cn;
    float s = 0.f;
    for (int i = threadIdx.x; i < Cn; i += 256) {
        float v = xr[i];
        s = fmaf(v, v, s);
    }
    __shared__ float red[8];
    #pragma unroll
    for (int o2 = 16; o2; o2 >>= 1) s += __shfl_xor_sync(0xffffffffu, s, o2);
    if ((threadIdx.x & 31) == 0) red[threadIdx.x >> 5] = s;
    __syncthreads();
    if (threadIdx.x < 32) {
        float v = (threadIdx.x < 8) ? red[threadIdx.x] : 0.f;
        #pragma unroll
        for (int o2 = 4; o2; o2 >>= 1) v += __shfl_xor_sync(0xffffffffu, v, o2);
        if (threadIdx.x == 0) red[0] = v;
    }
    __syncthreads();
    const float scale = rsqrtf(red[0] * (1.0f / Cn) + 1e-5f);
    size_t base = (size_t)row * Cn;
    for (int i = threadIdx.x; i < Cn; i += 256)
        o[base + i] = __float2half(xr[i] * scale * w[i]);
}

// =====================================================================
// fp16 tensor-core GEMM (unchanged core from R13)
// mode 0: C = acc (+R); mode 2: QKV epilogue (RoPE / plain -> single fp16);
// mode 3: gate/up interleaved -> silu(gate)*up single fp16
// =====================================================================
#define STAGES 5
#define G_A   0
#define G_B   8192
#define G_STAGE 24576
#define GEMM_SMEM (STAGES * G_STAGE)

__device__ __forceinline__ uint32_t sw(uint32_t row, uint32_t chunk) {
    return (row << 6) + (((chunk ^ (row >> 1)) & 3u) << 4);
}

__global__ void __launch_bounds__(256, 1) gemm_fp16(
        const fp16* __restrict__ A, const fp16* __restrict__ B,
        float* __restrict__ C, const float* __restrict__ R,
        fp16* __restrict__ O,
        const float2* __restrict__ tab,
        fp16* __restrict__ Qp, fp16* __restrict__ Kp, fp16* __restrict__ Vp,
        int mode, int M, int N, int K) {
    extern __shared__ __align__(128) char smem_raw[];
    const uint32_t smem_u = (uint32_t)__cvta_generic_to_shared(smem_raw);
    const int tid  = threadIdx.x;
    const int warp = tid >> 5;
    const int lane = tid & 31;
    const int wm   = warp & 1;
    const int wn   = warp >> 1;

    int bx, by;
    {
        int tiles_n = gridDim.x, tiles_m = gridDim.y;
        int lin = blockIdx.y * tiles_n + blockIdx.x;
        int per = 8 * tiles_n;
        int gid = lin / per, rem = lin % per;
        int gm  = tiles_m - gid * 8;
        if (gm > 8) gm = 8;
        by = gid * 8 + rem % gm;
        bx = rem / gm;
    }
    const int bm = by * 128;
    const int bn = bx * 256;

    float acc[4][8][4];
    #pragma unroll
    for (int i = 0; i < 4; i++)
        #pragma unroll
        for (int j = 0; j < 8; j++)
            #pragma unroll
            for (int v = 0; v < 4; v++) acc[i][j][v] = 0.f;

    const int kiters = K >> 5;

    auto load_stage = [&](int stage, int kt) {
        const uint32_t sbase = smem_u + stage * G_STAGE;
        #pragma unroll
        for (int rep = 0; rep < 2; rep++) {
            int idx = tid + rep * 256;
            int row = idx >> 2;
            int ch  = idx & 3;
            size_t go = (size_t)(bm + row) * K + kt + ch * 8;
            cp16(sbase + G_A + sw(row, ch), A + go);
        }
        #pragma unroll
        for (int rep = 0; rep < 4; rep++) {
            int idx = tid + rep * 256;
            int row = idx >> 2;
            int ch  = idx & 3;
            size_t go = (size_t)(bn + row) * K + kt + ch * 8;
            cp16(sbase + G_B + sw(row, ch), B + go);
        }
    };

    #pragma unroll
    for (int s = 0; s < STAGES - 1; s++) {
        load_stage(s, s * 32);
        asm volatile("cp.async.commit_group;\n");
    }

    for (int it = 0; it < kiters; ++it) {
        asm volatile("cp.async.wait_group %0;\n" :: "n"(STAGES - 2));
        __syncthreads();
        int pf = it + STAGES - 1;
        if (pf < kiters) load_stage(pf % STAGES, pf * 32);
        asm volatile("cp.async.commit_group;\n");

        const uint32_t sb = smem_u + (it % STAGES) * G_STAGE;

        #pragma unroll
        for (int kf = 0; kf < 2; kf++) {
            uint32_t ah[4][4];
            #pragma unroll
            for (int mt = 0; mt < 4; mt++) {
                uint32_t row = wm * 64 + mt * 16 + (lane & 15);
                uint32_t ch  = kf * 2 + (lane >> 4);
                ldm4(ah[mt], sb + G_A + sw(row, ch));
            }
            #pragma unroll
            for (int p = 0; p < 4; p++) {
                uint32_t rowb = wn * 64 + p * 16 + (lane & 7) + ((lane >> 4) & 1) * 8;
                uint32_t chb  = kf * 2 + ((lane >> 3) & 1);
                uint32_t bfr[4];
                ldm4(bfr, sb + G_B + sw(rowb, chb));
                #pragma unroll
                for (int mt = 0; mt < 4; mt++) {
                    mma16816h(acc[mt][2 * p],     ah[mt], bfr);
                    mma16816h(acc[mt][2 * p + 1], ah[mt], bfr + 2);
                }
            }
        }
    }

    // ---- epilogue ----
    const int rb = bm + wm * 64;
    const int cb = bn + wn * 64;
    #pragma unroll
    for (int mt = 0; mt < 4; mt++)
        #pragma unroll
        for (int nt = 0; nt < 8; nt++) {
            int r0 = rb + mt * 16 + (lane >> 2);
            int r1 = r0 + 8;
            int c  = cb + nt * 8 + (lane & 3) * 2;   // even global col
            if (mode == 0) {
                size_t i0 = (size_t)r0 * N + c;
                size_t i1 = (size_t)r1 * N + c;
                float2 v0 = make_float2(acc[mt][nt][0], acc[mt][nt][1]);
                float2 v1 = make_float2(acc[mt][nt][2], acc[mt][nt][3]);
                if (R) {
                    float2 q0 = *(const float2*)(R + i0);
                    float2 q1 = *(const float2*)(R + i1);
                    v0.x += q0.x; v0.y += q0.y;
                    v1.x += q1.x; v1.y += q1.y;
                }
                *(float2*)(C + i0) = v0;
                *(float2*)(C + i1) = v1;
            } else if (mode == 2) {
                // QKV: cols [0,2048) q (rope), [2048,2560) k (rope), [2560,3072) v
                if (bn < 2048) {
                    int i = (c & 127) >> 1;
                    float2 cs0 = tab[(size_t)r0 * 64 + i];
                    float2 cs1 = tab[(size_t)r1 * 64 + i];
                    float a0 = acc[mt][nt][0], b0 = acc[mt][nt][1];
                    float a1 = acc[mt][nt][2], b1 = acc[mt][nt][3];
                    size_t i0 = (size_t)r0 * Cn + c;
                    size_t i1 = (size_t)r1 * Cn + c;
                    *(uint32_t*)(Qp + i0) = pack_h2(
                        __float2half(fmaf(a0, cs0.x, -b0 * cs0.y)),
                        __float2half(fmaf(a0, cs0.y,  b0 * cs0.x)));
                    *(uint32_t*)(Qp + i1) = pack_h2(
                        __float2half(fmaf(a1, cs1.x, -b1 * cs1.y)),
                        __float2half(fmaf(a1, cs1.y,  b1 * cs1.x)));
                } else if (bn < 2560) {
                    int ck = c - 2048;
                    int i = (ck & 127) >> 1;
                    float2 cs0 = tab[(size_t)r0 * 64 + i];
                    float2 cs1 = tab[(size_t)r1 * 64 + i];
                    float a0 = acc[mt][nt][0], b0 = acc[mt][nt][1];
                    float a1 = acc[mt][nt][2], b1 = acc[mt][nt][3];
                    size_t i0 = (size_t)r0 * (NKV * HD) + ck;
                    size_t i1 = (size_t)r1 * (NKV * HD) + ck;
                    *(uint32_t*)(Kp + i0) = pack_h2(
                        __float2half(fmaf(a0, cs0.x, -b0 * cs0.y)),
                        __float2half(fmaf(a0, cs0.y,  b0 * cs0.x)));
                    *(uint32_t*)(Kp + i1) = pack_h2(
                        __float2half(fmaf(a1, cs1.x, -b1 * cs1.y)),
                        __float2half(fmaf(a1, cs1.y,  b1 * cs1.x)));
                } else {
                    int cv = c - 2560;
                    size_t i0 = (size_t)r0 * (NKV * HD) + cv;
                    size_t i1 = (size_t)r1 * (NKV * HD) + cv;
                    *(uint32_t*)(Vp + i0) = pack_h2(__float2half(acc[mt][nt][0]),
                                                    __float2half(acc[mt][nt][1]));
                    *(uint32_t*)(Vp + i1) = pack_h2(__float2half(acc[mt][nt][2]),
                                                    __float2half(acc[mt][nt][3]));
                }
            } else {
                // mode 3: acc[0]=gate, acc[1]=up (even col c -> gate_{c/2})
                int gcol = c >> 1;
                float ga0 = acc[mt][nt][0], up0 = acc[mt][nt][1];
                float ga1 = acc[mt][nt][2], up1 = acc[mt][nt][3];
                O[(size_t)r0 * FFN + gcol] = __float2half(ga0 / (1.f + expf(-ga0)) * up0);
                O[(size_t)r1 * FFN + gcol] = __float2half(ga1 / (1.f + expf(-ga1)) * up1);
            }
        }
}

// =====================================================================
// Tensor-core causal flash attention — single fp16 Q/K/V/P
// CTA: 128 q-rows x head, 8 warps; KV tiles 64, double-buffered.
// smem: Q 32KB + 2 x (K 16KB + V 16KB) = 96KB.
// =====================================================================
#define AQ    0
#define AKV   32768
#define AKV_STAGE 32768
#define AV    16384
#define ATTN_SMEM (AKV + 2 * AKV_STAGE)

__device__ __forceinline__ uint32_t sw256(uint32_t row, uint32_t ch) {
    return (row << 8) + ((((ch ^ row) & 7u) | (ch & 8u)) << 4);
}

__global__ void __launch_bounds__(256, 1) attn_tc(
        const fp16* __restrict__ q, const fp16* __restrict__ k,
        const fp16* __restrict__ v, fp16* __restrict__ y) {
    extern __shared__ __align__(128) char smem_raw[];
    const uint32_t sb = (uint32_t)__cvta_generic_to_shared(smem_raw);
    const int qt   = 31 - blockIdx.x;
    const int head = blockIdx.y;
    const int kvh  = head >> 2;
    const int qb   = qt * 128;
    const int tid  = threadIdx.x;
    const int warp = tid >> 5;
    const int lane = tid & 31;
    const int njt  = 2 * qt + 2;

    // Q tile: 128 rows x 16 chunks
    #pragma unroll
    for (int i = 0; i < 8; i++) {
        int idx = tid + i * 256;
        int row = idx >> 4;
        int ch  = idx & 15;
        size_t g = (size_t)(qb + row) * Cn + head * HD + ch * 8;
        cp16(sb + AQ + sw256(row, ch), q + g);
    }

    auto load_kv = [&](int jt, int buf) {
        const uint32_t base = sb + AKV + buf * AKV_STAGE;
        #pragma unroll
        for (int i = 0; i < 4; i++) {
            int idx = tid + i * 256;
            int row = idx >> 4;
            int ch  = idx & 15;
            size_t g = (size_t)(jt * 64 + row) * (NKV * HD) + kvh * HD + ch * 8;
            uint32_t off = sw256(row, ch);
            cp16(base + off,      k + g);
            cp16(base + AV + off, v + g);
        }
    };

    load_kv(0, 0);
    asm volatile("cp.async.commit_group;\n");

    float m0 = -1e30f, m1 = -1e30f, l0 = 0.f, l1 = 0.f;
    float o[16][4];
    #pragma unroll
    for (int nt = 0; nt < 16; nt++)
        #pragma unroll
        for (int e = 0; e < 4; e++) o[nt][e] = 0.f;

    const float cs = 0.12751743621340608f;      // log2(e)/sqrt(128)
    const int r0g = qb + (warp << 4) + (lane >> 2);
    const int r1g = r0g + 8;

    for (int jt = 0; jt < njt; jt++) {
        if (jt + 1 < njt) load_kv(jt + 1, (jt + 1) & 1);
        asm volatile("cp.async.commit_group;\n");
        asm volatile("cp.async.wait_group 1;\n");
        __syncthreads();

        const uint32_t kb = sb + AKV + (jt & 1) * AKV_STAGE;
        const uint32_t vb = kb + AV;

        // ---- S = Q K^T ----
        float sacc[8][4];
        #pragma unroll
        for (int nt = 0; nt < 8; nt++)
            #pragma unroll
            for (int e = 0; e < 4; e++) sacc[nt][e] = 0.f;

        #pragma unroll
        for (int ks = 0; ks < 8; ks++) {
            uint32_t ah[4];
            {
                uint32_t row = (warp << 4) + (lane & 15);
                uint32_t ch  = ks * 2 + (lane >> 4);
                ldm4(ah, sb + AQ + sw256(row, ch));
            }
            #pragma unroll
            for (int p = 0; p < 4; p++) {
                uint32_t rowb = p * 16 + (lane & 7) + ((lane >> 4) & 1) * 8;
                uint32_t chb  = ks * 2 + ((lane >> 3) & 1);
                uint32_t bfr[4];
                ldm4(bfr, kb + sw256(rowb, chb));
                mma16816h(sacc[2 * p],     ah, bfr);
                mma16816h(sacc[2 * p + 1], ah, bfr + 2);
            }
        }

        // ---- scale + mask ----
        const bool domask = (jt >= 2 * qt);
        #pragma unroll
        for (int nt = 0; nt < 8; nt++) {
            int cbase = jt * 64 + nt * 8 + (lane & 3) * 2;
            #pragma unroll
            for (int e = 0; e < 4; e++) {
                float vv = sacc[nt][e] * cs;
                if (domask) {
                    int col = cbase + (e & 1);
                    int row = (e < 2) ? r0g : r1g;
                    if (col > row) vv = -1e30f;
                }
                sacc[nt][e] = vv;
            }
        }

        // ---- online softmax (base-2) ----
        float mx0 = -1e30f, mx1 = -1e30f;
        #pragma unroll
        for (int nt = 0; nt < 8; nt++) {
            mx0 = fmaxf(mx0, fmaxf(sacc[nt][0], sacc[nt][1]));
            mx1 = fmaxf(mx1, fmaxf(sacc[nt][2], sacc[nt][3]));
        }
        mx0 = fmaxf(mx0, __shfl_xor_sync(0xffffffffu, mx0, 1));
        mx0 = fmaxf(mx0, __shfl_xor_sync(0xffffffffu, mx0, 2));
        mx1 = fmaxf(mx1, __shfl_xor_sync(0xffffffffu, mx1, 1));
        mx1 = fmaxf(mx1, __shfl_xor_sync(0xffffffffu, mx1, 2));
        float mn0 = fmaxf(m0, mx0);
        float mn1 = fmaxf(m1, mx1);

        float ls0 = 0.f, ls1 = 0.f;
        #pragma unroll
        for (int nt = 0; nt < 8; nt++) {
            float p0 = exp2f(sacc[nt][0] - mn0);
            float p1 = exp2f(sacc[nt][1] - mn0);
            float p2 = exp2f(sacc[nt][2] - mn1);
            float p3 = exp2f(sacc[nt][3] - mn1);
            ls0 += p0 + p1;
            ls1 += p2 + p3;
            sacc[nt][0] = p0; sacc[nt][1] = p1; sacc[nt][2] = p2; sacc[nt][3] = p3;
        }
        ls0 += __shfl_xor_sync(0xffffffffu, ls0, 1);
        ls0 += __shfl_xor_sync(0xffffffffu, ls0, 2);
        ls1 += __shfl_xor_sync(0xffffffffu, ls1, 1);
        ls1 += __shfl_xor_sync(0xffffffffu, ls1, 2);

        float a0 = exp2f(m0 - mn0);
        float a1 = exp2f(m1 - mn1);
        m0 = mn0; m1 = mn1;
        l0 = l0 * a0 + ls0;
        l1 = l1 * a1 + ls1;
        #pragma unroll
        for (int nt = 0; nt < 16; nt++) {
            o[nt][0] *= a0; o[nt][1] *= a0;
            o[nt][2] *= a1; o[nt][3] *= a1;
        }

        // ---- O += P V (P single fp16) ----
        #pragma unroll
        for (int ks = 0; ks < 4; ks++) {
            uint32_t ah[4];
            ah[0] = pack_h2(__float2half(sacc[2 * ks][0]),     __float2half(sacc[2 * ks][1]));
            ah[1] = pack_h2(__float2half(sacc[2 * ks][2]),     __float2half(sacc[2 * ks][3]));
            ah[2] = pack_h2(__float2half(sacc[2 * ks + 1][0]), __float2half(sacc[2 * ks + 1][1]));
            ah[3] = pack_h2(__float2half(sacc[2 * ks + 1][2]), __float2half(sacc[2 * ks + 1][3]));

            #pragma unroll
            for (int dq = 0; dq < 4; dq++) {
                uint32_t row = ks * 16 + (lane & 15);
                uint32_t ch0 = (2 * dq) * 2 + (lane >> 4);
                uint32_t ch1 = (2 * dq + 1) * 2 + (lane >> 4);
                uint32_t b0[4], b1[4];
                ldm4t(b0, vb + sw256(row, ch0));
                ldm4t(b1, vb + sw256(row, ch1));
                mma16816h(o[4 * dq + 0], ah, b0);
                mma16816h(o[4 * dq + 1], ah, b0 + 2);
                mma16816h(o[4 * dq + 2], ah, b1);
                mma16816h(o[4 * dq + 3], ah, b1 + 2);
            }
        }
        __syncthreads();
    }

    // ---- epilogue ----
    float inv0 = 1.0f / l0;
    float inv1 = 1.0f / l1;
    #pragma unroll
    for (int nt = 0; nt < 16; nt++) {
        int c = head * HD + nt * 8 + (lane & 3) * 2;
        size_t i0 = (size_t)r0g * Cn + c;
        size_t i1 = (size_t)r1g * Cn + c;
        *(uint32_t*)(y + i0) = pack_h2(__float2half(o[nt][0] * inv0),
                                       __float2half(o[nt][1] * inv0));
        *(uint32_t*)(y + i1) = pack_h2(__float2half(o[nt][2] * inv1),
                                       __float2half(o[nt][3] * inv1));
    }
}

// ---------------- launch ----------------
extern "C" void kernel_launch(void* const* d_in, const int* in_sizes, int n_in,
                              void* d_out, int out_size) {
    (void)in_sizes; (void)n_in; (void)out_size;
    const float* x           = (const float*)d_in[0];
    const float* attn_norm_w = (const float*)d_in[2];
    const float* wq          = (const float*)d_in[3];
    const float* wk          = (const float*)d_in[4];
    const float* wv          = (const float*)d_in[5];
    const float* wo          = (const float*)d_in[6];
    const float* ffn_norm_w  = (const float*)d_in[7];
    const float* w_gate      = (const float*)d_in[8];
    const float* w_up        = (const float*)d_in[9];
    const float* w_down      = (const float*)d_in[10];
    float* out = (float*)d_out;

    float2* rtab;
    fp16 *h, *h2, *y, *gs, *qp, *kp, *vp;
    fp16 *wqkv_h, *wo_h, *wgu_h, *wd_h;

    cudaGetSymbolAddress((void**)&rtab, g_rope);
    cudaGetSymbolAddress((void**)&h,  g_h);
    cudaGetSymbolAddress((void**)&h2, g_h2);
    cudaGetSymbolAddress((void**)&y,  g_y);
    cudaGetSymbolAddress((void**)&gs, g_gs);
    cudaGetSymbolAddress((void**)&qp, g_qh);
    cudaGetSymbolAddress((void**)&kp, g_kh);
    cudaGetSymbolAddress((void**)&vp, g_vh);
    cudaGetSymbolAddress((void**)&wqkv_h, g_wqkv_h);
    cudaGetSymbolAddress((void**)&wo_h, g_wo_h);
    cudaGetSymbolAddress((void**)&wgu_h, g_wgu_h);
    cudaGetSymbolAddress((void**)&wd_h, g_wd_h);

    cudaFuncSetAttribute(gemm_fp16, cudaFuncAttributeMaxDynamicSharedMemorySize, GEMM_SMEM);
    cudaFuncSetAttribute(attn_tc, cudaFuncAttributeMaxDynamicSharedMemorySize, ATTN_SMEM);

    #define CONVW(src, dst, n) \
        convert_w_kernel<<<((n) / 8 + 255) / 256, 256>>>(src, dst, n)
    #define GEMM0(Aa, Bw, Cp, Rp, Mm, Nn, Kk) \
        gemm_fp16<<<dim3((Nn) / 256, (Mm) / 128), 256, GEMM_SMEM>>>( \
            Aa, Bw, Cp, Rp, nullptr, nullptr, nullptr, nullptr, nullptr, 0, Mm, Nn, Kk)

    rope_table_kernel<<<(Tn * 64 + 255) / 256, 256>>>(rtab);
    rmsnorm_kernel<<<Tn, 256>>>(x, attn_norm_w, h);
    // QKV weights concatenated: rows [0,2048) wq, [2048,2560) wk, [2560,3072) wv
    CONVW(wq, wqkv_h, Cn * Cn);
    CONVW(wk, wqkv_h + (size_t)Cn * Cn, NKV * HD * Cn);
    CONVW(wv, wqkv_h + (size_t)(Cn + NKV * HD) * Cn, NKV * HD * Cn);
    // merged QKV GEMM with RoPE epilogue -> q/k/v single fp16
    gemm_fp16<<<dim3((Cn + 2 * NKV * HD) / 256, Tn / 128), 256, GEMM_SMEM>>>(
        h, wqkv_h, nullptr, nullptr, nullptr,
        rtab, qp, kp, vp, 2, Tn, Cn + 2 * NKV * HD, Cn);
    // attention (single fp16) -> y
    attn_tc<<<dim3(32, NH), 256, ATTN_SMEM>>>(qp, kp, vp, y);
    // out = x + y @ wo^T
    CONVW(wo, wo_h, Cn * Cn);
    GEMM0(y, wo_h, out, x, Tn, Cn, Cn);
    // rmsnorm2 -> single fp16
    rmsnorm_kernel<<<Tn, 256>>>(out, ffn_norm_w, h2);
    // gate/up interleaved; fused silu(gate)*up -> gs single fp16
    convert_w_pair_kernel<<<((FFN * Cn) / 8 + 255) / 256, 256>>>(w_gate, wgu_h, FFN * Cn, 0);
    convert_w_pair_kernel<<<((FFN * Cn) / 8 + 255) / 256, 256>>>(w_up,   wgu_h, FFN * Cn, 1);
    gemm_fp16<<<dim3((2 * FFN) / 256, Tn / 128), 256, GEMM_SMEM>>>(
        h2, wgu_h, nullptr, nullptr, gs,
        nullptr, nullptr, nullptr, nullptr, 3, Tn, 2 * FFN, Cn);
    // out += gs @ w_down^T
    CONVW(w_down, wd_h, Cn * FFN);
    GEMM0(gs, wd_h, out, out, Tn, Cn, FFN);

    #undef CONVW
    #undef GEMM0
}

// round 15
// speedup vs baseline: 8.2344x; 1.0021x over previous
#include <cuda_runtime.h>
#include <cuda_fp16.h>
#include <math.h>
#include <stdint.h>

#define Tn   4096
#define Cn   2048
#define NH   16
#define NKV  4
#define HD   128
#define FFN  8192

typedef __half fp16;

// ---------------- scratch (static device globals; no allocation) ----------------
static __device__ float2 g_rope[Tn * 64];

static __device__ fp16 g_h  [Tn * Cn];
static __device__ fp16 g_h2 [Tn * Cn];
static __device__ fp16 g_y  [Tn * Cn];
static __device__ fp16 g_gs [Tn * FFN];

static __device__ fp16 g_qh[Tn * Cn];
static __device__ fp16 g_kh[Tn * NKV * HD];
static __device__ fp16 g_vh[Tn * NKV * HD];

static __device__ fp16 g_wqkv_h[(Cn + 2 * NKV * HD) * Cn];  // rows: wq | wk | wv
static __device__ fp16 g_wo_h[Cn * Cn];
static __device__ fp16 g_wgu_h[2 * FFN * Cn];               // interleaved: 2j = wg[j], 2j+1 = wu[j]
static __device__ fp16 g_wd_h[Cn * FFN];

__device__ __forceinline__ uint32_t pack_h2(fp16 a, fp16 b) {
    __half2 t; t.x = a; t.y = b;
    return *reinterpret_cast<uint32_t*>(&t);
}

// ---------------- common PTX helpers ----------------
__device__ __forceinline__ void cp16(uint32_t dst, const void* src) {
    asm volatile("cp.async.cg.shared.global [%0], [%1], 16;\n" :: "r"(dst), "l"(src));
}
__device__ __forceinline__ void ldm4(uint32_t* r, uint32_t addr) {
    asm volatile("ldmatrix.sync.aligned.m8n8.x4.shared.b16 {%0,%1,%2,%3}, [%4];\n"
                 : "=r"(r[0]), "=r"(r[1]), "=r"(r[2]), "=r"(r[3]) : "r"(addr));
}
__device__ __forceinline__ void ldm4t(uint32_t* r, uint32_t addr) {
    asm volatile("ldmatrix.sync.aligned.m8n8.x4.trans.shared.b16 {%0,%1,%2,%3}, [%4];\n"
                 : "=r"(r[0]), "=r"(r[1]), "=r"(r[2]), "=r"(r[3]) : "r"(addr));
}
__device__ __forceinline__ void mma16816h(float* c, const uint32_t* a, const uint32_t* b) {
    asm volatile("mma.sync.aligned.m16n8k16.row.col.f32.f16.f16.f32 "
                 "{%0,%1,%2,%3},{%4,%5,%6,%7},{%8,%9},{%0,%1,%2,%3};\n"
                 : "+f"(c[0]), "+f"(c[1]), "+f"(c[2]), "+f"(c[3])
                 : "r"(a[0]), "r"(a[1]), "r"(a[2]), "r"(a[3]), "r"(b[0]), "r"(b[1]));
}

// ---------------- weight fp32 -> single fp16 (16 elems/thread) ----------------
__global__ void convert_w_kernel(const float* __restrict__ w, fp16* __restrict__ o, int n) {
    int i = (blockIdx.x * blockDim.x + threadIdx.x) * 16;
    if (i >= n) return;
    #pragma unroll
    for (int half = 0; half < 2; half++) {
        float4 a = *(const float4*)(w + i + half * 8);
        float4 b = *(const float4*)(w + i + half * 8 + 4);
        uint4 p;
        p.x = pack_h2(__float2half(a.x), __float2half(a.y));
        p.y = pack_h2(__float2half(a.z), __float2half(a.w));
        p.z = pack_h2(__float2half(b.x), __float2half(b.y));
        p.w = pack_h2(__float2half(b.z), __float2half(b.w));
        *(uint4*)(o + i + half * 8) = p;
    }
}

// ---------------- gate+up fp32 -> fp16, row-interleaved, one pass ----------------
__global__ void convert_w_gu_kernel(const float* __restrict__ wg, const float* __restrict__ wu,
                                    fp16* __restrict__ o, int n) {
    int i = (blockIdx.x * blockDim.x + threadIdx.x) * 8;
    if (i >= n) return;
    int row = i / Cn;
    int col = i - row * Cn;
    float4 a = *(const float4*)(wg + i);
    float4 b = *(const float4*)(wg + i + 4);
    uint4 p;
    p.x = pack_h2(__float2half(a.x), __float2half(a.y));
    p.y = pack_h2(__float2half(a.z), __float2half(a.w));
    p.z = pack_h2(__float2half(b.x), __float2half(b.y));
    p.w = pack_h2(__float2half(b.z), __float2half(b.w));
    *(uint4*)(o + (size_t)(2 * row) * Cn + col) = p;
    a = *(const float4*)(wu + i);
    b = *(const float4*)(wu + i + 4);
    p.x = pack_h2(__float2half(a.x), __float2half(a.y));
    p.y = pack_h2(__float2half(a.z), __float2half(a.w));
    p.z = pack_h2(__float2half(b.x), __float2half(b.y));
    p.w = pack_h2(__float2half(b.z), __float2half(b.w));
    *(uint4*)(o + (size_t)(2 * row + 1) * Cn + col) = p;
}

// ---------------- RoPE cos/sin table (double sincos — fast-math immune) ----------------
__global__ void rope_table_kernel(float2* __restrict__ tab) {
    int idx = blockIdx.x * blockDim.x + threadIdx.x;
    if (idx >= Tn * 64) return;
    int i = idx & 63;
    int t = idx >> 6;
    double invf_d = pow(500000.0, -((double)(2 * i) / 128.0));
    float  invf_f = (float)invf_d;
    float  ang_f  = (float)t * invf_f;
    double c, s;
    sincos((double)ang_f, &s, &c);
    tab[idx] = make_float2((float)c, (float)s);
}

// ---------------- rmsnorm: one block per row, writes single fp16 ----------------
__global__ void __launch_bounds__(256) rmsnorm_kernel(const float* __restrict__ x,
                                                      const float* __restrict__ w,
                                                      fp16* __restrict__ o) {
    const int row = blockIdx.x;
    const float* xr = x + (size_t)row * Cn;
    float s = 0.f;
    for (int i = threadIdx.x; i < Cn; i += 256) {
        float v = xr[i];
        s = fmaf(v, v, s);
    }
    __shared__ float red[8];
    #pragma unroll
    for (int o2 = 16; o2; o2 >>= 1) s += __shfl_xor_sync(0xffffffffu, s, o2);
    if ((threadIdx.x & 31) == 0) red[threadIdx.x >> 5] = s;
    __syncthreads();
    if (threadIdx.x < 32) {
        float v = (threadIdx.x < 8) ? red[threadIdx.x] : 0.f;
        #pragma unroll
        for (int o2 = 4; o2; o2 >>= 1) v += __shfl_xor_sync(0xffffffffu, v, o2);
        if (threadIdx.x == 0) red[0] = v;
    }
    __syncthreads();
    const float scale = rsqrtf(red[0] * (1.0f / Cn) + 1e-5f);
    size_t base = (size_t)row * Cn;
    for (int i = threadIdx.x; i < Cn; i += 256)
        o[base + i] = __float2half(xr[i] * scale * w[i]);
}

// =====================================================================
// fp16 tensor-core GEMM — hoisted operand loads (8 ldm, then 32-mma burst)
// mode 0: C = acc (+R); mode 2: QKV epilogue; mode 3: silu(gate)*up
// =====================================================================
#define STAGES 5
#define G_A   0
#define G_B   8192
#define G_STAGE 24576
#define GEMM_SMEM (STAGES * G_STAGE)

__device__ __forceinline__ uint32_t sw(uint32_t row, uint32_t chunk) {
    return (row << 6) + (((chunk ^ (row >> 1)) & 3u) << 4);
}

__global__ void __launch_bounds__(256, 1) gemm_fp16(
        const fp16* __restrict__ A, const fp16* __restrict__ B,
        float* __restrict__ C, const float* __restrict__ R,
        fp16* __restrict__ O,
        const float2* __restrict__ tab,
        fp16* __restrict__ Qp, fp16* __restrict__ Kp, fp16* __restrict__ Vp,
        int mode, int M, int N, int K) {
    extern __shared__ __align__(128) char smem_raw[];
    const uint32_t smem_u = (uint32_t)__cvta_generic_to_shared(smem_raw);
    const int tid  = threadIdx.x;
    const int warp = tid >> 5;
    const int lane = tid & 31;
    const int wm   = warp & 1;
    const int wn   = warp >> 1;

    int bx, by;
    {
        int tiles_n = gridDim.x, tiles_m = gridDim.y;
        int lin = blockIdx.y * tiles_n + blockIdx.x;
        int per = 8 * tiles_n;
        int gid = lin / per, rem = lin % per;
        int gm  = tiles_m - gid * 8;
        if (gm > 8) gm = 8;
        by = gid * 8 + rem % gm;
        bx = rem / gm;
    }
    const int bm = by * 128;
    const int bn = bx * 256;

    float acc[4][8][4];
    #pragma unroll
    for (int i = 0; i < 4; i++)
        #pragma unroll
        for (int j = 0; j < 8; j++)
            #pragma unroll
            for (int v = 0; v < 4; v++) acc[i][j][v] = 0.f;

    const int kiters = K >> 5;

    auto load_stage = [&](int stage, int kt) {
        const uint32_t sbase = smem_u + stage * G_STAGE;
        #pragma unroll
        for (int rep = 0; rep < 2; rep++) {
            int idx = tid + rep * 256;
            int row = idx >> 2;
            int ch  = idx & 3;
            size_t go = (size_t)(bm + row) * K + kt + ch * 8;
            cp16(sbase + G_A + sw(row, ch), A + go);
        }
        #pragma unroll
        for (int rep = 0; rep < 4; rep++) {
            int idx = tid + rep * 256;
            int row = idx >> 2;
            int ch  = idx & 3;
            size_t go = (size_t)(bn + row) * K + kt + ch * 8;
            cp16(sbase + G_B + sw(row, ch), B + go);
        }
    };

    #pragma unroll
    for (int s = 0; s < STAGES - 1; s++) {
        load_stage(s, s * 32);
        asm volatile("cp.async.commit_group;\n");
    }

    for (int it = 0; it < kiters; ++it) {
        asm volatile("cp.async.wait_group %0;\n" :: "n"(STAGES - 2));
        __syncthreads();
        int pf = it + STAGES - 1;
        if (pf < kiters) load_stage(pf % STAGES, pf * 32);
        asm volatile("cp.async.commit_group;\n");

        const uint32_t sb = smem_u + (it % STAGES) * G_STAGE;

        #pragma unroll
        for (int kf = 0; kf < 2; kf++) {
            // hoist ALL operand fragments into distinct registers (no WAR reuse)
            uint32_t ah[4][4], bf[4][4];
            #pragma unroll
            for (int mt = 0; mt < 4; mt++) {
                uint32_t row = wm * 64 + mt * 16 + (lane & 15);
                uint32_t ch  = kf * 2 + (lane >> 4);
                ldm4(ah[mt], sb + G_A + sw(row, ch));
            }
            #pragma unroll
            for (int p = 0; p < 4; p++) {
                uint32_t rowb = wn * 64 + p * 16 + (lane & 7) + ((lane >> 4) & 1) * 8;
                uint32_t chb  = kf * 2 + ((lane >> 3) & 1);
                ldm4(bf[p], sb + G_B + sw(rowb, chb));
            }
            // unbroken 32-mma burst; per-acc K-order identical to R14
            #pragma unroll
            for (int p = 0; p < 4; p++)
                #pragma unroll
                for (int mt = 0; mt < 4; mt++) {
                    mma16816h(acc[mt][2 * p],     ah[mt], bf[p]);
                    mma16816h(acc[mt][2 * p + 1], ah[mt], bf[p] + 2);
                }
        }
    }

    // ---- epilogue ----
    const int rb = bm + wm * 64;
    const int cb = bn + wn * 64;
    #pragma unroll
    for (int mt = 0; mt < 4; mt++)
        #pragma unroll
        for (int nt = 0; nt < 8; nt++) {
            int r0 = rb + mt * 16 + (lane >> 2);
            int r1 = r0 + 8;
            int c  = cb + nt * 8 + (lane & 3) * 2;
            if (mode == 0) {
                size_t i0 = (size_t)r0 * N + c;
                size_t i1 = (size_t)r1 * N + c;
                float2 v0 = make_float2(acc[mt][nt][0], acc[mt][nt][1]);
                float2 v1 = make_float2(acc[mt][nt][2], acc[mt][nt][3]);
                if (R) {
                    float2 q0 = *(const float2*)(R + i0);
                    float2 q1 = *(const float2*)(R + i1);
                    v0.x += q0.x; v0.y += q0.y;
                    v1.x += q1.x; v1.y += q1.y;
                }
                *(float2*)(C + i0) = v0;
                *(float2*)(C + i1) = v1;
            } else if (mode == 2) {
                if (bn < 2048) {
                    int i = (c & 127) >> 1;
                    float2 cs0 = tab[(size_t)r0 * 64 + i];
                    float2 cs1 = tab[(size_t)r1 * 64 + i];
                    float a0 = acc[mt][nt][0], b0 = acc[mt][nt][1];
                    float a1 = acc[mt][nt][2], b1 = acc[mt][nt][3];
                    size_t i0 = (size_t)r0 * Cn + c;
                    size_t i1 = (size_t)r1 * Cn + c;
                    *(uint32_t*)(Qp + i0) = pack_h2(
                        __float2half(fmaf(a0, cs0.x, -b0 * cs0.y)),
                        __float2half(fmaf(a0, cs0.y,  b0 * cs0.x)));
                    *(uint32_t*)(Qp + i1) = pack_h2(
                        __float2half(fmaf(a1, cs1.x, -b1 * cs1.y)),
                        __float2half(fmaf(a1, cs1.y,  b1 * cs1.x)));
                } else if (bn < 2560) {
                    int ck = c - 2048;
                    int i = (ck & 127) >> 1;
                    float2 cs0 = tab[(size_t)r0 * 64 + i];
                    float2 cs1 = tab[(size_t)r1 * 64 + i];
                    float a0 = acc[mt][nt][0], b0 = acc[mt][nt][1];
                    float a1 = acc[mt][nt][2], b1 = acc[mt][nt][3];
                    size_t i0 = (size_t)r0 * (NKV * HD) + ck;
                    size_t i1 = (size_t)r1 * (NKV * HD) + ck;
                    *(uint32_t*)(Kp + i0) = pack_h2(
                        __float2half(fmaf(a0, cs0.x, -b0 * cs0.y)),
                        __float2half(fmaf(a0, cs0.y,  b0 * cs0.x)));
                    *(uint32_t*)(Kp + i1) = pack_h2(
                        __float2half(fmaf(a1, cs1.x, -b1 * cs1.y)),
                        __float2half(fmaf(a1, cs1.y,  b1 * cs1.x)));
                } else {
                    int cv = c - 2560;
                    size_t i0 = (size_t)r0 * (NKV * HD) + cv;
                    size_t i1 = (size_t)r1 * (NKV * HD) + cv;
                    *(uint32_t*)(Vp + i0) = pack_h2(__float2half(acc[mt][nt][0]),
                                                    __float2half(acc[mt][nt][1]));
                    *(uint32_t*)(Vp + i1) = pack_h2(__float2half(acc[mt][nt][2]),
                                                    __float2half(acc[mt][nt][3]));
                }
            } else {
                int gcol = c >> 1;
                float ga0 = acc[mt][nt][0], up0 = acc[mt][nt][1];
                float ga1 = acc[mt][nt][2], up1 = acc[mt][nt][3];
                O[(size_t)r0 * FFN + gcol] = __float2half(ga0 / (1.f + expf(-ga0)) * up0);
                O[(size_t)r1 * FFN + gcol] = __float2half(ga1 / (1.f + expf(-ga1)) * up1);
            }
        }
}

// =====================================================================
// Tensor-core causal flash attention — single fp16 (unchanged R14)
// =====================================================================
#define AQ    0
#define AKV   32768
#define AKV_STAGE 32768
#define AV    16384
#define ATTN_SMEM (AKV + 2 * AKV_STAGE)

__device__ __forceinline__ uint32_t sw256(uint32_t row, uint32_t ch) {
    return (row << 8) + ((((ch ^ row) & 7u) | (ch & 8u)) << 4);
}

__global__ void __launch_bounds__(256, 1) attn_tc(
        const fp16* __restrict__ q, const fp16* __restrict__ k,
        const fp16* __restrict__ v, fp16* __restrict__ y) {
    extern __shared__ __align__(128) char smem_raw[];
    const uint32_t sb = (uint32_t)__cvta_generic_to_shared(smem_raw);
    const int qt   = 31 - blockIdx.x;
    const int head = blockIdx.y;
    const int kvh  = head >> 2;
    const int qb   = qt * 128;
    const int tid  = threadIdx.x;
    const int warp = tid >> 5;
    const int lane = tid & 31;
    const int njt  = 2 * qt + 2;

    #pragma unroll
    for (int i = 0; i < 8; i++) {
        int idx = tid + i * 256;
        int row = idx >> 4;
        int ch  = idx & 15;
        size_t g = (size_t)(qb + row) * Cn + head * HD + ch * 8;
        cp16(sb + AQ + sw256(row, ch), q + g);
    }

    auto load_kv = [&](int jt, int buf) {
        const uint32_t base = sb + AKV + buf * AKV_STAGE;
        #pragma unroll
        for (int i = 0; i < 4; i++) {
            int idx = tid + i * 256;
            int row = idx >> 4;
            int ch  = idx & 15;
            size_t g = (size_t)(jt * 64 + row) * (NKV * HD) + kvh * HD + ch * 8;
            uint32_t off = sw256(row, ch);
            cp16(base + off,      k + g);
            cp16(base + AV + off, v + g);
        }
    };

    load_kv(0, 0);
    asm volatile("cp.async.commit_group;\n");

    float m0 = -1e30f, m1 = -1e30f, l0 = 0.f, l1 = 0.f;
    float o[16][4];
    #pragma unroll
    for (int nt = 0; nt < 16; nt++)
        #pragma unroll
        for (int e = 0; e < 4; e++) o[nt][e] = 0.f;

    const float cs = 0.12751743621340608f;
    const int r0g = qb + (warp << 4) + (lane >> 2);
    const int r1g = r0g + 8;

    for (int jt = 0; jt < njt; jt++) {
        if (jt + 1 < njt) load_kv(jt + 1, (jt + 1) & 1);
        asm volatile("cp.async.commit_group;\n");
        asm volatile("cp.async.wait_group 1;\n");
        __syncthreads();

        const uint32_t kb = sb + AKV + (jt & 1) * AKV_STAGE;
        const uint32_t vb = kb + AV;

        float sacc[8][4];
        #pragma unroll
        for (int nt = 0; nt < 8; nt++)
            #pragma unroll
            for (int e = 0; e < 4; e++) sacc[nt][e] = 0.f;

        #pragma unroll
        for (int ks = 0; ks < 8; ks++) {
            uint32_t ah[4];
            {
                uint32_t row = (warp << 4) + (lane & 15);
                uint32_t ch  = ks * 2 + (lane >> 4);
                ldm4(ah, sb + AQ + sw256(row, ch));
            }
            #pragma unroll
            for (int p = 0; p < 4; p++) {
                uint32_t rowb = p * 16 + (lane & 7) + ((lane >> 4) & 1) * 8;
                uint32_t chb  = ks * 2 + ((lane >> 3) & 1);
                uint32_t bfr[4];
                ldm4(bfr, kb + sw256(rowb, chb));
                mma16816h(sacc[2 * p],     ah, bfr);
                mma16816h(sacc[2 * p + 1], ah, bfr + 2);
            }
        }

        const bool domask = (jt >= 2 * qt);
        #pragma unroll
        for (int nt = 0; nt < 8; nt++) {
            int cbase = jt * 64 + nt * 8 + (lane & 3) * 2;
            #pragma unroll
            for (int e = 0; e < 4; e++) {
                float vv = sacc[nt][e] * cs;
                if (domask) {
                    int col = cbase + (e & 1);
                    int row = (e < 2) ? r0g : r1g;
                    if (col > row) vv = -1e30f;
                }
                sacc[nt][e] = vv;
            }
        }

        float mx0 = -1e30f, mx1 = -1e30f;
        #pragma unroll
        for (int nt = 0; nt < 8; nt++) {
            mx0 = fmaxf(mx0, fmaxf(sacc[nt][0], sacc[nt][1]));
            mx1 = fmaxf(mx1, fmaxf(sacc[nt][2], sacc[nt][3]));
        }
        mx0 = fmaxf(mx0, __shfl_xor_sync(0xffffffffu, mx0, 1));
        mx0 = fmaxf(mx0, __shfl_xor_sync(0xffffffffu, mx0, 2));
        mx1 = fmaxf(mx1, __shfl_xor_sync(0xffffffffu, mx1, 1));
        mx1 = fmaxf(mx1, __shfl_xor_sync(0xffffffffu, mx1, 2));
        float mn0 = fmaxf(m0, mx0);
        float mn1 = fmaxf(m1, mx1);

        float ls0 = 0.f, ls1 = 0.f;
        #pragma unroll
        for (int nt = 0; nt < 8; nt++) {
            float p0 = exp2f(sacc[nt][0] - mn0);
            float p1 = exp2f(sacc[nt][1] - mn0);
            float p2 = exp2f(sacc[nt][2] - mn1);
            float p3 = exp2f(sacc[nt][3] - mn1);
            ls0 += p0 + p1;
            ls1 += p2 + p3;
            sacc[nt][0] = p0; sacc[nt][1] = p1; sacc[nt][2] = p2; sacc[nt][3] = p3;
        }
        ls0 += __shfl_xor_sync(0xffffffffu, ls0, 1);
        ls0 += __shfl_xor_sync(0xffffffffu, ls0, 2);
        ls1 += __shfl_xor_sync(0xffffffffu, ls1, 1);
        ls1 += __shfl_xor_sync(0xffffffffu, ls1, 2);

        float a0 = exp2f(m0 - mn0);
        float a1 = exp2f(m1 - mn1);
        m0 = mn0; m1 = mn1;
        l0 = l0 * a0 + ls0;
        l1 = l1 * a1 + ls1;
        #pragma unroll
        for (int nt = 0; nt < 16; nt++) {
            o[nt][0] *= a0; o[nt][1] *= a0;
            o[nt][2] *= a1; o[nt][3] *= a1;
        }

        #pragma unroll
        for (int ks = 0; ks < 4; ks++) {
            uint32_t ah[4];
            ah[0] = pack_h2(__float2half(sacc[2 * ks][0]),     __float2half(sacc[2 * ks][1]));
            ah[1] = pack_h2(__float2half(sacc[2 * ks][2]),     __float2half(sacc[2 * ks][3]));
            ah[2] = pack_h2(__float2half(sacc[2 * ks + 1][0]), __float2half(sacc[2 * ks + 1][1]));
            ah[3] = pack_h2(__float2half(sacc[2 * ks + 1][2]), __float2half(sacc[2 * ks + 1][3]));

            #pragma unroll
            for (int dq = 0; dq < 4; dq++) {
                uint32_t row = ks * 16 + (lane & 15);
                uint32_t ch0 = (2 * dq) * 2 + (lane >> 4);
                uint32_t ch1 = (2 * dq + 1) * 2 + (lane >> 4);
                uint32_t b0[4], b1[4];
                ldm4t(b0, vb + sw256(row, ch0));
                ldm4t(b1, vb + sw256(row, ch1));
                mma16816h(o[4 * dq + 0], ah, b0);
                mma16816h(o[4 * dq + 1], ah, b0 + 2);
                mma16816h(o[4 * dq + 2], ah, b1);
                mma16816h(o[4 * dq + 3], ah, b1 + 2);
            }
        }
        __syncthreads();
    }

    float inv0 = 1.0f / l0;
    float inv1 = 1.0f / l1;
    #pragma unroll
    for (int nt = 0; nt < 16; nt++) {
        int c = head * HD + nt * 8 + (lane & 3) * 2;
        size_t i0 = (size_t)r0g * Cn + c;
        size_t i1 = (size_t)r1g * Cn + c;
        *(uint32_t*)(y + i0) = pack_h2(__float2half(o[nt][0] * inv0),
                                       __float2half(o[nt][1] * inv0));
        *(uint32_t*)(y + i1) = pack_h2(__float2half(o[nt][2] * inv1),
                                       __float2half(o[nt][3] * inv1));
    }
}

// ---------------- launch ----------------
extern "C" void kernel_launch(void* const* d_in, const int* in_sizes, int n_in,
                              void* d_out, int out_size) {
    (void)in_sizes; (void)n_in; (void)out_size;
    const float* x           = (const float*)d_in[0];
    const float* attn_norm_w = (const float*)d_in[2];
    const float* wq          = (const float*)d_in[3];
    const float* wk          = (const float*)d_in[4];
    const float* wv          = (const float*)d_in[5];
    const float* wo          = (const float*)d_in[6];
    const float* ffn_norm_w  = (const float*)d_in[7];
    const float* w_gate      = (const float*)d_in[8];
    const float* w_up        = (const float*)d_in[9];
    const float* w_down      = (const float*)d_in[10];
    float* out = (float*)d_out;

    float2* rtab;
    fp16 *h, *h2, *y, *gs, *qp, *kp, *vp;
    fp16 *wqkv_h, *wo_h, *wgu_h, *wd_h;

    cudaGetSymbolAddress((void**)&rtab, g_rope);
    cudaGetSymbolAddress((void**)&h,  g_h);
    cudaGetSymbolAddress((void**)&h2, g_h2);
    cudaGetSymbolAddress((void**)&y,  g_y);
    cudaGetSymbolAddress((void**)&gs, g_gs);
    cudaGetSymbolAddress((void**)&qp, g_qh);
    cudaGetSymbolAddress((void**)&kp, g_kh);
    cudaGetSymbolAddress((void**)&vp, g_vh);
    cudaGetSymbolAddress((void**)&wqkv_h, g_wqkv_h);
    cudaGetSymbolAddress((void**)&wo_h, g_wo_h);
    cudaGetSymbolAddress((void**)&wgu_h, g_wgu_h);
    cudaGetSymbolAddress((void**)&wd_h, g_wd_h);

    cudaFuncSetAttribute(gemm_fp16, cudaFuncAttributeMaxDynamicSharedMemorySize, GEMM_SMEM);
    cudaFuncSetAttribute(attn_tc, cudaFuncAttributeMaxDynamicSharedMemorySize, ATTN_SMEM);

    #define CONVW(src, dst, n) \
        convert_w_kernel<<<((n) / 16 + 255) / 256, 256>>>(src, dst, n)
    #define GEMM0(Aa, Bw, Cp, Rp, Mm, Nn, Kk) \
        gemm_fp16<<<dim3((Nn) / 256, (Mm) / 128), 256, GEMM_SMEM>>>( \
            Aa, Bw, Cp, Rp, nullptr, nullptr, nullptr, nullptr, nullptr, 0, Mm, Nn, Kk)

    rope_table_kernel<<<(Tn * 64 + 255) / 256, 256>>>(rtab);
    rmsnorm_kernel<<<Tn, 256>>>(x, attn_norm_w, h);
    CONVW(wq, wqkv_h, Cn * Cn);
    CONVW(wk, wqkv_h + (size_t)Cn * Cn, NKV * HD * Cn);
    CONVW(wv, wqkv_h + (size_t)(Cn + NKV * HD) * Cn, NKV * HD * Cn);
    // merged QKV GEMM with RoPE epilogue -> q/k/v single fp16
    gemm_fp16<<<dim3((Cn + 2 * NKV * HD) / 256, Tn / 128), 256, GEMM_SMEM>>>(
        h, wqkv_h, nullptr, nullptr, nullptr,
        rtab, qp, kp, vp, 2, Tn, Cn + 2 * NKV * HD, Cn);
    // attention -> y
    attn_tc<<<dim3(32, NH), 256, ATTN_SMEM>>>(qp, kp, vp, y);
    // out = x + y @ wo^T
    CONVW(wo, wo_h, Cn * Cn);
    GEMM0(y, wo_h, out, x, Tn, Cn, Cn);
    // rmsnorm2
    rmsnorm_kernel<<<Tn, 256>>>(out, ffn_norm_w, h2);
    // gate+up converted in one pass (interleaved); fused silu(gate)*up GEMM
    convert_w_gu_kernel<<<((FFN * Cn) / 8 + 255) / 256, 256>>>(w_gate, w_up, wgu_h, FFN * Cn);
    gemm_fp16<<<dim3((2 * FFN) / 256, Tn / 128), 256, GEMM_SMEM>>>(
        h2, wgu_h, nullptr, nullptr, gs,
        nullptr, nullptr, nullptr, nullptr, 3, Tn, 2 * FFN, Cn);
    // out += gs @ w_down^T
    CONVW(w_down, wd_h, Cn * FFN);
    GEMM0(gs, wd_h, out, out, Tn, Cn, FFN);

    #undef CONVW
    #undef GEMM0
}

// round 16
// speedup vs baseline: 8.3072x; 1.0088x over previous
#include <cuda_runtime.h>
#include <cuda_fp16.h>
#include <math.h>
#include <stdint.h>

#define Tn   4096
#define Cn   2048
#define NH   16
#define NKV  4
#define HD   128
#define FFN  8192

typedef __half fp16;

// ---------------- scratch (static device globals; no allocation) ----------------
static __device__ float2 g_rope[Tn * 64];

static __device__ fp16 g_h  [Tn * Cn];
static __device__ fp16 g_h2 [Tn * Cn];
static __device__ fp16 g_y  [Tn * Cn];
static __device__ fp16 g_gs [Tn * FFN];

static __device__ fp16 g_qh[Tn * Cn];
static __device__ fp16 g_kh[Tn * NKV * HD];
static __device__ fp16 g_vh[Tn * NKV * HD];

static __device__ fp16 g_wqkv_h[(Cn + 2 * NKV * HD) * Cn];  // rows: wq | wk | wv
static __device__ fp16 g_wo_h[Cn * Cn];
static __device__ fp16 g_wgu_h[2 * FFN * Cn];               // interleaved: 2j = wg[j], 2j+1 = wu[j]
static __device__ fp16 g_wd_h[Cn * FFN];

__device__ __forceinline__ uint32_t pack_h2(fp16 a, fp16 b) {
    __half2 t; t.x = a; t.y = b;
    return *reinterpret_cast<uint32_t*>(&t);
}

// ---------------- common PTX helpers ----------------
__device__ __forceinline__ void cp16(uint32_t dst, const void* src) {
    asm volatile("cp.async.cg.shared.global [%0], [%1], 16;\n" :: "r"(dst), "l"(src));
}
__device__ __forceinline__ void ldm4(uint32_t* r, uint32_t addr) {
    asm volatile("ldmatrix.sync.aligned.m8n8.x4.shared.b16 {%0,%1,%2,%3}, [%4];\n"
                 : "=r"(r[0]), "=r"(r[1]), "=r"(r[2]), "=r"(r[3]) : "r"(addr));
}
__device__ __forceinline__ void ldm4t(uint32_t* r, uint32_t addr) {
    asm volatile("ldmatrix.sync.aligned.m8n8.x4.trans.shared.b16 {%0,%1,%2,%3}, [%4];\n"
                 : "=r"(r[0]), "=r"(r[1]), "=r"(r[2]), "=r"(r[3]) : "r"(addr));
}
__device__ __forceinline__ void mma16816h(float* c, const uint32_t* a, const uint32_t* b) {
    asm volatile("mma.sync.aligned.m16n8k16.row.col.f32.f16.f16.f32 "
                 "{%0,%1,%2,%3},{%4,%5,%6,%7},{%8,%9},{%0,%1,%2,%3};\n"
                 : "+f"(c[0]), "+f"(c[1]), "+f"(c[2]), "+f"(c[3])
                 : "r"(a[0]), "r"(a[1]), "r"(a[2]), "r"(a[3]), "r"(b[0]), "r"(b[1]));
}

// ---------------- mega weight convert: all 7 weight arrays, one launch ----------------
// segment offsets (elements)
#define SOFF_WQ 0u
#define SOFF_WK 4194304u
#define SOFF_WV 5242880u
#define SOFF_WO 6291456u
#define SOFF_WG 10485760u
#define SOFF_WU 27262976u
#define SOFF_WD 44040192u
#define SOFF_END 60817408u
// total threads = SOFF_END/16 = 3,801,088 -> 14,848 blocks x 256

__device__ __forceinline__ void conv16(const float* __restrict__ s, fp16* __restrict__ d) {
    #pragma unroll
    for (int half = 0; half < 2; half++) {
        float4 a = *(const float4*)(s + half * 8);
        float4 b = *(const float4*)(s + half * 8 + 4);
        uint4 p;
        p.x = pack_h2(__float2half(a.x), __float2half(a.y));
        p.y = pack_h2(__float2half(a.z), __float2half(a.w));
        p.z = pack_h2(__float2half(b.x), __float2half(b.y));
        p.w = pack_h2(__float2half(b.z), __float2half(b.w));
        *(uint4*)(d + half * 8) = p;
    }
}

__global__ void __launch_bounds__(256) mega_convert_kernel(
        const float* __restrict__ wq, const float* __restrict__ wk,
        const float* __restrict__ wv, const float* __restrict__ wo,
        const float* __restrict__ wg, const float* __restrict__ wu,
        const float* __restrict__ wd,
        fp16* __restrict__ wqkv_h, fp16* __restrict__ wo_h,
        fp16* __restrict__ wgu_h,  fp16* __restrict__ wd_h) {
    uint32_t g = (blockIdx.x * blockDim.x + threadIdx.x) * 16u;
    if (g >= SOFF_END) return;
    if (g < SOFF_WK) {
        conv16(wq + g, wqkv_h + g);
    } else if (g < SOFF_WV) {
        conv16(wk + (g - SOFF_WK), wqkv_h + g);      // packed: dst offset == global offset
    } else if (g < SOFF_WO) {
        conv16(wv + (g - SOFF_WV), wqkv_h + g);
    } else if (g < SOFF_WG) {
        uint32_t l = g - SOFF_WO;
        conv16(wo + l, wo_h + l);
    } else if (g < SOFF_WU) {
        uint32_t l = g - SOFF_WG;
        uint32_t row = l / Cn, col = l - row * Cn;   // 16 elems stay in one row (Cn%16==0)
        conv16(wg + l, wgu_h + (size_t)(2 * row) * Cn + col);
    } else if (g < SOFF_WD) {
        uint32_t l = g - SOFF_WU;
        uint32_t row = l / Cn, col = l - row * Cn;
        conv16(wu + l, wgu_h + (size_t)(2 * row + 1) * Cn + col);
    } else {
        uint32_t l = g - SOFF_WD;
        conv16(wd + l, wd_h + l);
    }
}

// ---------------- RoPE cos/sin table (double sincos — fast-math immune) ----------------
__global__ void rope_table_kernel(float2* __restrict__ tab) {
    int idx = blockIdx.x * blockDim.x + threadIdx.x;
    if (idx >= Tn * 64) return;
    int i = idx & 63;
    int t = idx >> 6;
    double invf_d = pow(500000.0, -((double)(2 * i) / 128.0));
    float  invf_f = (float)invf_d;
    float  ang_f  = (float)t * invf_f;
    double c, s;
    sincos((double)ang_f, &s, &c);
    tab[idx] = make_float2((float)c, (float)s);
}

// ---------------- rmsnorm: one block per row, writes single fp16 ----------------
__global__ void __launch_bounds__(256) rmsnorm_kernel(const float* __restrict__ x,
                                                      const float* __restrict__ w,
                                                      fp16* __restrict__ o) {
    const int row = blockIdx.x;
    const float* xr = x + (size_t)row * Cn;
    float s = 0.f;
    for (int i = threadIdx.x; i < Cn; i += 256) {
        float v = xr[i];
        s = fmaf(v, v, s);
    }
    __shared__ float red[8];
    #pragma unroll
    for (int o2 = 16; o2; o2 >>= 1) s += __shfl_xor_sync(0xffffffffu, s, o2);
    if ((threadIdx.x & 31) == 0) red[threadIdx.x >> 5] = s;
    __syncthreads();
    if (threadIdx.x < 32) {
        float v = (threadIdx.x < 8) ? red[threadIdx.x] : 0.f;
        #pragma unroll
        for (int o2 = 4; o2; o2 >>= 1) v += __shfl_xor_sync(0xffffffffu, v, o2);
        if (threadIdx.x == 0) red[0] = v;
    }
    __syncthreads();
    const float scale = rsqrtf(red[0] * (1.0f / Cn) + 1e-5f);
    size_t base = (size_t)row * Cn;
    for (int i = threadIdx.x; i < Cn; i += 256)
        o[base + i] = __float2half(xr[i] * scale * w[i]);
}

// =====================================================================
// fp16 tensor-core GEMM (R15 core, unchanged)
// mode 0: C = acc (+R); mode 2: QKV epilogue; mode 3: silu(gate)*up
// =====================================================================
#define STAGES 5
#define G_A   0
#define G_B   8192
#define G_STAGE 24576
#define GEMM_SMEM (STAGES * G_STAGE)

__device__ __forceinline__ uint32_t sw(uint32_t row, uint32_t chunk) {
    return (row << 6) + (((chunk ^ (row >> 1)) & 3u) << 4);
}

__global__ void __launch_bounds__(256, 1) gemm_fp16(
        const fp16* __restrict__ A, const fp16* __restrict__ B,
        float* __restrict__ C, const float* __restrict__ R,
        fp16* __restrict__ O,
        const float2* __restrict__ tab,
        fp16* __restrict__ Qp, fp16* __restrict__ Kp, fp16* __restrict__ Vp,
        int mode, int M, int N, int K) {
    extern __shared__ __align__(128) char smem_raw[];
    const uint32_t smem_u = (uint32_t)__cvta_generic_to_shared(smem_raw);
    const int tid  = threadIdx.x;
    const int warp = tid >> 5;
    const int lane = tid & 31;
    const int wm   = warp & 1;
    const int wn   = warp >> 1;

    int bx, by;
    {
        int tiles_n = gridDim.x, tiles_m = gridDim.y;
        int lin = blockIdx.y * tiles_n + blockIdx.x;
        int per = 8 * tiles_n;
        int gid = lin / per, rem = lin % per;
        int gm  = tiles_m - gid * 8;
        if (gm > 8) gm = 8;
        by = gid * 8 + rem % gm;
        bx = rem / gm;
    }
    const int bm = by * 128;
    const int bn = bx * 256;

    float acc[4][8][4];
    #pragma unroll
    for (int i = 0; i < 4; i++)
        #pragma unroll
        for (int j = 0; j < 8; j++)
            #pragma unroll
            for (int v = 0; v < 4; v++) acc[i][j][v] = 0.f;

    const int kiters = K >> 5;

    auto load_stage = [&](int stage, int kt) {
        const uint32_t sbase = smem_u + stage * G_STAGE;
        #pragma unroll
        for (int rep = 0; rep < 2; rep++) {
            int idx = tid + rep * 256;
            int row = idx >> 2;
            int ch  = idx & 3;
            size_t go = (size_t)(bm + row) * K + kt + ch * 8;
            cp16(sbase + G_A + sw(row, ch), A + go);
        }
        #pragma unroll
        for (int rep = 0; rep < 4; rep++) {
            int idx = tid + rep * 256;
            int row = idx >> 2;
            int ch  = idx & 3;
            size_t go = (size_t)(bn + row) * K + kt + ch * 8;
            cp16(sbase + G_B + sw(row, ch), B + go);
        }
    };

    #pragma unroll
    for (int s = 0; s < STAGES - 1; s++) {
        load_stage(s, s * 32);
        asm volatile("cp.async.commit_group;\n");
    }

    for (int it = 0; it < kiters; ++it) {
        asm volatile("cp.async.wait_group %0;\n" :: "n"(STAGES - 2));
        __syncthreads();
        int pf = it + STAGES - 1;
        if (pf < kiters) load_stage(pf % STAGES, pf * 32);
        asm volatile("cp.async.commit_group;\n");

        const uint32_t sb = smem_u + (it % STAGES) * G_STAGE;

        #pragma unroll
        for (int kf = 0; kf < 2; kf++) {
            uint32_t ah[4][4], bf[4][4];
            #pragma unroll
            for (int mt = 0; mt < 4; mt++) {
                uint32_t row = wm * 64 + mt * 16 + (lane & 15);
                uint32_t ch  = kf * 2 + (lane >> 4);
                ldm4(ah[mt], sb + G_A + sw(row, ch));
            }
            #pragma unroll
            for (int p = 0; p < 4; p++) {
                uint32_t rowb = wn * 64 + p * 16 + (lane & 7) + ((lane >> 4) & 1) * 8;
                uint32_t chb  = kf * 2 + ((lane >> 3) & 1);
                ldm4(bf[p], sb + G_B + sw(rowb, chb));
            }
            #pragma unroll
            for (int p = 0; p < 4; p++)
                #pragma unroll
                for (int mt = 0; mt < 4; mt++) {
                    mma16816h(acc[mt][2 * p],     ah[mt], bf[p]);
                    mma16816h(acc[mt][2 * p + 1], ah[mt], bf[p] + 2);
                }
        }
    }

    // ---- epilogue ----
    const int rb = bm + wm * 64;
    const int cb = bn + wn * 64;
    #pragma unroll
    for (int mt = 0; mt < 4; mt++)
        #pragma unroll
        for (int nt = 0; nt < 8; nt++) {
            int r0 = rb + mt * 16 + (lane >> 2);
            int r1 = r0 + 8;
            int c  = cb + nt * 8 + (lane & 3) * 2;
            if (mode == 0) {
                size_t i0 = (size_t)r0 * N + c;
                size_t i1 = (size_t)r1 * N + c;
                float2 v0 = make_float2(acc[mt][nt][0], acc[mt][nt][1]);
                float2 v1 = make_float2(acc[mt][nt][2], acc[mt][nt][3]);
                if (R) {
                    float2 q0 = *(const float2*)(R + i0);
                    float2 q1 = *(const float2*)(R + i1);
                    v0.x += q0.x; v0.y += q0.y;
                    v1.x += q1.x; v1.y += q1.y;
                }
                *(float2*)(C + i0) = v0;
                *(float2*)(C + i1) = v1;
            } else if (mode == 2) {
                if (bn < 2048) {
                    int i = (c & 127) >> 1;
                    float2 cs0 = tab[(size_t)r0 * 64 + i];
                    float2 cs1 = tab[(size_t)r1 * 64 + i];
                    float a0 = acc[mt][nt][0], b0 = acc[mt][nt][1];
                    float a1 = acc[mt][nt][2], b1 = acc[mt][nt][3];
                    size_t i0 = (size_t)r0 * Cn + c;
                    size_t i1 = (size_t)r1 * Cn + c;
                    *(uint32_t*)(Qp + i0) = pack_h2(
                        __float2half(fmaf(a0, cs0.x, -b0 * cs0.y)),
                        __float2half(fmaf(a0, cs0.y,  b0 * cs0.x)));
                    *(uint32_t*)(Qp + i1) = pack_h2(
                        __float2half(fmaf(a1, cs1.x, -b1 * cs1.y)),
                        __float2half(fmaf(a1, cs1.y,  b1 * cs1.x)));
                } else if (bn < 2560) {
                    int ck = c - 2048;
                    int i = (ck & 127) >> 1;
                    float2 cs0 = tab[(size_t)r0 * 64 + i];
                    float2 cs1 = tab[(size_t)r1 * 64 + i];
                    float a0 = acc[mt][nt][0], b0 = acc[mt][nt][1];
                    float a1 = acc[mt][nt][2], b1 = acc[mt][nt][3];
                    size_t i0 = (size_t)r0 * (NKV * HD) + ck;
                    size_t i1 = (size_t)r1 * (NKV * HD) + ck;
                    *(uint32_t*)(Kp + i0) = pack_h2(
                        __float2half(fmaf(a0, cs0.x, -b0 * cs0.y)),
                        __float2half(fmaf(a0, cs0.y,  b0 * cs0.x)));
                    *(uint32_t*)(Kp + i1) = pack_h2(
                        __float2half(fmaf(a1, cs1.x, -b1 * cs1.y)),
                        __float2half(fmaf(a1, cs1.y,  b1 * cs1.x)));
                } else {
                    int cv = c - 2560;
                    size_t i0 = (size_t)r0 * (NKV * HD) + cv;
                    size_t i1 = (size_t)r1 * (NKV * HD) + cv;
                    *(uint32_t*)(Vp + i0) = pack_h2(__float2half(acc[mt][nt][0]),
                                                    __float2half(acc[mt][nt][1]));
                    *(uint32_t*)(Vp + i1) = pack_h2(__float2half(acc[mt][nt][2]),
                                                    __float2half(acc[mt][nt][3]));
                }
            } else {
                int gcol = c >> 1;
                float ga0 = acc[mt][nt][0], up0 = acc[mt][nt][1];
                float ga1 = acc[mt][nt][2], up1 = acc[mt][nt][3];
                O[(size_t)r0 * FFN + gcol] = __float2half(ga0 / (1.f + expf(-ga0)) * up0);
                O[(size_t)r1 * FFN + gcol] = __float2half(ga1 / (1.f + expf(-ga1)) * up1);
            }
        }
}

// =====================================================================
// Tensor-core causal flash attention — single fp16 (unchanged R14/R15)
// =====================================================================
#define AQ    0
#define AKV   32768
#define AKV_STAGE 32768
#define AV    16384
#define ATTN_SMEM (AKV + 2 * AKV_STAGE)

__device__ __forceinline__ uint32_t sw256(uint32_t row, uint32_t ch) {
    return (row << 8) + ((((ch ^ row) & 7u) | (ch & 8u)) << 4);
}

__global__ void __launch_bounds__(256, 1) attn_tc(
        const fp16* __restrict__ q, const fp16* __restrict__ k,
        const fp16* __restrict__ v, fp16* __restrict__ y) {
    extern __shared__ __align__(128) char smem_raw[];
    const uint32_t sb = (uint32_t)__cvta_generic_to_shared(smem_raw);
    const int qt   = 31 - blockIdx.x;
    const int head = blockIdx.y;
    const int kvh  = head >> 2;
    const int qb   = qt * 128;
    const int tid  = threadIdx.x;
    const int warp = tid >> 5;
    const int lane = tid & 31;
    const int njt  = 2 * qt + 2;

    #pragma unroll
    for (int i = 0; i < 8; i++) {
        int idx = tid + i * 256;
        int row = idx >> 4;
        int ch  = idx & 15;
        size_t g = (size_t)(qb + row) * Cn + head * HD + ch * 8;
        cp16(sb + AQ + sw256(row, ch), q + g);
    }

    auto load_kv = [&](int jt, int buf) {
        const uint32_t base = sb + AKV + buf * AKV_STAGE;
        #pragma unroll
        for (int i = 0; i < 4; i++) {
            int idx = tid + i * 256;
            int row = idx >> 4;
            int ch  = idx & 15;
            size_t g = (size_t)(jt * 64 + row) * (NKV * HD) + kvh * HD + ch * 8;
            uint32_t off = sw256(row, ch);
            cp16(base + off,      k + g);
            cp16(base + AV + off, v + g);
        }
    };

    load_kv(0, 0);
    asm volatile("cp.async.commit_group;\n");

    float m0 = -1e30f, m1 = -1e30f, l0 = 0.f, l1 = 0.f;
    float o[16][4];
    #pragma unroll
    for (int nt = 0; nt < 16; nt++)
        #pragma unroll
        for (int e = 0; e < 4; e++) o[nt][e] = 0.f;

    const float cs = 0.12751743621340608f;
    const int r0g = qb + (warp << 4) + (lane >> 2);
    const int r1g = r0g + 8;

    for (int jt = 0; jt < njt; jt++) {
        if (jt + 1 < njt) load_kv(jt + 1, (jt + 1) & 1);
        asm volatile("cp.async.commit_group;\n");
        asm volatile("cp.async.wait_group 1;\n");
        __syncthreads();

        const uint32_t kb = sb + AKV + (jt & 1) * AKV_STAGE;
        const uint32_t vb = kb + AV;

        float sacc[8][4];
        #pragma unroll
        for (int nt = 0; nt < 8; nt++)
            #pragma unroll
            for (int e = 0; e < 4; e++) sacc[nt][e] = 0.f;

        #pragma unroll
        for (int ks = 0; ks < 8; ks++) {
            uint32_t ah[4];
            {
                uint32_t row = (warp << 4) + (lane & 15);
                uint32_t ch  = ks * 2 + (lane >> 4);
                ldm4(ah, sb + AQ + sw256(row, ch));
            }
            #pragma unroll
            for (int p = 0; p < 4; p++) {
                uint32_t rowb = p * 16 + (lane & 7) + ((lane >> 4) & 1) * 8;
                uint32_t chb  = ks * 2 + ((lane >> 3) & 1);
                uint32_t bfr[4];
                ldm4(bfr, kb + sw256(rowb, chb));
                mma16816h(sacc[2 * p],     ah, bfr);
                mma16816h(sacc[2 * p + 1], ah, bfr + 2);
            }
        }

        const bool domask = (jt >= 2 * qt);
        #pragma unroll
        for (int nt = 0; nt < 8; nt++) {
            int cbase = jt * 64 + nt * 8 + (lane & 3) * 2;
            #pragma unroll
            for (int e = 0; e < 4; e++) {
                float vv = sacc[nt][e] * cs;
                if (domask) {
                    int col = cbase + (e & 1);
                    int row = (e < 2) ? r0g : r1g;
                    if (col > row) vv = -1e30f;
                }
                sacc[nt][e] = vv;
            }
        }

        float mx0 = -1e30f, mx1 = -1e30f;
        #pragma unroll
        for (int nt = 0; nt < 8; nt++) {
            mx0 = fmaxf(mx0, fmaxf(sacc[nt][0], sacc[nt][1]));
            mx1 = fmaxf(mx1, fmaxf(sacc[nt][2], sacc[nt][3]));
        }
        mx0 = fmaxf(mx0, __shfl_xor_sync(0xffffffffu, mx0, 1));
        mx0 = fmaxf(mx0, __shfl_xor_sync(0xffffffffu, mx0, 2));
        mx1 = fmaxf(mx1, __shfl_xor_sync(0xffffffffu, mx1, 1));
        mx1 = fmaxf(mx1, __shfl_xor_sync(0xffffffffu, mx1, 2));
        float mn0 = fmaxf(m0, mx0);
        float mn1 = fmaxf(m1, mx1);

        float ls0 = 0.f, ls1 = 0.f;
        #pragma unroll
        for (int nt = 0; nt < 8; nt++) {
            float p0 = exp2f(sacc[nt][0] - mn0);
            float p1 = exp2f(sacc[nt][1] - mn0);
            float p2 = exp2f(sacc[nt][2] - mn1);
            float p3 = exp2f(sacc[nt][3] - mn1);
            ls0 += p0 + p1;
            ls1 += p2 + p3;
            sacc[nt][0] = p0; sacc[nt][1] = p1; sacc[nt][2] = p2; sacc[nt][3] = p3;
        }
        ls0 += __shfl_xor_sync(0xffffffffu, ls0, 1);
        ls0 += __shfl_xor_sync(0xffffffffu, ls0, 2);
        ls1 += __shfl_xor_sync(0xffffffffu, ls1, 1);
        ls1 += __shfl_xor_sync(0xffffffffu, ls1, 2);

        float a0 = exp2f(m0 - mn0);
        float a1 = exp2f(m1 - mn1);
        m0 = mn0; m1 = mn1;
        l0 = l0 * a0 + ls0;
        l1 = l1 * a1 + ls1;
        #pragma unroll
        for (int nt = 0; nt < 16; nt++) {
            o[nt][0] *= a0; o[nt][1] *= a0;
            o[nt][2] *= a1; o[nt][3] *= a1;
        }

        #pragma unroll
        for (int ks = 0; ks < 4; ks++) {
            uint32_t ah[4];
            ah[0] = pack_h2(__float2half(sacc[2 * ks][0]),     __float2half(sacc[2 * ks][1]));
            ah[1] = pack_h2(__float2half(sacc[2 * ks][2]),     __float2half(sacc[2 * ks][3]));
            ah[2] = pack_h2(__float2half(sacc[2 * ks + 1][0]), __float2half(sacc[2 * ks + 1][1]));
            ah[3] = pack_h2(__float2half(sacc[2 * ks + 1][2]), __float2half(sacc[2 * ks + 1][3]));

            #pragma unroll
            for (int dq = 0; dq < 4; dq++) {
                uint32_t row = ks * 16 + (lane & 15);
                uint32_t ch0 = (2 * dq) * 2 + (lane >> 4);
                uint32_t ch1 = (2 * dq + 1) * 2 + (lane >> 4);
                uint32_t b0[4], b1[4];
                ldm4t(b0, vb + sw256(row, ch0));
                ldm4t(b1, vb + sw256(row, ch1));
                mma16816h(o[4 * dq + 0], ah, b0);
                mma16816h(o[4 * dq + 1], ah, b0 + 2);
                mma16816h(o[4 * dq + 2], ah, b1);
                mma16816h(o[4 * dq + 3], ah, b1 + 2);
            }
        }
        __syncthreads();
    }

    float inv0 = 1.0f / l0;
    float inv1 = 1.0f / l1;
    #pragma unroll
    for (int nt = 0; nt < 16; nt++) {
        int c = head * HD + nt * 8 + (lane & 3) * 2;
        size_t i0 = (size_t)r0g * Cn + c;
        size_t i1 = (size_t)r1g * Cn + c;
        *(uint32_t*)(y + i0) = pack_h2(__float2half(o[nt][0] * inv0),
                                       __float2half(o[nt][1] * inv0));
        *(uint32_t*)(y + i1) = pack_h2(__float2half(o[nt][2] * inv1),
                                       __float2half(o[nt][3] * inv1));
    }
}

// ---------------- launch ----------------
extern "C" void kernel_launch(void* const* d_in, const int* in_sizes, int n_in,
                              void* d_out, int out_size) {
    (void)in_sizes; (void)n_in; (void)out_size;
    const float* x           = (const float*)d_in[0];
    const float* attn_norm_w = (const float*)d_in[2];
    const float* wq          = (const float*)d_in[3];
    const float* wk          = (const float*)d_in[4];
    const float* wv          = (const float*)d_in[5];
    const float* wo          = (const float*)d_in[6];
    const float* ffn_norm_w  = (const float*)d_in[7];
    const float* w_gate      = (const float*)d_in[8];
    const float* w_up        = (const float*)d_in[9];
    const float* w_down      = (const float*)d_in[10];
    float* out = (float*)d_out;

    float2* rtab;
    fp16 *h, *h2, *y, *gs, *qp, *kp, *vp;
    fp16 *wqkv_h, *wo_h, *wgu_h, *wd_h;

    cudaGetSymbolAddress((void**)&rtab, g_rope);
    cudaGetSymbolAddress((void**)&h,  g_h);
    cudaGetSymbolAddress((void**)&h2, g_h2);
    cudaGetSymbolAddress((void**)&y,  g_y);
    cudaGetSymbolAddress((void**)&gs, g_gs);
    cudaGetSymbolAddress((void**)&qp, g_qh);
    cudaGetSymbolAddress((void**)&kp, g_kh);
    cudaGetSymbolAddress((void**)&vp, g_vh);
    cudaGetSymbolAddress((void**)&wqkv_h, g_wqkv_h);
    cudaGetSymbolAddress((void**)&wo_h, g_wo_h);
    cudaGetSymbolAddress((void**)&wgu_h, g_wgu_h);
    cudaGetSymbolAddress((void**)&wd_h, g_wd_h);

    cudaFuncSetAttribute(gemm_fp16, cudaFuncAttributeMaxDynamicSharedMemorySize, GEMM_SMEM);
    cudaFuncSetAttribute(attn_tc, cudaFuncAttributeMaxDynamicSharedMemorySize, ATTN_SMEM);

    #define GEMM0(Aa, Bw, Cp, Rp, Mm, Nn, Kk) \
        gemm_fp16<<<dim3((Nn) / 256, (Mm) / 128), 256, GEMM_SMEM>>>( \
            Aa, Bw, Cp, Rp, nullptr, nullptr, nullptr, nullptr, nullptr, 0, Mm, Nn, Kk)

    // launch 1: RoPE table
    rope_table_kernel<<<(Tn * 64 + 255) / 256, 256>>>(rtab);
    // launch 2: rmsnorm1
    rmsnorm_kernel<<<Tn, 256>>>(x, attn_norm_w, h);
    // launch 3: ALL weight converts in one kernel
    mega_convert_kernel<<<SOFF_END / 16 / 256, 256>>>(
        wq, wk, wv, wo, w_gate, w_up, w_down, wqkv_h, wo_h, wgu_h, wd_h);
    // launch 4: merged QKV GEMM + RoPE epilogue (ncu capture target)
    gemm_fp16<<<dim3((Cn + 2 * NKV * HD) / 256, Tn / 128), 256, GEMM_SMEM>>>(
        h, wqkv_h, nullptr, nullptr, nullptr,
        rtab, qp, kp, vp, 2, Tn, Cn + 2 * NKV * HD, Cn);
    // launch 5: attention
    attn_tc<<<dim3(32, NH), 256, ATTN_SMEM>>>(qp, kp, vp, y);
    // launch 6: out = x + y @ wo^T
    GEMM0(y, wo_h, out, x, Tn, Cn, Cn);
    // launch 7: rmsnorm2
    rmsnorm_kernel<<<Tn, 256>>>(out, ffn_norm_w, h2);
    // launch 8: fused silu(gate)*up GEMM (interleaved weights)
    gemm_fp16<<<dim3((2 * FFN) / 256, Tn / 128), 256, GEMM_SMEM>>>(
        h2, wgu_h, nullptr, nullptr, gs,
        nullptr, nullptr, nullptr, nullptr, 3, Tn, 2 * FFN, Cn);
    // launch 9: out += gs @ w_down^T
    GEMM0(gs, wd_h, out, out, Tn, Cn, FFN);

    #undef GEMM0
}

// round 17
// speedup vs baseline: 8.4637x; 1.0188x over previous
#include <cuda_runtime.h>
#include <cuda_fp16.h>
#include <math.h>
#include <stdint.h>

#define Tn   4096
#define Cn   2048
#define NH   16
#define NKV  4
#define HD   128
#define FFN  8192

typedef __half fp16;

// ---------------- scratch (static device globals; no allocation) ----------------
static __device__ float2 g_rope[Tn * 64];

static __device__ fp16 g_h  [Tn * Cn];
static __device__ fp16 g_h2 [Tn * Cn];
static __device__ fp16 g_y  [Tn * Cn];
static __device__ fp16 g_gs [Tn * FFN];

static __device__ fp16 g_qh[Tn * Cn];
static __device__ fp16 g_kh[Tn * NKV * HD];
static __device__ fp16 g_vh[Tn * NKV * HD];

static __device__ fp16 g_wqkv_h[(Cn + 2 * NKV * HD) * Cn];  // rows: wq | wk | wv
static __device__ fp16 g_wo_h[Cn * Cn];
static __device__ fp16 g_wgu_h[2 * FFN * Cn];               // interleaved: 2j = wg[j], 2j+1 = wu[j]
static __device__ fp16 g_wd_h[Cn * FFN];

__device__ __forceinline__ uint32_t pack_h2(fp16 a, fp16 b) {
    __half2 t; t.x = a; t.y = b;
    return *reinterpret_cast<uint32_t*>(&t);
}

// ---------------- common PTX helpers ----------------
__device__ __forceinline__ void cp16(uint32_t dst, const void* src) {
    asm volatile("cp.async.cg.shared.global [%0], [%1], 16;\n" :: "r"(dst), "l"(src));
}
__device__ __forceinline__ void ldm4(uint32_t* r, uint32_t addr) {
    asm volatile("ldmatrix.sync.aligned.m8n8.x4.shared.b16 {%0,%1,%2,%3}, [%4];\n"
                 : "=r"(r[0]), "=r"(r[1]), "=r"(r[2]), "=r"(r[3]) : "r"(addr));
}
__device__ __forceinline__ void ldm4t(uint32_t* r, uint32_t addr) {
    asm volatile("ldmatrix.sync.aligned.m8n8.x4.trans.shared.b16 {%0,%1,%2,%3}, [%4];\n"
                 : "=r"(r[0]), "=r"(r[1]), "=r"(r[2]), "=r"(r[3]) : "r"(addr));
}
__device__ __forceinline__ void mma16816h(float* c, const uint32_t* a, const uint32_t* b) {
    asm volatile("mma.sync.aligned.m16n8k16.row.col.f32.f16.f16.f32 "
                 "{%0,%1,%2,%3},{%4,%5,%6,%7},{%8,%9},{%0,%1,%2,%3};\n"
                 : "+f"(c[0]), "+f"(c[1]), "+f"(c[2]), "+f"(c[3])
                 : "r"(a[0]), "r"(a[1]), "r"(a[2]), "r"(a[3]), "r"(b[0]), "r"(b[1]));
}

// ---------------- mega weight convert: all 7 weight arrays, one launch ----------------
#define SOFF_WQ 0u
#define SOFF_WK 4194304u
#define SOFF_WV 5242880u
#define SOFF_WO 6291456u
#define SOFF_WG 10485760u
#define SOFF_WU 27262976u
#define SOFF_WD 44040192u
#define SOFF_END 60817408u

__device__ __forceinline__ void conv16(const float* __restrict__ s, fp16* __restrict__ d) {
    #pragma unroll
    for (int half = 0; half < 2; half++) {
        float4 a = *(const float4*)(s + half * 8);
        float4 b = *(const float4*)(s + half * 8 + 4);
        uint4 p;
        p.x = pack_h2(__float2half(a.x), __float2half(a.y));
        p.y = pack_h2(__float2half(a.z), __float2half(a.w));
        p.z = pack_h2(__float2half(b.x), __float2half(b.y));
        p.w = pack_h2(__float2half(b.z), __float2half(b.w));
        *(uint4*)(d + half * 8) = p;
    }
}

__global__ void __launch_bounds__(256) mega_convert_kernel(
        const float* __restrict__ wq, const float* __restrict__ wk,
        const float* __restrict__ wv, const float* __restrict__ wo,
        const float* __restrict__ wg, const float* __restrict__ wu,
        const float* __restrict__ wd,
        fp16* __restrict__ wqkv_h, fp16* __restrict__ wo_h,
        fp16* __restrict__ wgu_h,  fp16* __restrict__ wd_h) {
    uint32_t g = (blockIdx.x * blockDim.x + threadIdx.x) * 16u;
    if (g >= SOFF_END) return;
    if (g < SOFF_WK) {
        conv16(wq + g, wqkv_h + g);
    } else if (g < SOFF_WV) {
        conv16(wk + (g - SOFF_WK), wqkv_h + g);
    } else if (g < SOFF_WO) {
        conv16(wv + (g - SOFF_WV), wqkv_h + g);
    } else if (g < SOFF_WG) {
        uint32_t l = g - SOFF_WO;
        conv16(wo + l, wo_h + l);
    } else if (g < SOFF_WU) {
        uint32_t l = g - SOFF_WG;
        uint32_t row = l / Cn, col = l - row * Cn;
        conv16(wg + l, wgu_h + (size_t)(2 * row) * Cn + col);
    } else if (g < SOFF_WD) {
        uint32_t l = g - SOFF_WU;
        uint32_t row = l / Cn, col = l - row * Cn;
        conv16(wu + l, wgu_h + (size_t)(2 * row + 1) * Cn + col);
    } else {
        uint32_t l = g - SOFF_WD;
        conv16(wd + l, wd_h + l);
    }
}

// ---------------- RoPE cos/sin table (double sincos — fast-math immune) ----------------
__global__ void rope_table_kernel(float2* __restrict__ tab) {
    int idx = blockIdx.x * blockDim.x + threadIdx.x;
    if (idx >= Tn * 64) return;
    int i = idx & 63;
    int t = idx >> 6;
    double invf_d = pow(500000.0, -((double)(2 * i) / 128.0));
    float  invf_f = (float)invf_d;
    float  ang_f  = (float)t * invf_f;
    double c, s;
    sincos((double)ang_f, &s, &c);
    tab[idx] = make_float2((float)c, (float)s);
}

// ---------------- rmsnorm: one block per row, writes single fp16 ----------------
__global__ void __launch_bounds__(256) rmsnorm_kernel(const float* __restrict__ x,
                                                      const float* __restrict__ w,
                                                      fp16* __restrict__ o) {
    const int row = blockIdx.x;
    const float* xr = x + (size_t)row * Cn;
    float s = 0.f;
    for (int i = threadIdx.x; i < Cn; i += 256) {
        float v = xr[i];
        s = fmaf(v, v, s);
    }
    __shared__ float red[8];
    #pragma unroll
    for (int o2 = 16; o2; o2 >>= 1) s += __shfl_xor_sync(0xffffffffu, s, o2);
    if ((threadIdx.x & 31) == 0) red[threadIdx.x >> 5] = s;
    __syncthreads();
    if (threadIdx.x < 32) {
        float v = (threadIdx.x < 8) ? red[threadIdx.x] : 0.f;
        #pragma unroll
        for (int o2 = 4; o2; o2 >>= 1) v += __shfl_xor_sync(0xffffffffu, v, o2);
        if (threadIdx.x == 0) red[0] = v;
    }
    __syncthreads();
    const float scale = rsqrtf(red[0] * (1.0f / Cn) + 1e-5f);
    size_t base = (size_t)row * Cn;
    for (int i = threadIdx.x; i < Cn; i += 256)
        o[base + i] = __float2half(xr[i] * scale * w[i]);
}

// =====================================================================
// fp16 tensor-core GEMM — 512 threads (16 warps, 4/SMSP), warp tile 32x64
// CTA tile 128(M) x 256(N), BK=32, 5-stage cp.async, CTA swizzle.
// mode 0: C = acc (+R); mode 2: QKV epilogue; mode 3: silu(gate)*up
// =====================================================================
#define STAGES 5
#define G_A   0
#define G_B   8192
#define G_STAGE 24576
#define GEMM_SMEM (STAGES * G_STAGE)

__device__ __forceinline__ uint32_t sw(uint32_t row, uint32_t chunk) {
    return (row << 6) + (((chunk ^ (row >> 1)) & 3u) << 4);
}

__global__ void __launch_bounds__(512, 1) gemm_fp16(
        const fp16* __restrict__ A, const fp16* __restrict__ B,
        float* __restrict__ C, const float* __restrict__ R,
        fp16* __restrict__ O,
        const float2* __restrict__ tab,
        fp16* __restrict__ Qp, fp16* __restrict__ Kp, fp16* __restrict__ Vp,
        int mode, int M, int N, int K) {
    extern __shared__ __align__(128) char smem_raw[];
    const uint32_t smem_u = (uint32_t)__cvta_generic_to_shared(smem_raw);
    const int tid  = threadIdx.x;
    const int warp = tid >> 5;
    const int lane = tid & 31;
    const int wm   = warp & 3;       // 4 warps along M (32 rows each)
    const int wn   = warp >> 2;      // 4 warps along N (64 cols each)

    int bx, by;
    {
        int tiles_n = gridDim.x, tiles_m = gridDim.y;
        int lin = blockIdx.y * tiles_n + blockIdx.x;
        int per = 8 * tiles_n;
        int gid = lin / per, rem = lin % per;
        int gm  = tiles_m - gid * 8;
        if (gm > 8) gm = 8;
        by = gid * 8 + rem % gm;
        bx = rem / gm;
    }
    const int bm = by * 128;
    const int bn = bx * 256;

    float acc[2][8][4];
    #pragma unroll
    for (int i = 0; i < 2; i++)
        #pragma unroll
        for (int j = 0; j < 8; j++)
            #pragma unroll
            for (int v = 0; v < 4; v++) acc[i][j][v] = 0.f;

    const int kiters = K >> 5;

    auto load_stage = [&](int stage, int kt) {
        const uint32_t sbase = smem_u + stage * G_STAGE;
        {   // A: 128 rows x 4 chunks = 512 chunks, one per thread
            int row = tid >> 2;
            int ch  = tid & 3;
            size_t go = (size_t)(bm + row) * K + kt + ch * 8;
            cp16(sbase + G_A + sw(row, ch), A + go);
        }
        #pragma unroll
        for (int rep = 0; rep < 2; rep++) {   // B: 256 rows x 4 chunks = 1024 chunks
            int idx = tid + rep * 512;
            int row = idx >> 2;
            int ch  = idx & 3;
            size_t go = (size_t)(bn + row) * K + kt + ch * 8;
            cp16(sbase + G_B + sw(row, ch), B + go);
        }
    };

    #pragma unroll
    for (int s = 0; s < STAGES - 1; s++) {
        load_stage(s, s * 32);
        asm volatile("cp.async.commit_group;\n");
    }

    for (int it = 0; it < kiters; ++it) {
        asm volatile("cp.async.wait_group %0;\n" :: "n"(STAGES - 2));
        __syncthreads();
        int pf = it + STAGES - 1;
        if (pf < kiters) load_stage(pf % STAGES, pf * 32);
        asm volatile("cp.async.commit_group;\n");

        const uint32_t sb = smem_u + (it % STAGES) * G_STAGE;

        #pragma unroll
        for (int kf = 0; kf < 2; kf++) {
            uint32_t ah[2][4], bf[4][4];
            #pragma unroll
            for (int mt = 0; mt < 2; mt++) {
                uint32_t row = wm * 32 + mt * 16 + (lane & 15);
                uint32_t ch  = kf * 2 + (lane >> 4);
                ldm4(ah[mt], sb + G_A + sw(row, ch));
            }
            #pragma unroll
            for (int p = 0; p < 4; p++) {
                uint32_t rowb = wn * 64 + p * 16 + (lane & 7) + ((lane >> 4) & 1) * 8;
                uint32_t chb  = kf * 2 + ((lane >> 3) & 1);
                ldm4(bf[p], sb + G_B + sw(rowb, chb));
            }
            #pragma unroll
            for (int p = 0; p < 4; p++)
                #pragma unroll
                for (int mt = 0; mt < 2; mt++) {
                    mma16816h(acc[mt][2 * p],     ah[mt], bf[p]);
                    mma16816h(acc[mt][2 * p + 1], ah[mt], bf[p] + 2);
                }
        }
    }

    // ---- epilogue ----
    const int rb = bm + wm * 32;
    const int cb = bn + wn * 64;
    #pragma unroll
    for (int mt = 0; mt < 2; mt++)
        #pragma unroll
        for (int nt = 0; nt < 8; nt++) {
            int r0 = rb + mt * 16 + (lane >> 2);
            int r1 = r0 + 8;
            int c  = cb + nt * 8 + (lane & 3) * 2;
            if (mode == 0) {
                size_t i0 = (size_t)r0 * N + c;
                size_t i1 = (size_t)r1 * N + c;
                float2 v0 = make_float2(acc[mt][nt][0], acc[mt][nt][1]);
                float2 v1 = make_float2(acc[mt][nt][2], acc[mt][nt][3]);
                if (R) {
                    float2 q0 = *(const float2*)(R + i0);
                    float2 q1 = *(const float2*)(R + i1);
                    v0.x += q0.x; v0.y += q0.y;
                    v1.x += q1.x; v1.y += q1.y;
                }
                *(float2*)(C + i0) = v0;
                *(float2*)(C + i1) = v1;
            } else if (mode == 2) {
                if (bn < 2048) {
                    int i = (c & 127) >> 1;
                    float2 cs0 = tab[(size_t)r0 * 64 + i];
                    float2 cs1 = tab[(size_t)r1 * 64 + i];
                    float a0 = acc[mt][nt][0], b0 = acc[mt][nt][1];
                    float a1 = acc[mt][nt][2], b1 = acc[mt][nt][3];
                    size_t i0 = (size_t)r0 * Cn + c;
                    size_t i1 = (size_t)r1 * Cn + c;
                    *(uint32_t*)(Qp + i0) = pack_h2(
                        __float2half(fmaf(a0, cs0.x, -b0 * cs0.y)),
                        __float2half(fmaf(a0, cs0.y,  b0 * cs0.x)));
                    *(uint32_t*)(Qp + i1) = pack_h2(
                        __float2half(fmaf(a1, cs1.x, -b1 * cs1.y)),
                        __float2half(fmaf(a1, cs1.y,  b1 * cs1.x)));
                } else if (bn < 2560) {
                    int ck = c - 2048;
                    int i = (ck & 127) >> 1;
                    float2 cs0 = tab[(size_t)r0 * 64 + i];
                    float2 cs1 = tab[(size_t)r1 * 64 + i];
                    float a0 = acc[mt][nt][0], b0 = acc[mt][nt][1];
                    float a1 = acc[mt][nt][2], b1 = acc[mt][nt][3];
                    size_t i0 = (size_t)r0 * (NKV * HD) + ck;
                    size_t i1 = (size_t)r1 * (NKV * HD) + ck;
                    *(uint32_t*)(Kp + i0) = pack_h2(
                        __float2half(fmaf(a0, cs0.x, -b0 * cs0.y)),
                        __float2half(fmaf(a0, cs0.y,  b0 * cs0.x)));
                    *(uint32_t*)(Kp + i1) = pack_h2(
                        __float2half(fmaf(a1, cs1.x, -b1 * cs1.y)),
                        __float2half(fmaf(a1, cs1.y,  b1 * cs1.x)));
                } else {
                    int cv = c - 2560;
                    size_t i0 = (size_t)r0 * (NKV * HD) + cv;
                    size_t i1 = (size_t)r1 * (NKV * HD) + cv;
                    *(uint32_t*)(Vp + i0) = pack_h2(__float2half(acc[mt][nt][0]),
                                                    __float2half(acc[mt][nt][1]));
                    *(uint32_t*)(Vp + i1) = pack_h2(__float2half(acc[mt][nt][2]),
                                                    __float2half(acc[mt][nt][3]));
                }
            } else {
                int gcol = c >> 1;
                float ga0 = acc[mt][nt][0], up0 = acc[mt][nt][1];
                float ga1 = acc[mt][nt][2], up1 = acc[mt][nt][3];
                O[(size_t)r0 * FFN + gcol] = __float2half(ga0 / (1.f + expf(-ga0)) * up0);
                O[(size_t)r1 * FFN + gcol] = __float2half(ga1 / (1.f + expf(-ga1)) * up1);
            }
        }
}

// =====================================================================
// Tensor-core causal flash attention — single fp16 (unchanged R14-16)
// =====================================================================
#define AQ    0
#define AKV   32768
#define AKV_STAGE 32768
#define AV    16384
#define ATTN_SMEM (AKV + 2 * AKV_STAGE)

__device__ __forceinline__ uint32_t sw256(uint32_t row, uint32_t ch) {
    return (row << 8) + ((((ch ^ row) & 7u) | (ch & 8u)) << 4);
}

__global__ void __launch_bounds__(256, 1) attn_tc(
        const fp16* __restrict__ q, const fp16* __restrict__ k,
        const fp16* __restrict__ v, fp16* __restrict__ y) {
    extern __shared__ __align__(128) char smem_raw[];
    const uint32_t sb = (uint32_t)__cvta_generic_to_shared(smem_raw);
    const int qt   = 31 - blockIdx.x;
    const int head = blockIdx.y;
    const int kvh  = head >> 2;
    const int qb   = qt * 128;
    const int tid  = threadIdx.x;
    const int warp = tid >> 5;
    const int lane = tid & 31;
    const int njt  = 2 * qt + 2;

    #pragma unroll
    for (int i = 0; i < 8; i++) {
        int idx = tid + i * 256;
        int row = idx >> 4;
        int ch  = idx & 15;
        size_t g = (size_t)(qb + row) * Cn + head * HD + ch * 8;
        cp16(sb + AQ + sw256(row, ch), q + g);
    }

    auto load_kv = [&](int jt, int buf) {
        const uint32_t base = sb + AKV + buf * AKV_STAGE;
        #pragma unroll
        for (int i = 0; i < 4; i++) {
            int idx = tid + i * 256;
            int row = idx >> 4;
            int ch  = idx & 15;
            size_t g = (size_t)(jt * 64 + row) * (NKV * HD) + kvh * HD + ch * 8;
            uint32_t off = sw256(row, ch);
            cp16(base + off,      k + g);
            cp16(base + AV + off, v + g);
        }
    };

    load_kv(0, 0);
    asm volatile("cp.async.commit_group;\n");

    float m0 = -1e30f, m1 = -1e30f, l0 = 0.f, l1 = 0.f;
    float o[16][4];
    #pragma unroll
    for (int nt = 0; nt < 16; nt++)
        #pragma unroll
        for (int e = 0; e < 4; e++) o[nt][e] = 0.f;

    const float cs = 0.12751743621340608f;
    const int r0g = qb + (warp << 4) + (lane >> 2);
    const int r1g = r0g + 8;

    for (int jt = 0; jt < njt; jt++) {
        if (jt + 1 < njt) load_kv(jt + 1, (jt + 1) & 1);
        asm volatile("cp.async.commit_group;\n");
        asm volatile("cp.async.wait_group 1;\n");
        __syncthreads();

        const uint32_t kb = sb + AKV + (jt & 1) * AKV_STAGE;
        const uint32_t vb = kb + AV;

        float sacc[8][4];
        #pragma unroll
        for (int nt = 0; nt < 8; nt++)
            #pragma unroll
            for (int e = 0; e < 4; e++) sacc[nt][e] = 0.f;

        #pragma unroll
        for (int ks = 0; ks < 8; ks++) {
            uint32_t ah[4];
            {
                uint32_t row = (warp << 4) + (lane & 15);
                uint32_t ch  = ks * 2 + (lane >> 4);
                ldm4(ah, sb + AQ + sw256(row, ch));
            }
            #pragma unroll
            for (int p = 0; p < 4; p++) {
                uint32_t rowb = p * 16 + (lane & 7) + ((lane >> 4) & 1) * 8;
                uint32_t chb  = ks * 2 + ((lane >> 3) & 1);
                uint32_t bfr[4];
                ldm4(bfr, kb + sw256(rowb, chb));
                mma16816h(sacc[2 * p],     ah, bfr);
                mma16816h(sacc[2 * p + 1], ah, bfr + 2);
            }
        }

        const bool domask = (jt >= 2 * qt);
        #pragma unroll
        for (int nt = 0; nt < 8; nt++) {
            int cbase = jt * 64 + nt * 8 + (lane & 3) * 2;
            #pragma unroll
            for (int e = 0; e < 4; e++) {
                float vv = sacc[nt][e] * cs;
                if (domask) {
                    int col = cbase + (e & 1);
                    int row = (e < 2) ? r0g : r1g;
                    if (col > row) vv = -1e30f;
                }
                sacc[nt][e] = vv;
            }
        }

        float mx0 = -1e30f, mx1 = -1e30f;
        #pragma unroll
        for (int nt = 0; nt < 8; nt++) {
            mx0 = fmaxf(mx0, fmaxf(sacc[nt][0], sacc[nt][1]));
            mx1 = fmaxf(mx1, fmaxf(sacc[nt][2], sacc[nt][3]));
        }
        mx0 = fmaxf(mx0, __shfl_xor_sync(0xffffffffu, mx0, 1));
        mx0 = fmaxf(mx0, __shfl_xor_sync(0xffffffffu, mx0, 2));
        mx1 = fmaxf(mx1, __shfl_xor_sync(0xffffffffu, mx1, 1));
        mx1 = fmaxf(mx1, __shfl_xor_sync(0xffffffffu, mx1, 2));
        float mn0 = fmaxf(m0, mx0);
        float mn1 = fmaxf(m1, mx1);

        float ls0 = 0.f, ls1 = 0.f;
        #pragma unroll
        for (int nt = 0; nt < 8; nt++) {
            float p0 = exp2f(sacc[nt][0] - mn0);
            float p1 = exp2f(sacc[nt][1] - mn0);
            float p2 = exp2f(sacc[nt][2] - mn1);
            float p3 = exp2f(sacc[nt][3] - mn1);
            ls0 += p0 + p1;
            ls1 += p2 + p3;
            sacc[nt][0] = p0; sacc[nt][1] = p1; sacc[nt][2] = p2; sacc[nt][3] = p3;
        }
        ls0 += __shfl_xor_sync(0xffffffffu, ls0, 1);
        ls0 += __shfl_xor_sync(0xffffffffu, ls0, 2);
        ls1 += __shfl_xor_sync(0xffffffffu, ls1, 1);
        ls1 += __shfl_xor_sync(0xffffffffu, ls1, 2);

        float a0 = exp2f(m0 - mn0);
        float a1 = exp2f(m1 - mn1);
        m0 = mn0; m1 = mn1;
        l0 = l0 * a0 + ls0;
        l1 = l1 * a1 + ls1;
        #pragma unroll
        for (int nt = 0; nt < 16; nt++) {
            o[nt][0] *= a0; o[nt][1] *= a0;
            o[nt][2] *= a1; o[nt][3] *= a1;
        }

        #pragma unroll
        for (int ks = 0; ks < 4; ks++) {
            uint32_t ah[4];
            ah[0] = pack_h2(__float2half(sacc[2 * ks][0]),     __float2half(sacc[2 * ks][1]));
            ah[1] = pack_h2(__float2half(sacc[2 * ks][2]),     __float2half(sacc[2 * ks][3]));
            ah[2] = pack_h2(__float2half(sacc[2 * ks + 1][0]), __float2half(sacc[2 * ks + 1][1]));
            ah[3] = pack_h2(__float2half(sacc[2 * ks + 1][2]), __float2half(sacc[2 * ks + 1][3]));

            #pragma unroll
            for (int dq = 0; dq < 4; dq++) {
                uint32_t row = ks * 16 + (lane & 15);
                uint32_t ch0 = (2 * dq) * 2 + (lane >> 4);
                uint32_t ch1 = (2 * dq + 1) * 2 + (lane >> 4);
                uint32_t b0[4], b1[4];
                ldm4t(b0, vb + sw256(row, ch0));
                ldm4t(b1, vb + sw256(row, ch1));
                mma16816h(o[4 * dq + 0], ah, b0);
                mma16816h(o[4 * dq + 1], ah, b0 + 2);
                mma16816h(o[4 * dq + 2], ah, b1);
                mma16816h(o[4 * dq + 3], ah, b1 + 2);
            }
        }
        __syncthreads();
    }

    float inv0 = 1.0f / l0;
    float inv1 = 1.0f / l1;
    #pragma unroll
    for (int nt = 0; nt < 16; nt++) {
        int c = head * HD + nt * 8 + (lane & 3) * 2;
        size_t i0 = (size_t)r0g * Cn + c;
        size_t i1 = (size_t)r1g * Cn + c;
        *(uint32_t*)(y + i0) = pack_h2(__float2half(o[nt][0] * inv0),
                                       __float2half(o[nt][1] * inv0));
        *(uint32_t*)(y + i1) = pack_h2(__float2half(o[nt][2] * inv1),
                                       __float2half(o[nt][3] * inv1));
    }
}

// ---------------- launch ----------------
extern "C" void kernel_launch(void* const* d_in, const int* in_sizes, int n_in,
                              void* d_out, int out_size) {
    (void)in_sizes; (void)n_in; (void)out_size;
    const float* x           = (const float*)d_in[0];
    const float* attn_norm_w = (const float*)d_in[2];
    const float* wq          = (const float*)d_in[3];
    const float* wk          = (const float*)d_in[4];
    const float* wv          = (const float*)d_in[5];
    const float* wo          = (const float*)d_in[6];
    const float* ffn_norm_w  = (const float*)d_in[7];
    const float* w_gate      = (const float*)d_in[8];
    const float* w_up        = (const float*)d_in[9];
    const float* w_down      = (const float*)d_in[10];
    float* out = (float*)d_out;

    float2* rtab;
    fp16 *h, *h2, *y, *gs, *qp, *kp, *vp;
    fp16 *wqkv_h, *wo_h, *wgu_h, *wd_h;

    cudaGetSymbolAddress((void**)&rtab, g_rope);
    cudaGetSymbolAddress((void**)&h,  g_h);
    cudaGetSymbolAddress((void**)&h2, g_h2);
    cudaGetSymbolAddress((void**)&y,  g_y);
    cudaGetSymbolAddress((void**)&gs, g_gs);
    cudaGetSymbolAddress((void**)&qp, g_qh);
    cudaGetSymbolAddress((void**)&kp, g_kh);
    cudaGetSymbolAddress((void**)&vp, g_vh);
    cudaGetSymbolAddress((void**)&wqkv_h, g_wqkv_h);
    cudaGetSymbolAddress((void**)&wo_h, g_wo_h);
    cudaGetSymbolAddress((void**)&wgu_h, g_wgu_h);
    cudaGetSymbolAddress((void**)&wd_h, g_wd_h);

    cudaFuncSetAttribute(gemm_fp16, cudaFuncAttributeMaxDynamicSharedMemorySize, GEMM_SMEM);
    cudaFuncSetAttribute(attn_tc, cudaFuncAttributeMaxDynamicSharedMemorySize, ATTN_SMEM);

    #define GEMM0(Aa, Bw, Cp, Rp, Mm, Nn, Kk) \
        gemm_fp16<<<dim3((Nn) / 256, (Mm) / 128), 512, GEMM_SMEM>>>( \
            Aa, Bw, Cp, Rp, nullptr, nullptr, nullptr, nullptr, nullptr, 0, Mm, Nn, Kk)

    // launch 1: RoPE table
    rope_table_kernel<<<(Tn * 64 + 255) / 256, 256>>>(rtab);
    // launch 2: rmsnorm1
    rmsnorm_kernel<<<Tn, 256>>>(x, attn_norm_w, h);
    // launch 3: ALL weight converts in one kernel
    mega_convert_kernel<<<SOFF_END / 16 / 256, 256>>>(
        wq, wk, wv, wo, w_gate, w_up, w_down, wqkv_h, wo_h, wgu_h, wd_h);
    // launch 4: merged QKV GEMM + RoPE epilogue (ncu capture target)
    gemm_fp16<<<dim3((Cn + 2 * NKV * HD) / 256, Tn / 128), 512, GEMM_SMEM>>>(
        h, wqkv_h, nullptr, nullptr, nullptr,
        rtab, qp, kp, vp, 2, Tn, Cn + 2 * NKV * HD, Cn);
    // launch 5: attention
    attn_tc<<<dim3(32, NH), 256, ATTN_SMEM>>>(qp, kp, vp, y);
    // launch 6: out = x + y @ wo^T
    GEMM0(y, wo_h, out, x, Tn, Cn, Cn);
    // launch 7: rmsnorm2
    rmsnorm_kernel<<<Tn, 256>>>(out, ffn_norm_w, h2);
    // launch 8: fused silu(gate)*up GEMM (interleaved weights)
    gemm_fp16<<<dim3((2 * FFN) / 256, Tn / 128), 512, GEMM_SMEM>>>(
        h2, wgu_h, nullptr, nullptr, gs,
        nullptr, nullptr, nullptr, nullptr, 3, Tn, 2 * FFN, Cn);
    // launch 9: out += gs @ w_down^T
    GEMM0(gs, wd_h, out, out, Tn, Cn, FFN);

    #undef GEMM0
}